// round 5
// baseline (speedup 1.0000x reference)
#include <cuda_runtime.h>

#define S_LEN  2048
#define NHEAD  16
#define HDIM   64
#define DMODEL 1024
#define BATCH  4
#define NTOK   (BATCH * S_LEN)   // 8192

// ---------------- scratch (no allocations allowed) ----------------
__device__ float g_q[BATCH * NHEAD * S_LEN * HDIM];   // 32 MB, [b,h,s,hd], pre-scaled by 1/8
__device__ float g_k[BATCH * NHEAD * S_LEN * HDIM];   // 32 MB
__device__ float g_v[BATCH * NHEAD * S_LEN * HDIM];   // 32 MB
__device__ float g_att[NTOK * DMODEL];                // 32 MB, [b*s, h*hd]

// ---------------- tiled fp32 GEMM: C = A(MxK) * B(KxN) ----------------
// mode 0: C row-major [M,N]
// mode 1: scatter into [b, h, s, hd] layout (QKV projections), scale applied
__global__ __launch_bounds__(256, 2)
void sgemm_kernel(const float* __restrict__ A, const float* __restrict__ B,
                  float* __restrict__ C, int M, int N, int K, int mode, float scale)
{
    __shared__ float As[8][128];   // A tile, transposed: As[k][m]
    __shared__ float Bs[8][128];   // B tile: Bs[k][n]

    const int tid  = threadIdx.x;
    const int m0   = blockIdx.y * 128;
    const int n0   = blockIdx.x * 128;
    const int trow = tid >> 4;          // 0..15
    const int tcol = tid & 15;          // 0..15

    const int aRow = tid >> 1;          // 0..127
    const int aCol = (tid & 1) << 2;    // 0 or 4
    const int bRow = tid >> 5;          // 0..7
    const int bCol = (tid & 31) << 2;   // 0..124

    const float* Aptr = A + (size_t)(m0 + aRow) * K + aCol;
    const float* Bptr = B + (size_t)bRow * N + n0 + bCol;

    float acc[8][8];
#pragma unroll
    for (int i = 0; i < 8; i++)
#pragma unroll
        for (int j = 0; j < 8; j++) acc[i][j] = 0.f;

    for (int k0 = 0; k0 < K; k0 += 8) {
        float4 a = *(const float4*)(Aptr + k0);
        float4 b = *(const float4*)(Bptr + (size_t)k0 * N);
        As[aCol + 0][aRow] = a.x;
        As[aCol + 1][aRow] = a.y;
        As[aCol + 2][aRow] = a.z;
        As[aCol + 3][aRow] = a.w;
        *(float4*)&Bs[bRow][bCol] = b;
        __syncthreads();
#pragma unroll
        for (int kk = 0; kk < 8; kk++) {
            float ar[8], br[8];
            *(float4*)&ar[0] = *(const float4*)&As[kk][trow * 8];
            *(float4*)&ar[4] = *(const float4*)&As[kk][trow * 8 + 4];
            *(float4*)&br[0] = *(const float4*)&Bs[kk][tcol * 8];
            *(float4*)&br[4] = *(const float4*)&Bs[kk][tcol * 8 + 4];
#pragma unroll
            for (int i = 0; i < 8; i++)
#pragma unroll
                for (int j = 0; j < 8; j++)
                    acc[i][j] += ar[i] * br[j];
        }
        __syncthreads();
    }

    if (mode == 0) {
#pragma unroll
        for (int i = 0; i < 8; i++) {
            int m = m0 + trow * 8 + i;
#pragma unroll
            for (int j = 0; j < 8; j++) {
                int n = n0 + tcol * 8 + j;
                C[(size_t)m * N + n] = acc[i][j] * scale;
            }
        }
    } else {
        // scatter: token m -> (b, s); column n -> (h, d); C[((b*16+h)*2048+s)*64+d]
#pragma unroll
        for (int i = 0; i < 8; i++) {
            int m = m0 + trow * 8 + i;
            int b = m >> 11;
            int s = m & 2047;
#pragma unroll
            for (int j = 0; j < 8; j++) {
                int n = n0 + tcol * 8 + j;
                int h = n >> 6;
                int d = n & 63;
                C[(((size_t)(b * NHEAD + h)) * S_LEN + s) * HDIM + d] = acc[i][j] * scale;
            }
        }
    }
}

// ---------------- fused causal flash-attention, fp32 ----------------
// One CTA per (b*h, q-tile of 64 rows). Streams K/V tiles of 64 rows.
// Thread layout: warp w owns q rows [w*8, w*8+8); within a warp,
// lane>>4 picks a 4-row group, lane&15 picks a 4-column group.
// Row-wise max/sum reductions run over the 16 lanes sharing rows (width-16 shfl).
#define SMPAD 68   // smem row stride (floats) — breaks bank conflicts on K reads

__global__ __launch_bounds__(256, 2)
void attn_kernel(const float* __restrict__ q, const float* __restrict__ k,
                 const float* __restrict__ v, float* __restrict__ att)
{
    extern __shared__ float sm[];
    float* Qs = sm;                    // 64 x 68
    float* Ks = sm + 64 * SMPAD;
    float* Vs = sm + 2 * 64 * SMPAD;
    float* Ps = sm + 3 * 64 * SMPAD;

    const int tid   = threadIdx.x;
    const int bh    = blockIdx.y;
    const int qt    = (int)gridDim.x - 1 - (int)blockIdx.x;  // heavy tiles first
    const int b     = bh >> 4;
    const int h     = bh & 15;
    const int qbase = qt * 64;

    const int lane  = tid & 31;
    const int rbase = (tid >> 5) * 8 + ((lane >> 4) << 2);   // 4 q-rows
    const int cbase = (lane & 15) << 2;                      // 4 kv-cols / hd-cols

    const size_t head_off = (size_t)bh * (S_LEN * HDIM);

    // load Q tile (contiguous 4096 floats)
    const float4* qg = (const float4*)(q + head_off + (size_t)qbase * HDIM);
#pragma unroll
    for (int i = 0; i < 4; i++) {
        int lin = i * 256 + tid;
        int r = lin >> 4, d = (lin & 15) << 2;
        *(float4*)&Qs[r * SMPAD + d] = qg[lin];
    }

    float o[4][4];
    float mrow[4], lrow[4];
#pragma unroll
    for (int i = 0; i < 4; i++) {
        mrow[i] = -1e30f; lrow[i] = 0.f;
#pragma unroll
        for (int j = 0; j < 4; j++) o[i][j] = 0.f;
    }

    for (int kt = 0; kt <= qt; kt++) {
        const float4* kg = (const float4*)(k + head_off + (size_t)kt * 64 * HDIM);
        const float4* vg = (const float4*)(v + head_off + (size_t)kt * 64 * HDIM);
#pragma unroll
        for (int i = 0; i < 4; i++) {
            int lin = i * 256 + tid;
            int r = lin >> 4, d = (lin & 15) << 2;
            *(float4*)&Ks[r * SMPAD + d] = kg[lin];
            *(float4*)&Vs[r * SMPAD + d] = vg[lin];
        }
        __syncthreads();

        // S = Q @ K^T (Q pre-scaled by 1/sqrt(HD))
        float s[4][4];
#pragma unroll
        for (int i = 0; i < 4; i++)
#pragma unroll
            for (int j = 0; j < 4; j++) s[i][j] = 0.f;

#pragma unroll 4
        for (int d = 0; d < 64; d += 4) {
            float4 qv[4], kv[4];
#pragma unroll
            for (int i = 0; i < 4; i++) qv[i] = *(const float4*)&Qs[(rbase + i) * SMPAD + d];
#pragma unroll
            for (int j = 0; j < 4; j++) kv[j] = *(const float4*)&Ks[(cbase + j) * SMPAD + d];
#pragma unroll
            for (int i = 0; i < 4; i++)
#pragma unroll
                for (int j = 0; j < 4; j++)
                    s[i][j] += qv[i].x * kv[j].x + qv[i].y * kv[j].y
                             + qv[i].z * kv[j].z + qv[i].w * kv[j].w;
        }

        if (kt == qt) {   // causal mask only touches the diagonal tile
#pragma unroll
            for (int i = 0; i < 4; i++)
#pragma unroll
                for (int j = 0; j < 4; j++)
                    if (cbase + j > rbase + i) s[i][j] = -1e30f;
        }

        // online softmax update
#pragma unroll
        for (int i = 0; i < 4; i++) {
            float rm = fmaxf(fmaxf(s[i][0], s[i][1]), fmaxf(s[i][2], s[i][3]));
#pragma unroll
            for (int off = 8; off > 0; off >>= 1)
                rm = fmaxf(rm, __shfl_xor_sync(0xffffffffu, rm, off, 16));
            float mn = fmaxf(mrow[i], rm);
            float p0 = __expf(s[i][0] - mn);
            float p1 = __expf(s[i][1] - mn);
            float p2 = __expf(s[i][2] - mn);
            float p3 = __expf(s[i][3] - mn);
            float rs = (p0 + p1) + (p2 + p3);
#pragma unroll
            for (int off = 8; off > 0; off >>= 1)
                rs += __shfl_xor_sync(0xffffffffu, rs, off, 16);
            float al = __expf(mrow[i] - mn);
            lrow[i] = lrow[i] * al + rs;
            mrow[i] = mn;
#pragma unroll
            for (int j = 0; j < 4; j++) o[i][j] *= al;
            *(float4*)&Ps[(rbase + i) * SMPAD + cbase] = make_float4(p0, p1, p2, p3);
        }
        __syncthreads();

        // O += P @ V
#pragma unroll 4
        for (int c = 0; c < 64; c += 4) {
            float4 pr[4], vr[4];
#pragma unroll
            for (int i = 0; i < 4; i++) pr[i] = *(const float4*)&Ps[(rbase + i) * SMPAD + c];
#pragma unroll
            for (int u = 0; u < 4; u++) vr[u] = *(const float4*)&Vs[(c + u) * SMPAD + cbase];
#pragma unroll
            for (int i = 0; i < 4; i++) {
                o[i][0] += pr[i].x * vr[0].x + pr[i].y * vr[1].x + pr[i].z * vr[2].x + pr[i].w * vr[3].x;
                o[i][1] += pr[i].x * vr[0].y + pr[i].y * vr[1].y + pr[i].z * vr[2].y + pr[i].w * vr[3].y;
                o[i][2] += pr[i].x * vr[0].z + pr[i].y * vr[1].z + pr[i].z * vr[2].z + pr[i].w * vr[3].z;
                o[i][3] += pr[i].x * vr[0].w + pr[i].y * vr[1].w + pr[i].z * vr[2].w + pr[i].w * vr[3].w;
            }
        }
        __syncthreads();
    }

    // epilogue: normalize and write in [b, s, h*hd] layout for the output GEMM
#pragma unroll
    for (int i = 0; i < 4; i++) {
        float inv = 1.0f / lrow[i];
        int qpos = qbase + rbase + i;
        float4 r = make_float4(o[i][0] * inv, o[i][1] * inv, o[i][2] * inv, o[i][3] * inv);
        *(float4*)&att[((size_t)(b * S_LEN + qpos)) * DMODEL + h * HDIM + cbase] = r;
    }
}

// ---------------- launch ----------------
extern "C" void kernel_launch(void* const* d_in, const int* in_sizes, int n_in,
                              void* d_out, int out_size)
{
    const float* x  = (const float*)d_in[0];
    const float* Wq = (const float*)d_in[1];
    const float* Wk = (const float*)d_in[2];
    const float* Wv = (const float*)d_in[3];
    const float* Wo = (const float*)d_in[4];
    float* out = (float*)d_out;

    float *q, *k, *v, *att;
    cudaGetSymbolAddress((void**)&q,   g_q);
    cudaGetSymbolAddress((void**)&k,   g_k);
    cudaGetSymbolAddress((void**)&v,   g_v);
    cudaGetSymbolAddress((void**)&att, g_att);

    dim3 gblk(256);
    dim3 ggrid(DMODEL / 128, NTOK / 128);   // (8, 64)

    // QKV projections (Q pre-scaled by 1/sqrt(HD) = 0.125, exact)
    sgemm_kernel<<<ggrid, gblk>>>(x, Wq, q, NTOK, DMODEL, DMODEL, 1, 0.125f);
    sgemm_kernel<<<ggrid, gblk>>>(x, Wk, k, NTOK, DMODEL, DMODEL, 1, 1.0f);
    sgemm_kernel<<<ggrid, gblk>>>(x, Wv, v, NTOK, DMODEL, DMODEL, 1, 1.0f);

    // fused causal attention
    const int attn_smem = 4 * 64 * SMPAD * (int)sizeof(float);   // 69632 B
    cudaFuncSetAttribute(attn_kernel, cudaFuncAttributeMaxDynamicSharedMemorySize, attn_smem);
    attn_kernel<<<dim3(S_LEN / 64, BATCH * NHEAD), 256, attn_smem>>>(q, k, v, att);

    // output projection
    sgemm_kernel<<<ggrid, gblk>>>(att, Wo, out, NTOK, DMODEL, DMODEL, 0, 1.0f);
}

// round 7
// speedup vs baseline: 1.4629x; 1.4629x over previous
#include <cuda_runtime.h>
#include <cuda_bf16.h>
#include <cstdint>

#define S_LEN  2048
#define NHEAD  16
#define HDIM   64
#define DMODEL 1024
#define BATCH  4
#define NTOK   (BATCH * S_LEN)   // 8192

// ---------------- scratch (no allocations allowed) ----------------
__device__ float g_q[BATCH * NHEAD * S_LEN * HDIM];        // [b,h,s,hd], pre-scaled 1/8
__device__ float g_k[BATCH * NHEAD * S_LEN * HDIM];
__device__ float g_v[BATCH * NHEAD * S_LEN * HDIM];
__device__ float g_att[NTOK * DMODEL];                     // [b*s, h*hd]
__device__ __nv_bfloat16 g_ahi[NTOK * DMODEL];             // activation hi (x, later att)
__device__ __nv_bfloat16 g_alo[NTOK * DMODEL];             // activation lo
__device__ __nv_bfloat16 g_wthi[DMODEL * DMODEL];          // W^T hi  [N,K]
__device__ __nv_bfloat16 g_wtlo[DMODEL * DMODEL];          // W^T lo  [N,K]

// ================= helpers =================
__device__ __forceinline__ uint32_t smem_u32(const void* p) {
    uint32_t a;
    asm("{ .reg .u64 t; cvta.to.shared.u64 t, %1; cvt.u32.u64 %0, t; }" : "=r"(a) : "l"(p));
    return a;
}
__device__ __forceinline__ uint32_t lds32(uint32_t addr) {
    uint32_t v;
    asm volatile("ld.shared.b32 %0, [%1];" : "=r"(v) : "r"(addr));
    return v;
}
#define CP16(dst, src) \
    asm volatile("cp.async.cg.shared.global [%0], [%1], 16;" :: "r"(dst), "l"(src))
#define CP_COMMIT() asm volatile("cp.async.commit_group;" ::: "memory")
#define CP_WAIT1()  asm volatile("cp.async.wait_group 1;" ::: "memory")
#define CP_WAIT0()  asm volatile("cp.async.wait_group 0;" ::: "memory")

// bf16 warp MMA: D(16x8,f32) += A(16x16) * B(16x8)
#define MMA_BF16(d, a, b0, b1) \
    asm volatile("mma.sync.aligned.m16n8k16.row.col.f32.bf16.bf16.f32 " \
        "{%0,%1,%2,%3}, {%4,%5,%6,%7}, {%8,%9}, {%0,%1,%2,%3};" \
        : "+f"((d)[0]), "+f"((d)[1]), "+f"((d)[2]), "+f"((d)[3]) \
        : "r"((a)[0]), "r"((a)[1]), "r"((a)[2]), "r"((a)[3]), "r"(b0), "r"(b1))

// ================= conversion kernels =================
__global__ void convert_split_kernel(const float* __restrict__ in,
                                     __nv_bfloat16* __restrict__ hi,
                                     __nv_bfloat16* __restrict__ lo, int n4) {
    int i = blockIdx.x * blockDim.x + threadIdx.x;
    if (i >= n4) return;
    float4 v = ((const float4*)in)[i];
    __nv_bfloat16 h0 = __float2bfloat16(v.x), h1 = __float2bfloat16(v.y);
    __nv_bfloat16 h2 = __float2bfloat16(v.z), h3 = __float2bfloat16(v.w);
    __nv_bfloat16 l0 = __float2bfloat16(v.x - __bfloat162float(h0));
    __nv_bfloat16 l1 = __float2bfloat16(v.y - __bfloat162float(h1));
    __nv_bfloat16 l2 = __float2bfloat16(v.z - __bfloat162float(h2));
    __nv_bfloat16 l3 = __float2bfloat16(v.w - __bfloat162float(h3));
    ((__nv_bfloat162*)hi)[2*i]   = __nv_bfloat162(h0, h1);
    ((__nv_bfloat162*)hi)[2*i+1] = __nv_bfloat162(h2, h3);
    ((__nv_bfloat162*)lo)[2*i]   = __nv_bfloat162(l0, l1);
    ((__nv_bfloat162*)lo)[2*i+1] = __nv_bfloat162(l2, l3);
}

// W [K=1024, N=1024] row-major -> W^T hi/lo [N, K] bf16
__global__ void convert_wt_kernel(const float* __restrict__ W,
                                  __nv_bfloat16* __restrict__ hiT,
                                  __nv_bfloat16* __restrict__ loT) {
    __shared__ float sm[32][33];
    int n0 = blockIdx.x * 32, k0 = blockIdx.y * 32;
    int tx = threadIdx.x, ty = threadIdx.y;   // 32 x 8
#pragma unroll
    for (int i = 0; i < 4; i++)
        sm[ty + 8*i][tx] = W[(size_t)(k0 + ty + 8*i) * DMODEL + n0 + tx];
    __syncthreads();
#pragma unroll
    for (int i = 0; i < 4; i++) {
        float v = sm[tx][ty + 8*i];           // = W[k0+tx][n0+ty+8i]
        __nv_bfloat16 h = __float2bfloat16(v);
        __nv_bfloat16 l = __float2bfloat16(v - __bfloat162float(h));
        size_t o = (size_t)(n0 + ty + 8*i) * DMODEL + k0 + tx;
        hiT[o] = h; loT[o] = l;
    }
}

// ================= bf16-split GEMM on mma.sync (HMMA) =================
// C[M,N] = A[M,K] * B[K,N]; A hi/lo bf16 [M,K], B as transposed hi/lo bf16 [N,K].
// CTA tile 128x128, warp tile 32x64, K chunk 32, 2-stage cp.async pipeline.
// mode 0: C row-major. mode 1: scatter to [b,h,s,hd].
#define SA       80                         // smem row stride bytes (32 bf16 + pad)
#define T_AH     0
#define T_AL     (128 * SA)                 // 10240
#define T_BH     (2 * 128 * SA)
#define T_BL     (3 * 128 * SA)
#define STAGE_SZ (4 * 128 * SA)             // 40960
#define GEMM_SMEM (2 * STAGE_SZ)            // 81920
#define NKCH     (DMODEL / 32)              // 32

__global__ __launch_bounds__(256, 2)
void gemm_mma_kernel(const __nv_bfloat16* __restrict__ Ahi, const __nv_bfloat16* __restrict__ Alo,
                     const __nv_bfloat16* __restrict__ Bhi, const __nv_bfloat16* __restrict__ Blo,
                     float* __restrict__ C, int mode, float scale)
{
    extern __shared__ char smem[];
    const uint32_t sb = smem_u32(smem);
    const int tid  = threadIdx.x;
    const int lane = tid & 31;
    const int wid  = tid >> 5;
    const int wm   = wid & 3;        // 4 warps along M -> 32 rows each
    const int wn   = wid >> 2;       // 2 warps along N -> 64 cols each
    const int m0   = blockIdx.y * 128;
    const int n0   = blockIdx.x * 128;
    const int g    = lane >> 2;      // 0..7
    const int t    = lane & 3;       // 0..3

    // --- async load mapping: per stage, 4 tiles of 128 rows x 64B; 8 cp.async/thread
    const int lrow = tid >> 2;       // 0..63 (+64 on pass 1)
    const int lch  = tid & 3;        // 16B chunk within row

    float d[2][8][4];
#pragma unroll
    for (int i = 0; i < 2; i++)
#pragma unroll
        for (int j = 0; j < 8; j++)
#pragma unroll
            for (int e = 0; e < 4; e++) d[i][j][e] = 0.f;

    // prologue: stage 0 and 1
#pragma unroll
    for (int c = 0; c < 2; c++) {
        const int koe = c * 32;
        const uint32_t bufb = sb + c * STAGE_SZ;
#pragma unroll
        for (int p = 0; p < 2; p++) {
            int row = lrow + p * 64;
            size_t ga = (size_t)(m0 + row) * DMODEL + koe + lch * 8;
            size_t gb = (size_t)(n0 + row) * DMODEL + koe + lch * 8;
            uint32_t so = bufb + (uint32_t)row * SA + lch * 16;
            CP16(so + T_AH, Ahi + ga);
            CP16(so + T_AL, Alo + ga);
            CP16(so + T_BH, Bhi + gb);
            CP16(so + T_BL, Blo + gb);
        }
        CP_COMMIT();
    }

    for (int c = 0; c < NKCH; c++) {
        if (c + 1 < NKCH) { CP_WAIT1(); } else { CP_WAIT0(); }
        __syncthreads();
        const uint32_t base = sb + (uint32_t)(c & 1) * STAGE_SZ;

#pragma unroll
        for (int ks = 0; ks < 2; ks++) {
            const uint32_t ko = (uint32_t)ks * 32;   // bytes (16 bf16)
            uint32_t ah[2][4], al[2][4];
#pragma unroll
            for (int mi = 0; mi < 2; mi++) {
                uint32_t r0 = (uint32_t)(32 * wm + 16 * mi + g);
                uint32_t ra = base + r0 * SA + 4 * t + ko;
                ah[mi][0] = lds32(ra + T_AH);
                ah[mi][1] = lds32(ra + T_AH + 8 * SA);
                ah[mi][2] = lds32(ra + T_AH + 16);
                ah[mi][3] = lds32(ra + T_AH + 8 * SA + 16);
                al[mi][0] = lds32(ra + T_AL);
                al[mi][1] = lds32(ra + T_AL + 8 * SA);
                al[mi][2] = lds32(ra + T_AL + 16);
                al[mi][3] = lds32(ra + T_AL + 8 * SA + 16);
            }
#pragma unroll
            for (int nj = 0; nj < 8; nj++) {
                uint32_t rn = (uint32_t)(64 * wn + 8 * nj + g);
                uint32_t rb = base + rn * SA + 4 * t + ko;
                uint32_t bh0 = lds32(rb + T_BH);
                uint32_t bh1 = lds32(rb + T_BH + 16);
                uint32_t bl0 = lds32(rb + T_BL);
                uint32_t bl1 = lds32(rb + T_BL + 16);
                MMA_BF16(d[0][nj], ah[0], bh0, bh1);   // hi*hi
                MMA_BF16(d[1][nj], ah[1], bh0, bh1);
                MMA_BF16(d[0][nj], al[0], bh0, bh1);   // lo*hi
                MMA_BF16(d[1][nj], al[1], bh0, bh1);
                MMA_BF16(d[0][nj], ah[0], bl0, bl1);   // hi*lo
                MMA_BF16(d[1][nj], ah[1], bl0, bl1);
            }
        }
        __syncthreads();

        if (c + 2 < NKCH) {
            const int koe = (c + 2) * 32;
            const uint32_t bufb = sb + (uint32_t)(c & 1) * STAGE_SZ;
#pragma unroll
            for (int p = 0; p < 2; p++) {
                int row = lrow + p * 64;
                size_t ga = (size_t)(m0 + row) * DMODEL + koe + lch * 8;
                size_t gb = (size_t)(n0 + row) * DMODEL + koe + lch * 8;
                uint32_t so = bufb + (uint32_t)row * SA + lch * 16;
                CP16(so + T_AH, Ahi + ga);
                CP16(so + T_AL, Alo + ga);
                CP16(so + T_BH, Bhi + gb);
                CP16(so + T_BL, Blo + gb);
            }
            CP_COMMIT();
        }
    }

    // epilogue: each tile row pair -> float2 stores
#pragma unroll
    for (int mi = 0; mi < 2; mi++) {
        int r0 = m0 + 32 * wm + 16 * mi + g;
#pragma unroll
        for (int nj = 0; nj < 8; nj++) {
            int n = n0 + 64 * wn + 8 * nj + 2 * t;
            float2 lo2 = make_float2(d[mi][nj][0] * scale, d[mi][nj][1] * scale);
            float2 hi2 = make_float2(d[mi][nj][2] * scale, d[mi][nj][3] * scale);
            if (mode == 0) {
                *(float2*)(C + (size_t)r0 * DMODEL + n)       = lo2;
                *(float2*)(C + (size_t)(r0 + 8) * DMODEL + n) = hi2;
            } else {
                int h = n >> 6, dd = n & 63;
                int b0 = r0 >> 11, s0 = r0 & 2047;
                int b1 = (r0 + 8) >> 11, s1 = (r0 + 8) & 2047;
                *(float2*)(C + (((size_t)(b0 * NHEAD + h)) * S_LEN + s0) * HDIM + dd) = lo2;
                *(float2*)(C + (((size_t)(b1 * NHEAD + h)) * S_LEN + s1) * HDIM + dd) = hi2;
            }
        }
    }
}

// ---------------- fused causal flash-attention, fp32 (unchanged) ----------------
#define SMPAD 68

__global__ __launch_bounds__(256, 2)
void attn_kernel(const float* __restrict__ q, const float* __restrict__ k,
                 const float* __restrict__ v, float* __restrict__ att)
{
    extern __shared__ float sm[];
    float* Qs = sm;
    float* Ks = sm + 64 * SMPAD;
    float* Vs = sm + 2 * 64 * SMPAD;
    float* Ps = sm + 3 * 64 * SMPAD;

    const int tid   = threadIdx.x;
    const int bh    = blockIdx.y;
    const int qt    = (int)gridDim.x - 1 - (int)blockIdx.x;
    const int b     = bh >> 4;
    const int h     = bh & 15;
    const int qbase = qt * 64;

    const int lane  = tid & 31;
    const int rbase = (tid >> 5) * 8 + ((lane >> 4) << 2);
    const int cbase = (lane & 15) << 2;

    const size_t head_off = (size_t)bh * (S_LEN * HDIM);

    const float4* qg = (const float4*)(q + head_off + (size_t)qbase * HDIM);
#pragma unroll
    for (int i = 0; i < 4; i++) {
        int lin = i * 256 + tid;
        int r = lin >> 4, d = (lin & 15) << 2;
        *(float4*)&Qs[r * SMPAD + d] = qg[lin];
    }

    float o[4][4];
    float mrow[4], lrow[4];
#pragma unroll
    for (int i = 0; i < 4; i++) {
        mrow[i] = -1e30f; lrow[i] = 0.f;
#pragma unroll
        for (int j = 0; j < 4; j++) o[i][j] = 0.f;
    }

    for (int kt = 0; kt <= qt; kt++) {
        const float4* kg = (const float4*)(k + head_off + (size_t)kt * 64 * HDIM);
        const float4* vg = (const float4*)(v + head_off + (size_t)kt * 64 * HDIM);
#pragma unroll
        for (int i = 0; i < 4; i++) {
            int lin = i * 256 + tid;
            int r = lin >> 4, d = (lin & 15) << 2;
            *(float4*)&Ks[r * SMPAD + d] = kg[lin];
            *(float4*)&Vs[r * SMPAD + d] = vg[lin];
        }
        __syncthreads();

        float s[4][4];
#pragma unroll
        for (int i = 0; i < 4; i++)
#pragma unroll
            for (int j = 0; j < 4; j++) s[i][j] = 0.f;

#pragma unroll 4
        for (int d = 0; d < 64; d += 4) {
            float4 qv[4], kv[4];
#pragma unroll
            for (int i = 0; i < 4; i++) qv[i] = *(const float4*)&Qs[(rbase + i) * SMPAD + d];
#pragma unroll
            for (int j = 0; j < 4; j++) kv[j] = *(const float4*)&Ks[(cbase + j) * SMPAD + d];
#pragma unroll
            for (int i = 0; i < 4; i++)
#pragma unroll
                for (int j = 0; j < 4; j++)
                    s[i][j] += qv[i].x * kv[j].x + qv[i].y * kv[j].y
                             + qv[i].z * kv[j].z + qv[i].w * kv[j].w;
        }

        if (kt == qt) {
#pragma unroll
            for (int i = 0; i < 4; i++)
#pragma unroll
                for (int j = 0; j < 4; j++)
                    if (cbase + j > rbase + i) s[i][j] = -1e30f;
        }

#pragma unroll
        for (int i = 0; i < 4; i++) {
            float rm = fmaxf(fmaxf(s[i][0], s[i][1]), fmaxf(s[i][2], s[i][3]));
#pragma unroll
            for (int off = 8; off > 0; off >>= 1)
                rm = fmaxf(rm, __shfl_xor_sync(0xffffffffu, rm, off, 16));
            float mn = fmaxf(mrow[i], rm);
            float p0 = __expf(s[i][0] - mn);
            float p1 = __expf(s[i][1] - mn);
            float p2 = __expf(s[i][2] - mn);
            float p3 = __expf(s[i][3] - mn);
            float rs = (p0 + p1) + (p2 + p3);
#pragma unroll
            for (int off = 8; off > 0; off >>= 1)
                rs += __shfl_xor_sync(0xffffffffu, rs, off, 16);
            float al = __expf(mrow[i] - mn);
            lrow[i] = lrow[i] * al + rs;
            mrow[i] = mn;
#pragma unroll
            for (int j = 0; j < 4; j++) o[i][j] *= al;
            *(float4*)&Ps[(rbase + i) * SMPAD + cbase] = make_float4(p0, p1, p2, p3);
        }
        __syncthreads();

#pragma unroll 4
        for (int c = 0; c < 64; c += 4) {
            float4 pr[4], vr[4];
#pragma unroll
            for (int i = 0; i < 4; i++) pr[i] = *(const float4*)&Ps[(rbase + i) * SMPAD + c];
#pragma unroll
            for (int u = 0; u < 4; u++) vr[u] = *(const float4*)&Vs[(c + u) * SMPAD + cbase];
#pragma unroll
            for (int i = 0; i < 4; i++) {
                o[i][0] += pr[i].x * vr[0].x + pr[i].y * vr[1].x + pr[i].z * vr[2].x + pr[i].w * vr[3].x;
                o[i][1] += pr[i].x * vr[0].y + pr[i].y * vr[1].y + pr[i].z * vr[2].y + pr[i].w * vr[3].y;
                o[i][2] += pr[i].x * vr[0].z + pr[i].y * vr[1].z + pr[i].z * vr[2].z + pr[i].w * vr[3].z;
                o[i][3] += pr[i].x * vr[0].w + pr[i].y * vr[1].w + pr[i].z * vr[2].w + pr[i].w * vr[3].w;
            }
        }
        __syncthreads();
    }

#pragma unroll
    for (int i = 0; i < 4; i++) {
        float inv = 1.0f / lrow[i];
        int qpos = qbase + rbase + i;
        float4 r = make_float4(o[i][0] * inv, o[i][1] * inv, o[i][2] * inv, o[i][3] * inv);
        *(float4*)&att[((size_t)(b * S_LEN + qpos)) * DMODEL + h * HDIM + cbase] = r;
    }
}

// ---------------- launch ----------------
extern "C" void kernel_launch(void* const* d_in, const int* in_sizes, int n_in,
                              void* d_out, int out_size)
{
    const float* x  = (const float*)d_in[0];
    const float* Wq = (const float*)d_in[1];
    const float* Wk = (const float*)d_in[2];
    const float* Wv = (const float*)d_in[3];
    const float* Wo = (const float*)d_in[4];
    float* out = (float*)d_out;

    float *q, *k, *v, *att;
    __nv_bfloat16 *ahi, *alo, *wthi, *wtlo;
    cudaGetSymbolAddress((void**)&q,    g_q);
    cudaGetSymbolAddress((void**)&k,    g_k);
    cudaGetSymbolAddress((void**)&v,    g_v);
    cudaGetSymbolAddress((void**)&att,  g_att);
    cudaGetSymbolAddress((void**)&ahi,  g_ahi);
    cudaGetSymbolAddress((void**)&alo,  g_alo);
    cudaGetSymbolAddress((void**)&wthi, g_wthi);
    cudaGetSymbolAddress((void**)&wtlo, g_wtlo);

    cudaFuncSetAttribute(gemm_mma_kernel, cudaFuncAttributeMaxDynamicSharedMemorySize, GEMM_SMEM);
    const int attn_smem = 4 * 64 * SMPAD * (int)sizeof(float);
    cudaFuncSetAttribute(attn_kernel, cudaFuncAttributeMaxDynamicSharedMemorySize, attn_smem);

    const int n4 = NTOK * DMODEL / 4;
    dim3 wtgrid(DMODEL / 32, DMODEL / 32), wtblk(32, 8);
    dim3 ggrid(DMODEL / 128, NTOK / 128);   // (8, 64)

    // x -> bf16 hi/lo
    convert_split_kernel<<<n4 / 256, 256>>>(x, ahi, alo, n4);

    // QKV projections on HMMA tensor path (Q pre-scaled by 1/8)
    convert_wt_kernel<<<wtgrid, wtblk>>>(Wq, wthi, wtlo);
    gemm_mma_kernel<<<ggrid, 256, GEMM_SMEM>>>(ahi, alo, wthi, wtlo, q, 1, 0.125f);
    convert_wt_kernel<<<wtgrid, wtblk>>>(Wk, wthi, wtlo);
    gemm_mma_kernel<<<ggrid, 256, GEMM_SMEM>>>(ahi, alo, wthi, wtlo, k, 1, 1.0f);
    convert_wt_kernel<<<wtgrid, wtblk>>>(Wv, wthi, wtlo);
    gemm_mma_kernel<<<ggrid, 256, GEMM_SMEM>>>(ahi, alo, wthi, wtlo, v, 1, 1.0f);

    // fused causal attention (fp32)
    attn_kernel<<<dim3(S_LEN / 64, BATCH * NHEAD), 256, attn_smem>>>(q, k, v, att);

    // output projection
    convert_split_kernel<<<n4 / 256, 256>>>(att, ahi, alo, n4);
    convert_wt_kernel<<<wtgrid, wtblk>>>(Wo, wthi, wtlo);
    gemm_mma_kernel<<<ggrid, 256, GEMM_SMEM>>>(ahi, alo, wthi, wtlo, out, 0, 1.0f);
}

// round 8
// speedup vs baseline: 3.1540x; 2.1560x over previous
#include <cuda_runtime.h>
#include <cuda_bf16.h>
#include <cstdint>

#define S_LEN  2048
#define NHEAD  16
#define HDIM   64
#define DMODEL 1024
#define BATCH  4
#define NTOK   (BATCH * S_LEN)   // 8192
#define NBH    (BATCH * NHEAD)   // 64

// ---------------- scratch (no allocations allowed) ----------------
__device__ float         g_v[NBH * S_LEN * HDIM];      // fp32 V [bh][s][hd]
__device__ __nv_bfloat16 g_qhi[NBH * S_LEN * HDIM];    // [bh][s][hd], pre-scaled 1/8
__device__ __nv_bfloat16 g_qlo[NBH * S_LEN * HDIM];
__device__ __nv_bfloat16 g_khi[NBH * S_LEN * HDIM];
__device__ __nv_bfloat16 g_klo[NBH * S_LEN * HDIM];
__device__ __nv_bfloat16 g_vthi[NBH * HDIM * S_LEN];   // [bh][hd][s]
__device__ __nv_bfloat16 g_vtlo[NBH * HDIM * S_LEN];
__device__ __nv_bfloat16 g_ahi[NTOK * DMODEL];         // activation hi (x, later att)
__device__ __nv_bfloat16 g_alo[NTOK * DMODEL];
__device__ __nv_bfloat16 g_wthi[DMODEL * DMODEL];      // W^T hi [N,K]
__device__ __nv_bfloat16 g_wtlo[DMODEL * DMODEL];

// ================= helpers =================
__device__ __forceinline__ uint32_t smem_u32(const void* p) {
    uint32_t a;
    asm("{ .reg .u64 t; cvta.to.shared.u64 t, %1; cvt.u32.u64 %0, t; }" : "=r"(a) : "l"(p));
    return a;
}
__device__ __forceinline__ uint32_t lds32(uint32_t addr) {
    uint32_t v;
    asm volatile("ld.shared.b32 %0, [%1];" : "=r"(v) : "r"(addr));
    return v;
}
#define CP16(dst, src) \
    asm volatile("cp.async.cg.shared.global [%0], [%1], 16;" :: "r"(dst), "l"(src))
#define CP_COMMIT() asm volatile("cp.async.commit_group;" ::: "memory")
#define CP_WAIT1()  asm volatile("cp.async.wait_group 1;" ::: "memory")
#define CP_WAIT0()  asm volatile("cp.async.wait_group 0;" ::: "memory")

// bf16 warp MMA: D(16x8,f32) += A(16x16) * B(16x8)
#define MMA_BF16(d, a, b0, b1) \
    asm volatile("mma.sync.aligned.m16n8k16.row.col.f32.bf16.bf16.f32 " \
        "{%0,%1,%2,%3}, {%4,%5,%6,%7}, {%8,%9}, {%0,%1,%2,%3};" \
        : "+f"((d)[0]), "+f"((d)[1]), "+f"((d)[2]), "+f"((d)[3]) \
        : "r"((a)[0]), "r"((a)[1]), "r"((a)[2]), "r"((a)[3]), "r"(b0), "r"(b1))

// pack two f32 -> bf16x2 reg; low half = 'lo' (memory-first element)
__device__ __forceinline__ uint32_t packb(float lo, float hi) {
    uint32_t r;
    asm("cvt.rn.bf16x2.f32 %0, %1, %2;" : "=r"(r) : "f"(hi), "f"(lo));
    return r;
}
__device__ __forceinline__ float bres(float x) {
    return x - __bfloat162float(__float2bfloat16(x));
}

// ================= conversion kernels =================
__global__ void convert_split_kernel(const float* __restrict__ in,
                                     __nv_bfloat16* __restrict__ hi,
                                     __nv_bfloat16* __restrict__ lo, int n4) {
    int i = blockIdx.x * blockDim.x + threadIdx.x;
    if (i >= n4) return;
    float4 v = ((const float4*)in)[i];
    ((uint32_t*)hi)[2*i]   = packb(v.x, v.y);
    ((uint32_t*)hi)[2*i+1] = packb(v.z, v.w);
    ((uint32_t*)lo)[2*i]   = packb(bres(v.x), bres(v.y));
    ((uint32_t*)lo)[2*i+1] = packb(bres(v.z), bres(v.w));
}

// W [K,N] row-major -> W^T hi/lo [N,K]
__global__ void convert_wt_kernel(const float* __restrict__ W,
                                  __nv_bfloat16* __restrict__ hiT,
                                  __nv_bfloat16* __restrict__ loT) {
    __shared__ float sm[32][33];
    int n0 = blockIdx.x * 32, k0 = blockIdx.y * 32;
    int tx = threadIdx.x, ty = threadIdx.y;   // 32 x 8
#pragma unroll
    for (int i = 0; i < 4; i++)
        sm[ty + 8*i][tx] = W[(size_t)(k0 + ty + 8*i) * DMODEL + n0 + tx];
    __syncthreads();
#pragma unroll
    for (int i = 0; i < 4; i++) {
        float v = sm[tx][ty + 8*i];
        size_t o = (size_t)(n0 + ty + 8*i) * DMODEL + k0 + tx;
        hiT[o] = __float2bfloat16(v);
        loT[o] = __float2bfloat16(bres(v));
    }
}

// V fp32 [bh][s][hd] -> VT bf16 hi/lo [bh][hd][s]
__global__ void vt_kernel(const float* __restrict__ v,
                          __nv_bfloat16* __restrict__ vth,
                          __nv_bfloat16* __restrict__ vtl) {
    __shared__ float sm[32][33];
    int s0 = blockIdx.x * 32, d0 = blockIdx.y * 32, bh = blockIdx.z;
    int tx = threadIdx.x, ty = threadIdx.y;   // 32 x 8
    const float* vb = v + (size_t)bh * S_LEN * HDIM;
#pragma unroll
    for (int i = 0; i < 4; i++)
        sm[ty + 8*i][tx] = vb[(size_t)(s0 + ty + 8*i) * HDIM + d0 + tx];
    __syncthreads();
#pragma unroll
    for (int i = 0; i < 4; i++) {
        float f = sm[tx][ty + 8*i];           // = V[s0+tx][d0+ty+8i]
        size_t o = (size_t)bh * HDIM * S_LEN + (size_t)(d0 + ty + 8*i) * S_LEN + s0 + tx;
        vth[o] = __float2bfloat16(f);
        vtl[o] = __float2bfloat16(bres(f));
    }
}

// ================= bf16-split GEMM on mma.sync (HMMA) =================
// mode 0: fp32 C row-major; mode 1: fp32 scatter [b,h,s,hd];
// mode 2: bf16 hi/lo scatter [b,h,s,hd]
#define SA       80
#define T_AH     0
#define T_AL     (128 * SA)
#define T_BH     (2 * 128 * SA)
#define T_BL     (3 * 128 * SA)
#define STAGE_SZ (4 * 128 * SA)
#define GEMM_SMEM (2 * STAGE_SZ)
#define NKCH     (DMODEL / 32)

__global__ __launch_bounds__(256, 2)
void gemm_mma_kernel(const __nv_bfloat16* __restrict__ Ahi, const __nv_bfloat16* __restrict__ Alo,
                     const __nv_bfloat16* __restrict__ Bhi, const __nv_bfloat16* __restrict__ Blo,
                     float* __restrict__ C, __nv_bfloat16* __restrict__ Chi,
                     __nv_bfloat16* __restrict__ Clo, int mode, float scale)
{
    extern __shared__ char smem[];
    const uint32_t sb = smem_u32(smem);
    const int tid  = threadIdx.x;
    const int lane = tid & 31;
    const int wid  = tid >> 5;
    const int wm   = wid & 3;
    const int wn   = wid >> 2;
    const int m0   = blockIdx.y * 128;
    const int n0   = blockIdx.x * 128;
    const int g    = lane >> 2;
    const int t    = lane & 3;

    const int lrow = tid >> 2;
    const int lch  = tid & 3;

    float d[2][8][4];
#pragma unroll
    for (int i = 0; i < 2; i++)
#pragma unroll
        for (int j = 0; j < 8; j++)
#pragma unroll
            for (int e = 0; e < 4; e++) d[i][j][e] = 0.f;

#pragma unroll
    for (int c = 0; c < 2; c++) {
        const int koe = c * 32;
        const uint32_t bufb = sb + c * STAGE_SZ;
#pragma unroll
        for (int p = 0; p < 2; p++) {
            int row = lrow + p * 64;
            size_t ga = (size_t)(m0 + row) * DMODEL + koe + lch * 8;
            size_t gb = (size_t)(n0 + row) * DMODEL + koe + lch * 8;
            uint32_t so = bufb + (uint32_t)row * SA + lch * 16;
            CP16(so + T_AH, Ahi + ga);
            CP16(so + T_AL, Alo + ga);
            CP16(so + T_BH, Bhi + gb);
            CP16(so + T_BL, Blo + gb);
        }
        CP_COMMIT();
    }

    for (int c = 0; c < NKCH; c++) {
        if (c + 1 < NKCH) { CP_WAIT1(); } else { CP_WAIT0(); }
        __syncthreads();
        const uint32_t base = sb + (uint32_t)(c & 1) * STAGE_SZ;

#pragma unroll
        for (int ks = 0; ks < 2; ks++) {
            const uint32_t ko = (uint32_t)ks * 32;
            uint32_t ah[2][4], al[2][4];
#pragma unroll
            for (int mi = 0; mi < 2; mi++) {
                uint32_t r0 = (uint32_t)(32 * wm + 16 * mi + g);
                uint32_t ra = base + r0 * SA + 4 * t + ko;
                ah[mi][0] = lds32(ra + T_AH);
                ah[mi][1] = lds32(ra + T_AH + 8 * SA);
                ah[mi][2] = lds32(ra + T_AH + 16);
                ah[mi][3] = lds32(ra + T_AH + 8 * SA + 16);
                al[mi][0] = lds32(ra + T_AL);
                al[mi][1] = lds32(ra + T_AL + 8 * SA);
                al[mi][2] = lds32(ra + T_AL + 16);
                al[mi][3] = lds32(ra + T_AL + 8 * SA + 16);
            }
#pragma unroll
            for (int nj = 0; nj < 8; nj++) {
                uint32_t rn = (uint32_t)(64 * wn + 8 * nj + g);
                uint32_t rb = base + rn * SA + 4 * t + ko;
                uint32_t bh0 = lds32(rb + T_BH);
                uint32_t bh1 = lds32(rb + T_BH + 16);
                uint32_t bl0 = lds32(rb + T_BL);
                uint32_t bl1 = lds32(rb + T_BL + 16);
                MMA_BF16(d[0][nj], ah[0], bh0, bh1);
                MMA_BF16(d[1][nj], ah[1], bh0, bh1);
                MMA_BF16(d[0][nj], al[0], bh0, bh1);
                MMA_BF16(d[1][nj], al[1], bh0, bh1);
                MMA_BF16(d[0][nj], ah[0], bl0, bl1);
                MMA_BF16(d[1][nj], ah[1], bl0, bl1);
            }
        }
        __syncthreads();

        if (c + 2 < NKCH) {
            const int koe = (c + 2) * 32;
            const uint32_t bufb = sb + (uint32_t)(c & 1) * STAGE_SZ;
#pragma unroll
            for (int p = 0; p < 2; p++) {
                int row = lrow + p * 64;
                size_t ga = (size_t)(m0 + row) * DMODEL + koe + lch * 8;
                size_t gb = (size_t)(n0 + row) * DMODEL + koe + lch * 8;
                uint32_t so = bufb + (uint32_t)row * SA + lch * 16;
                CP16(so + T_AH, Ahi + ga);
                CP16(so + T_AL, Alo + ga);
                CP16(so + T_BH, Bhi + gb);
                CP16(so + T_BL, Blo + gb);
            }
            CP_COMMIT();
        }
    }

#pragma unroll
    for (int mi = 0; mi < 2; mi++) {
        int r0 = m0 + 32 * wm + 16 * mi + g;
#pragma unroll
        for (int nj = 0; nj < 8; nj++) {
            int n = n0 + 64 * wn + 8 * nj + 2 * t;
            float f0 = d[mi][nj][0] * scale, f1 = d[mi][nj][1] * scale;
            float f2 = d[mi][nj][2] * scale, f3 = d[mi][nj][3] * scale;
            if (mode == 0) {
                *(float2*)(C + (size_t)r0 * DMODEL + n)       = make_float2(f0, f1);
                *(float2*)(C + (size_t)(r0 + 8) * DMODEL + n) = make_float2(f2, f3);
            } else {
                int h = n >> 6, dd = n & 63;
                int b0 = r0 >> 11, s0 = r0 & 2047;
                int b1 = (r0 + 8) >> 11, s1 = (r0 + 8) & 2047;
                size_t o0 = (((size_t)(b0 * NHEAD + h)) * S_LEN + s0) * HDIM + dd;
                size_t o1 = (((size_t)(b1 * NHEAD + h)) * S_LEN + s1) * HDIM + dd;
                if (mode == 1) {
                    *(float2*)(C + o0) = make_float2(f0, f1);
                    *(float2*)(C + o1) = make_float2(f2, f3);
                } else {
                    *(uint32_t*)(Chi + o0) = packb(f0, f1);
                    *(uint32_t*)(Clo + o0) = packb(bres(f0), bres(f1));
                    *(uint32_t*)(Chi + o1) = packb(f2, f3);
                    *(uint32_t*)(Clo + o1) = packb(bres(f2), bres(f3));
                }
            }
        }
    }
}

// ================= tensor-core causal flash-attention =================
// CTA: 128 q rows x one (b,h). 8 warps, 16 q rows each. K/V tiles of 64 keys,
// 2-stage cp.async. All MMA work in bf16 hi/lo split, fp32 softmax/accum.
#define AT_STRIDE 144
#define AT_KH 0
#define AT_KL (64 * AT_STRIDE)
#define AT_VH (2 * 64 * AT_STRIDE)
#define AT_VL (3 * 64 * AT_STRIDE)
#define AT_STAGE (4 * 64 * AT_STRIDE)   // 36864
#define ATT_SMEM (2 * AT_STAGE)         // 73728

__global__ __launch_bounds__(256, 2)
void attn_tc_kernel(const __nv_bfloat16* __restrict__ qh_, const __nv_bfloat16* __restrict__ ql_,
                    const __nv_bfloat16* __restrict__ kh_, const __nv_bfloat16* __restrict__ kl_,
                    const __nv_bfloat16* __restrict__ vth_, const __nv_bfloat16* __restrict__ vtl_,
                    __nv_bfloat16* __restrict__ outh, __nv_bfloat16* __restrict__ outl)
{
    extern __shared__ char smem[];
    const uint32_t sb = smem_u32(smem);
    const int tid = threadIdx.x, lane = tid & 31, wid = tid >> 5;
    const int g = lane >> 2, t = lane & 3;
    const int qt = (int)gridDim.x - 1 - (int)blockIdx.x;   // heavy tiles first
    const int bh = blockIdx.y;
    const int bidx = bh >> 4, hidx = bh & 15;
    const int qbase = qt * 128;
    const int ktlast = 2 * qt + 1;

    const __nv_bfloat16* qh  = qh_  + (size_t)bh * (S_LEN * HDIM);
    const __nv_bfloat16* ql  = ql_  + (size_t)bh * (S_LEN * HDIM);
    const __nv_bfloat16* kh  = kh_  + (size_t)bh * (S_LEN * HDIM);
    const __nv_bfloat16* kl  = kl_  + (size_t)bh * (S_LEN * HDIM);
    const __nv_bfloat16* vth = vth_ + (size_t)bh * (HDIM * S_LEN);
    const __nv_bfloat16* vtl = vtl_ + (size_t)bh * (HDIM * S_LEN);

    // ---- persistent Q fragments (16 rows x 64 hd, hi/lo) ----
    uint32_t qfh[4][4], qfl[4][4];
    {
        const int r0 = 16 * wid + g;
        const uint32_t* ph = (const uint32_t*)(qh + (size_t)(qbase + r0) * HDIM);
        const uint32_t* pl = (const uint32_t*)(ql + (size_t)(qbase + r0) * HDIM);
#pragma unroll
        for (int ks = 0; ks < 4; ks++) {
            qfh[ks][0] = ph[8*ks + t];        qfh[ks][2] = ph[8*ks + t + 4];
            qfh[ks][1] = ph[256 + 8*ks + t];  qfh[ks][3] = ph[256 + 8*ks + t + 4];
            qfl[ks][0] = pl[8*ks + t];        qfl[ks][2] = pl[8*ks + t + 4];
            qfl[ks][1] = pl[256 + 8*ks + t];  qfl[ks][3] = pl[256 + 8*ks + t + 4];
        }
    }

    float o[8][4];
#pragma unroll
    for (int j = 0; j < 8; j++)
#pragma unroll
        for (int e = 0; e < 4; e++) o[j][e] = 0.f;
    float m0 = -1e30f, m1 = -1e30f, l0 = 0.f, l1 = 0.f;

    const int lrow = tid >> 3, lch = tid & 7;
    auto stage_load = [&](int kt) {
        const uint32_t dst = sb + (uint32_t)(kt & 1) * AT_STAGE;
#pragma unroll
        for (int p = 0; p < 2; p++) {
            int r = lrow + 32 * p;
            uint32_t so = dst + (uint32_t)r * AT_STRIDE + lch * 16;
            CP16(so + AT_KH, kh  + (size_t)(kt * 64 + r) * HDIM + lch * 8);
            CP16(so + AT_KL, kl  + (size_t)(kt * 64 + r) * HDIM + lch * 8);
            CP16(so + AT_VH, vth + (size_t)r * S_LEN + kt * 64 + lch * 8);
            CP16(so + AT_VL, vtl + (size_t)r * S_LEN + kt * 64 + lch * 8);
        }
        CP_COMMIT();
    };
    stage_load(0);
    stage_load(1);

    for (int kt = 0; kt <= ktlast; kt++) {
        if (kt + 1 <= ktlast) { CP_WAIT1(); } else { CP_WAIT0(); }
        __syncthreads();

        // last (diagonal-upper) tile: lower warp half fully masked -> skip
        const bool active = !(kt == ktlast && wid < 4);
        if (active) {
            const uint32_t base = sb + (uint32_t)(kt & 1) * AT_STAGE
                                + (uint32_t)g * AT_STRIDE + 4 * t;

            // ---- S = Q K^T (split) ----
            float s[8][4];
#pragma unroll
            for (int j = 0; j < 8; j++)
#pragma unroll
                for (int e = 0; e < 4; e++) s[j][e] = 0.f;
#pragma unroll
            for (int nj = 0; nj < 8; nj++) {
                uint32_t ro = base + (uint32_t)(8 * nj) * AT_STRIDE;
#pragma unroll
                for (int ks = 0; ks < 4; ks++) {
                    uint32_t a = ro + ks * 32;
                    uint32_t b0 = lds32(a + AT_KH), b1 = lds32(a + AT_KH + 16);
                    uint32_t c0 = lds32(a + AT_KL), c1 = lds32(a + AT_KL + 16);
                    MMA_BF16(s[nj], qfh[ks], b0, b1);
                    MMA_BF16(s[nj], qfl[ks], b0, b1);
                    MMA_BF16(s[nj], qfh[ks], c0, c1);
                }
            }

            // ---- causal mask (only the top 2 k-tiles can intersect diag) ----
            if (kt >= 2 * qt) {
                const int kb = (kt - 2 * qt) * 64;
                const int r0 = 16 * wid + g, r1 = r0 + 8;
#pragma unroll
                for (int nj = 0; nj < 8; nj++) {
                    int k0 = kb + 8 * nj + 2 * t, k1 = k0 + 1;
                    if (k0 > r0) s[nj][0] = -1e30f;
                    if (k1 > r0) s[nj][1] = -1e30f;
                    if (k0 > r1) s[nj][2] = -1e30f;
                    if (k1 > r1) s[nj][3] = -1e30f;
                }
            }

            // ---- online softmax ----
            float mx0 = -1e30f, mx1 = -1e30f;
#pragma unroll
            for (int nj = 0; nj < 8; nj++) {
                mx0 = fmaxf(mx0, fmaxf(s[nj][0], s[nj][1]));
                mx1 = fmaxf(mx1, fmaxf(s[nj][2], s[nj][3]));
            }
            mx0 = fmaxf(mx0, __shfl_xor_sync(0xffffffffu, mx0, 1));
            mx0 = fmaxf(mx0, __shfl_xor_sync(0xffffffffu, mx0, 2));
            mx1 = fmaxf(mx1, __shfl_xor_sync(0xffffffffu, mx1, 1));
            mx1 = fmaxf(mx1, __shfl_xor_sync(0xffffffffu, mx1, 2));
            float mn0 = fmaxf(m0, mx0), mn1 = fmaxf(m1, mx1);
            float al0 = __expf(m0 - mn0), al1 = __expf(m1 - mn1);
            m0 = mn0; m1 = mn1;

            float rs0 = 0.f, rs1 = 0.f;
#pragma unroll
            for (int nj = 0; nj < 8; nj++) {
                s[nj][0] = __expf(s[nj][0] - mn0);
                s[nj][1] = __expf(s[nj][1] - mn0);
                s[nj][2] = __expf(s[nj][2] - mn1);
                s[nj][3] = __expf(s[nj][3] - mn1);
                rs0 += s[nj][0] + s[nj][1];
                rs1 += s[nj][2] + s[nj][3];
            }
            rs0 += __shfl_xor_sync(0xffffffffu, rs0, 1);
            rs0 += __shfl_xor_sync(0xffffffffu, rs0, 2);
            rs1 += __shfl_xor_sync(0xffffffffu, rs1, 1);
            rs1 += __shfl_xor_sync(0xffffffffu, rs1, 2);
            l0 = l0 * al0 + rs0;
            l1 = l1 * al1 + rs1;
#pragma unroll
            for (int nj = 0; nj < 8; nj++) {
                o[nj][0] *= al0; o[nj][1] *= al0;
                o[nj][2] *= al1; o[nj][3] *= al1;
            }

            // ---- P: accumulator -> A-fragments (regs only), hi/lo split ----
            uint32_t pah[4][4], pal[4][4];
#pragma unroll
            for (int ksn = 0; ksn < 4; ksn++) {
                int ja = 2 * ksn, jb = ja + 1;
                pah[ksn][0] = packb(s[ja][0], s[ja][1]);
                pah[ksn][1] = packb(s[ja][2], s[ja][3]);
                pah[ksn][2] = packb(s[jb][0], s[jb][1]);
                pah[ksn][3] = packb(s[jb][2], s[jb][3]);
                pal[ksn][0] = packb(bres(s[ja][0]), bres(s[ja][1]));
                pal[ksn][1] = packb(bres(s[ja][2]), bres(s[ja][3]));
                pal[ksn][2] = packb(bres(s[jb][0]), bres(s[jb][1]));
                pal[ksn][3] = packb(bres(s[jb][2]), bres(s[jb][3]));
            }

            // ---- O += P V (split) ----
#pragma unroll
            for (int nj = 0; nj < 8; nj++) {
                uint32_t ro = base + (uint32_t)(8 * nj) * AT_STRIDE;
#pragma unroll
                for (int ksn = 0; ksn < 4; ksn++) {
                    uint32_t a = ro + ksn * 32;
                    uint32_t b0 = lds32(a + AT_VH), b1 = lds32(a + AT_VH + 16);
                    uint32_t c0 = lds32(a + AT_VL), c1 = lds32(a + AT_VL + 16);
                    MMA_BF16(o[nj], pah[ksn], b0, b1);
                    MMA_BF16(o[nj], pal[ksn], b0, b1);
                    MMA_BF16(o[nj], pah[ksn], c0, c1);
                }
            }
        }
        __syncthreads();
        if (kt + 2 <= ktlast) stage_load(kt + 2);
    }

    // ---- epilogue: normalize, emit att as bf16 hi/lo in [b*s][h*hd] ----
    const float inv0 = 1.f / l0, inv1 = 1.f / l1;
    const int r0 = qbase + 16 * wid + g;
    const size_t base0 = ((size_t)bidx * S_LEN + r0) * DMODEL + hidx * 64 + 2 * t;
#pragma unroll
    for (int nj = 0; nj < 8; nj++) {
        float f0 = o[nj][0] * inv0, f1 = o[nj][1] * inv0;
        float f2 = o[nj][2] * inv1, f3 = o[nj][3] * inv1;
        size_t o0 = base0 + 8 * nj;
        size_t o1 = o0 + 8 * DMODEL;
        *(uint32_t*)(outh + o0) = packb(f0, f1);
        *(uint32_t*)(outl + o0) = packb(bres(f0), bres(f1));
        *(uint32_t*)(outh + o1) = packb(f2, f3);
        *(uint32_t*)(outl + o1) = packb(bres(f2), bres(f3));
    }
}

// ---------------- launch ----------------
extern "C" void kernel_launch(void* const* d_in, const int* in_sizes, int n_in,
                              void* d_out, int out_size)
{
    const float* x  = (const float*)d_in[0];
    const float* Wq = (const float*)d_in[1];
    const float* Wk = (const float*)d_in[2];
    const float* Wv = (const float*)d_in[3];
    const float* Wo = (const float*)d_in[4];
    float* out = (float*)d_out;

    float* v;
    __nv_bfloat16 *qhi, *qlo, *khi, *klo, *vthi, *vtlo, *ahi, *alo, *wthi, *wtlo;
    cudaGetSymbolAddress((void**)&v,    g_v);
    cudaGetSymbolAddress((void**)&qhi,  g_qhi);
    cudaGetSymbolAddress((void**)&qlo,  g_qlo);
    cudaGetSymbolAddress((void**)&khi,  g_khi);
    cudaGetSymbolAddress((void**)&klo,  g_klo);
    cudaGetSymbolAddress((void**)&vthi, g_vthi);
    cudaGetSymbolAddress((void**)&vtlo, g_vtlo);
    cudaGetSymbolAddress((void**)&ahi,  g_ahi);
    cudaGetSymbolAddress((void**)&alo,  g_alo);
    cudaGetSymbolAddress((void**)&wthi, g_wthi);
    cudaGetSymbolAddress((void**)&wtlo, g_wtlo);

    cudaFuncSetAttribute(gemm_mma_kernel, cudaFuncAttributeMaxDynamicSharedMemorySize, GEMM_SMEM);
    cudaFuncSetAttribute(attn_tc_kernel, cudaFuncAttributeMaxDynamicSharedMemorySize, ATT_SMEM);

    const int n4 = NTOK * DMODEL / 4;
    dim3 wtgrid(DMODEL / 32, DMODEL / 32), wtblk(32, 8);
    dim3 ggrid(DMODEL / 128, NTOK / 128);

    // x -> bf16 hi/lo
    convert_split_kernel<<<n4 / 256, 256>>>(x, ahi, alo, n4);

    // projections: Q,K -> bf16 hi/lo scatter; V -> fp32 scatter then transpose
    convert_wt_kernel<<<wtgrid, wtblk>>>(Wq, wthi, wtlo);
    gemm_mma_kernel<<<ggrid, 256, GEMM_SMEM>>>(ahi, alo, wthi, wtlo, nullptr, qhi, qlo, 2, 0.125f);
    convert_wt_kernel<<<wtgrid, wtblk>>>(Wk, wthi, wtlo);
    gemm_mma_kernel<<<ggrid, 256, GEMM_SMEM>>>(ahi, alo, wthi, wtlo, nullptr, khi, klo, 2, 1.0f);
    convert_wt_kernel<<<wtgrid, wtblk>>>(Wv, wthi, wtlo);
    gemm_mma_kernel<<<ggrid, 256, GEMM_SMEM>>>(ahi, alo, wthi, wtlo, v, nullptr, nullptr, 1, 1.0f);
    vt_kernel<<<dim3(S_LEN / 32, HDIM / 32, NBH), dim3(32, 8)>>>(v, vthi, vtlo);

    // fused causal attention on tensor cores -> att bf16 hi/lo
    attn_tc_kernel<<<dim3(S_LEN / 128, NBH), 256, ATT_SMEM>>>(
        qhi, qlo, khi, klo, vthi, vtlo, ahi, alo);

    // output projection
    convert_wt_kernel<<<wtgrid, wtblk>>>(Wo, wthi, wtlo);
    gemm_mma_kernel<<<ggrid, 256, GEMM_SMEM>>>(ahi, alo, wthi, wtlo, out, nullptr, nullptr, 0, 1.0f);
}

// round 9
// speedup vs baseline: 3.4618x; 1.0976x over previous
#include <cuda_runtime.h>
#include <cuda_bf16.h>
#include <cstdint>

#define S_LEN  2048
#define NHEAD  16
#define HDIM   64
#define DMODEL 1024
#define BATCH  4
#define NTOK   (BATCH * S_LEN)   // 8192
#define NBH    (BATCH * NHEAD)   // 64

// ---------------- scratch (no allocations allowed) ----------------
__device__ float         g_v[NBH * S_LEN * HDIM];      // fp32 V [bh][s][hd]
__device__ __nv_bfloat16 g_qhi[NBH * S_LEN * HDIM];    // [bh][s][hd], pre-scaled 1/8
__device__ __nv_bfloat16 g_qlo[NBH * S_LEN * HDIM];
__device__ __nv_bfloat16 g_khi[NBH * S_LEN * HDIM];
__device__ __nv_bfloat16 g_klo[NBH * S_LEN * HDIM];
__device__ __nv_bfloat16 g_vthi[NBH * HDIM * S_LEN];   // [bh][hd][s]
__device__ __nv_bfloat16 g_vtlo[NBH * HDIM * S_LEN];
__device__ __nv_bfloat16 g_ahi[NTOK * DMODEL];         // activation hi (x, later att)
__device__ __nv_bfloat16 g_alo[NTOK * DMODEL];
__device__ __nv_bfloat16 g_wt3hi[3 * DMODEL * DMODEL]; // [Wq^T;Wk^T;Wv^T] hi (also Wo^T)
__device__ __nv_bfloat16 g_wt3lo[3 * DMODEL * DMODEL];

// ================= helpers =================
__device__ __forceinline__ uint32_t smem_u32(const void* p) {
    uint32_t a;
    asm("{ .reg .u64 t; cvta.to.shared.u64 t, %1; cvt.u32.u64 %0, t; }" : "=r"(a) : "l"(p));
    return a;
}
__device__ __forceinline__ uint32_t lds32(uint32_t addr) {
    uint32_t v;
    asm volatile("ld.shared.b32 %0, [%1];" : "=r"(v) : "r"(addr));
    return v;
}
#define CP16(dst, src) \
    asm volatile("cp.async.cg.shared.global [%0], [%1], 16;" :: "r"(dst), "l"(src))
#define CP_COMMIT() asm volatile("cp.async.commit_group;" ::: "memory")
#define CP_WAIT1()  asm volatile("cp.async.wait_group 1;" ::: "memory")
#define CP_WAIT0()  asm volatile("cp.async.wait_group 0;" ::: "memory")

// bf16 warp MMA: D(16x8,f32) += A(16x16) * B(16x8)
#define MMA_BF16(d, a, b0, b1) \
    asm volatile("mma.sync.aligned.m16n8k16.row.col.f32.bf16.bf16.f32 " \
        "{%0,%1,%2,%3}, {%4,%5,%6,%7}, {%8,%9}, {%0,%1,%2,%3};" \
        : "+f"((d)[0]), "+f"((d)[1]), "+f"((d)[2]), "+f"((d)[3]) \
        : "r"((a)[0]), "r"((a)[1]), "r"((a)[2]), "r"((a)[3]), "r"(b0), "r"(b1))

// pack two f32 -> bf16x2 reg; low half = memory-first element
__device__ __forceinline__ uint32_t packb(float lo, float hi) {
    uint32_t r;
    asm("cvt.rn.bf16x2.f32 %0, %1, %2;" : "=r"(r) : "f"(hi), "f"(lo));
    return r;
}
__device__ __forceinline__ float bres(float x) {
    return x - __bfloat162float(__float2bfloat16(x));
}

// ================= conversion kernels =================
__global__ void convert_split_kernel(const float* __restrict__ in,
                                     __nv_bfloat16* __restrict__ hi,
                                     __nv_bfloat16* __restrict__ lo, int n4) {
    int i = blockIdx.x * blockDim.x + threadIdx.x;
    if (i >= n4) return;
    float4 v = ((const float4*)in)[i];
    ((uint32_t*)hi)[2*i]   = packb(v.x, v.y);
    ((uint32_t*)hi)[2*i+1] = packb(v.z, v.w);
    ((uint32_t*)lo)[2*i]   = packb(bres(v.x), bres(v.y));
    ((uint32_t*)lo)[2*i+1] = packb(bres(v.z), bres(v.w));
}

// W [K,N] row-major -> W^T hi/lo [N,K]
__global__ void convert_wt_kernel(const float* __restrict__ W,
                                  __nv_bfloat16* __restrict__ hiT,
                                  __nv_bfloat16* __restrict__ loT) {
    __shared__ float sm[32][33];
    int n0 = blockIdx.x * 32, k0 = blockIdx.y * 32;
    int tx = threadIdx.x, ty = threadIdx.y;   // 32 x 8
#pragma unroll
    for (int i = 0; i < 4; i++)
        sm[ty + 8*i][tx] = W[(size_t)(k0 + ty + 8*i) * DMODEL + n0 + tx];
    __syncthreads();
#pragma unroll
    for (int i = 0; i < 4; i++) {
        float v = sm[tx][ty + 8*i];
        size_t o = (size_t)(n0 + ty + 8*i) * DMODEL + k0 + tx;
        hiT[o] = __float2bfloat16(v);
        loT[o] = __float2bfloat16(bres(v));
    }
}

// V fp32 [bh][s][hd] -> VT bf16 hi/lo [bh][hd][s]
__global__ void vt_kernel(const float* __restrict__ v,
                          __nv_bfloat16* __restrict__ vth,
                          __nv_bfloat16* __restrict__ vtl) {
    __shared__ float sm[32][33];
    int s0 = blockIdx.x * 32, d0 = blockIdx.y * 32, bh = blockIdx.z;
    int tx = threadIdx.x, ty = threadIdx.y;   // 32 x 8
    const float* vb = v + (size_t)bh * S_LEN * HDIM;
#pragma unroll
    for (int i = 0; i < 4; i++)
        sm[ty + 8*i][tx] = vb[(size_t)(s0 + ty + 8*i) * HDIM + d0 + tx];
    __syncthreads();
#pragma unroll
    for (int i = 0; i < 4; i++) {
        float f = sm[tx][ty + 8*i];
        size_t o = (size_t)bh * HDIM * S_LEN + (size_t)(d0 + ty + 8*i) * S_LEN + s0 + tx;
        vth[o] = __float2bfloat16(f);
        vtl[o] = __float2bfloat16(bres(f));
    }
}

// ================= bf16-split GEMM, 64x64 warp tile =================
// CTA tile 128x128, 4 warps (2x2), K chunk 32, 2-stage cp.async.
// mode 0: fp32 C row-major (out-proj). mode 3: fused QKV — n selects projection:
//   [0,1024)  -> Q bf16 hi/lo scatter [b,h,s,hd], scaled 0.125
//   [1024,2048) -> K bf16 hi/lo scatter
//   [2048,3072) -> V fp32 scatter
#define SA       80
#define T_AH     0
#define T_AL     (128 * SA)
#define T_BH     (2 * 128 * SA)
#define T_BL     (3 * 128 * SA)
#define STAGE_SZ (4 * 128 * SA)
#define GEMM_SMEM (2 * STAGE_SZ)       // 81920
#define NKCH     (DMODEL / 32)

__global__ __launch_bounds__(128, 2)
void gemm_mma_kernel(const __nv_bfloat16* __restrict__ Ahi, const __nv_bfloat16* __restrict__ Alo,
                     const __nv_bfloat16* __restrict__ Bhi, const __nv_bfloat16* __restrict__ Blo,
                     float* __restrict__ C,
                     __nv_bfloat16* __restrict__ Qhi, __nv_bfloat16* __restrict__ Qlo,
                     __nv_bfloat16* __restrict__ Khi, __nv_bfloat16* __restrict__ Klo,
                     float* __restrict__ Vf, int mode)
{
    extern __shared__ char smem[];
    const uint32_t sb = smem_u32(smem);
    const int tid  = threadIdx.x;
    const int lane = tid & 31;
    const int wid  = tid >> 5;
    const int wm   = wid & 1;        // 2 warps along M, 64 rows each
    const int wn   = wid >> 1;       // 2 warps along N, 64 cols each
    const int m0   = blockIdx.y * 128;
    const int n0   = blockIdx.x * 128;
    const int g    = lane >> 2;
    const int t    = lane & 3;

    const int lrow = tid >> 2;       // 0..31 (+32p)
    const int lch  = tid & 3;        // 16B chunk in 64B row

    float d[4][8][4];
#pragma unroll
    for (int i = 0; i < 4; i++)
#pragma unroll
        for (int j = 0; j < 8; j++)
#pragma unroll
            for (int e = 0; e < 4; e++) d[i][j][e] = 0.f;

    // prologue: stages 0,1
#pragma unroll
    for (int c = 0; c < 2; c++) {
        const int koe = c * 32;
        const uint32_t bufb = sb + c * STAGE_SZ;
#pragma unroll
        for (int p = 0; p < 4; p++) {
            int row = lrow + 32 * p;
            size_t ga = (size_t)(m0 + row) * DMODEL + koe + lch * 8;
            size_t gb = (size_t)(n0 + row) * DMODEL + koe + lch * 8;
            uint32_t so = bufb + (uint32_t)row * SA + lch * 16;
            CP16(so + T_AH, Ahi + ga);
            CP16(so + T_AL, Alo + ga);
            CP16(so + T_BH, Bhi + gb);
            CP16(so + T_BL, Blo + gb);
        }
        CP_COMMIT();
    }

    for (int c = 0; c < NKCH; c++) {
        if (c + 1 < NKCH) { CP_WAIT1(); } else { CP_WAIT0(); }
        __syncthreads();
        const uint32_t base = sb + (uint32_t)(c & 1) * STAGE_SZ;

#pragma unroll
        for (int ks = 0; ks < 2; ks++) {
            const uint32_t ko = (uint32_t)ks * 32;
            uint32_t ah[4][4], al[4][4];
#pragma unroll
            for (int mi = 0; mi < 4; mi++) {
                uint32_t r0 = (uint32_t)(64 * wm + 16 * mi + g);
                uint32_t ra = base + r0 * SA + 4 * t + ko;
                ah[mi][0] = lds32(ra + T_AH);
                ah[mi][1] = lds32(ra + T_AH + 8 * SA);
                ah[mi][2] = lds32(ra + T_AH + 16);
                ah[mi][3] = lds32(ra + T_AH + 8 * SA + 16);
                al[mi][0] = lds32(ra + T_AL);
                al[mi][1] = lds32(ra + T_AL + 8 * SA);
                al[mi][2] = lds32(ra + T_AL + 16);
                al[mi][3] = lds32(ra + T_AL + 8 * SA + 16);
            }
#pragma unroll
            for (int nj = 0; nj < 8; nj++) {
                uint32_t rn = (uint32_t)(64 * wn + 8 * nj + g);
                uint32_t rb = base + rn * SA + 4 * t + ko;
                uint32_t bh0 = lds32(rb + T_BH);
                uint32_t bh1 = lds32(rb + T_BH + 16);
                uint32_t bl0 = lds32(rb + T_BL);
                uint32_t bl1 = lds32(rb + T_BL + 16);
#pragma unroll
                for (int mi = 0; mi < 4; mi++) {
                    MMA_BF16(d[mi][nj], ah[mi], bh0, bh1);
                    MMA_BF16(d[mi][nj], al[mi], bh0, bh1);
                    MMA_BF16(d[mi][nj], ah[mi], bl0, bl1);
                }
            }
        }
        __syncthreads();

        if (c + 2 < NKCH) {
            const int koe = (c + 2) * 32;
            const uint32_t bufb = sb + (uint32_t)(c & 1) * STAGE_SZ;
#pragma unroll
            for (int p = 0; p < 4; p++) {
                int row = lrow + 32 * p;
                size_t ga = (size_t)(m0 + row) * DMODEL + koe + lch * 8;
                size_t gb = (size_t)(n0 + row) * DMODEL + koe + lch * 8;
                uint32_t so = bufb + (uint32_t)row * SA + lch * 16;
                CP16(so + T_AH, Ahi + ga);
                CP16(so + T_AL, Alo + ga);
                CP16(so + T_BH, Bhi + gb);
                CP16(so + T_BL, Blo + gb);
            }
            CP_COMMIT();
        }
    }

    // ---- epilogue ----
#pragma unroll
    for (int mi = 0; mi < 4; mi++) {
        int r0 = m0 + 64 * wm + 16 * mi + g;
#pragma unroll
        for (int nj = 0; nj < 8; nj++) {
            int n = n0 + 64 * wn + 8 * nj + 2 * t;
            float f0 = d[mi][nj][0], f1 = d[mi][nj][1];
            float f2 = d[mi][nj][2], f3 = d[mi][nj][3];
            if (mode == 0) {
                *(float2*)(C + (size_t)r0 * DMODEL + n)       = make_float2(f0, f1);
                *(float2*)(C + (size_t)(r0 + 8) * DMODEL + n) = make_float2(f2, f3);
            } else {
                int proj = n >> 10, nn = n & 1023;
                int h = nn >> 6, dd = nn & 63;
                int b0 = r0 >> 11, s0 = r0 & 2047;
                int b1 = (r0 + 8) >> 11, s1 = (r0 + 8) & 2047;
                size_t o0 = (((size_t)(b0 * NHEAD + h)) * S_LEN + s0) * HDIM + dd;
                size_t o1 = (((size_t)(b1 * NHEAD + h)) * S_LEN + s1) * HDIM + dd;
                if (proj == 0) {           // Q, pre-scaled 1/8
                    f0 *= 0.125f; f1 *= 0.125f; f2 *= 0.125f; f3 *= 0.125f;
                    *(uint32_t*)(Qhi + o0) = packb(f0, f1);
                    *(uint32_t*)(Qlo + o0) = packb(bres(f0), bres(f1));
                    *(uint32_t*)(Qhi + o1) = packb(f2, f3);
                    *(uint32_t*)(Qlo + o1) = packb(bres(f2), bres(f3));
                } else if (proj == 1) {    // K
                    *(uint32_t*)(Khi + o0) = packb(f0, f1);
                    *(uint32_t*)(Klo + o0) = packb(bres(f0), bres(f1));
                    *(uint32_t*)(Khi + o1) = packb(f2, f3);
                    *(uint32_t*)(Klo + o1) = packb(bres(f2), bres(f3));
                } else {                   // V fp32
                    *(float2*)(Vf + o0) = make_float2(f0, f1);
                    *(float2*)(Vf + o1) = make_float2(f2, f3);
                }
            }
        }
    }
}

// ================= tensor-core causal flash-attention (unchanged, proven) =================
#define AT_STRIDE 144
#define AT_KH 0
#define AT_KL (64 * AT_STRIDE)
#define AT_VH (2 * 64 * AT_STRIDE)
#define AT_VL (3 * 64 * AT_STRIDE)
#define AT_STAGE (4 * 64 * AT_STRIDE)
#define ATT_SMEM (2 * AT_STAGE)

__global__ __launch_bounds__(256, 2)
void attn_tc_kernel(const __nv_bfloat16* __restrict__ qh_, const __nv_bfloat16* __restrict__ ql_,
                    const __nv_bfloat16* __restrict__ kh_, const __nv_bfloat16* __restrict__ kl_,
                    const __nv_bfloat16* __restrict__ vth_, const __nv_bfloat16* __restrict__ vtl_,
                    __nv_bfloat16* __restrict__ outh, __nv_bfloat16* __restrict__ outl)
{
    extern __shared__ char smem[];
    const uint32_t sb = smem_u32(smem);
    const int tid = threadIdx.x, lane = tid & 31, wid = tid >> 5;
    const int g = lane >> 2, t = lane & 3;
    const int qt = (int)gridDim.x - 1 - (int)blockIdx.x;
    const int bh = blockIdx.y;
    const int bidx = bh >> 4, hidx = bh & 15;
    const int qbase = qt * 128;
    const int ktlast = 2 * qt + 1;

    const __nv_bfloat16* qh  = qh_  + (size_t)bh * (S_LEN * HDIM);
    const __nv_bfloat16* ql  = ql_  + (size_t)bh * (S_LEN * HDIM);
    const __nv_bfloat16* kh  = kh_  + (size_t)bh * (S_LEN * HDIM);
    const __nv_bfloat16* kl  = kl_  + (size_t)bh * (S_LEN * HDIM);
    const __nv_bfloat16* vth = vth_ + (size_t)bh * (HDIM * S_LEN);
    const __nv_bfloat16* vtl = vtl_ + (size_t)bh * (HDIM * S_LEN);

    uint32_t qfh[4][4], qfl[4][4];
    {
        const int r0 = 16 * wid + g;
        const uint32_t* ph = (const uint32_t*)(qh + (size_t)(qbase + r0) * HDIM);
        const uint32_t* pl = (const uint32_t*)(ql + (size_t)(qbase + r0) * HDIM);
#pragma unroll
        for (int ks = 0; ks < 4; ks++) {
            qfh[ks][0] = ph[8*ks + t];        qfh[ks][2] = ph[8*ks + t + 4];
            qfh[ks][1] = ph[256 + 8*ks + t];  qfh[ks][3] = ph[256 + 8*ks + t + 4];
            qfl[ks][0] = pl[8*ks + t];        qfl[ks][2] = pl[8*ks + t + 4];
            qfl[ks][1] = pl[256 + 8*ks + t];  qfl[ks][3] = pl[256 + 8*ks + t + 4];
        }
    }

    float o[8][4];
#pragma unroll
    for (int j = 0; j < 8; j++)
#pragma unroll
        for (int e = 0; e < 4; e++) o[j][e] = 0.f;
    float m0 = -1e30f, m1 = -1e30f, l0 = 0.f, l1 = 0.f;

    const int lrow = tid >> 3, lch = tid & 7;
    auto stage_load = [&](int kt) {
        const uint32_t dst = sb + (uint32_t)(kt & 1) * AT_STAGE;
#pragma unroll
        for (int p = 0; p < 2; p++) {
            int r = lrow + 32 * p;
            uint32_t so = dst + (uint32_t)r * AT_STRIDE + lch * 16;
            CP16(so + AT_KH, kh  + (size_t)(kt * 64 + r) * HDIM + lch * 8);
            CP16(so + AT_KL, kl  + (size_t)(kt * 64 + r) * HDIM + lch * 8);
            CP16(so + AT_VH, vth + (size_t)r * S_LEN + kt * 64 + lch * 8);
            CP16(so + AT_VL, vtl + (size_t)r * S_LEN + kt * 64 + lch * 8);
        }
        CP_COMMIT();
    };
    stage_load(0);
    stage_load(1);

    for (int kt = 0; kt <= ktlast; kt++) {
        if (kt + 1 <= ktlast) { CP_WAIT1(); } else { CP_WAIT0(); }
        __syncthreads();

        const bool active = !(kt == ktlast && wid < 4);
        if (active) {
            const uint32_t base = sb + (uint32_t)(kt & 1) * AT_STAGE
                                + (uint32_t)g * AT_STRIDE + 4 * t;

            float s[8][4];
#pragma unroll
            for (int j = 0; j < 8; j++)
#pragma unroll
                for (int e = 0; e < 4; e++) s[j][e] = 0.f;
#pragma unroll
            for (int nj = 0; nj < 8; nj++) {
                uint32_t ro = base + (uint32_t)(8 * nj) * AT_STRIDE;
#pragma unroll
                for (int ks = 0; ks < 4; ks++) {
                    uint32_t a = ro + ks * 32;
                    uint32_t b0 = lds32(a + AT_KH), b1 = lds32(a + AT_KH + 16);
                    uint32_t c0 = lds32(a + AT_KL), c1 = lds32(a + AT_KL + 16);
                    MMA_BF16(s[nj], qfh[ks], b0, b1);
                    MMA_BF16(s[nj], qfl[ks], b0, b1);
                    MMA_BF16(s[nj], qfh[ks], c0, c1);
                }
            }

            if (kt >= 2 * qt) {
                const int kb = (kt - 2 * qt) * 64;
                const int r0 = 16 * wid + g, r1 = r0 + 8;
#pragma unroll
                for (int nj = 0; nj < 8; nj++) {
                    int k0 = kb + 8 * nj + 2 * t, k1 = k0 + 1;
                    if (k0 > r0) s[nj][0] = -1e30f;
                    if (k1 > r0) s[nj][1] = -1e30f;
                    if (k0 > r1) s[nj][2] = -1e30f;
                    if (k1 > r1) s[nj][3] = -1e30f;
                }
            }

            float mx0 = -1e30f, mx1 = -1e30f;
#pragma unroll
            for (int nj = 0; nj < 8; nj++) {
                mx0 = fmaxf(mx0, fmaxf(s[nj][0], s[nj][1]));
                mx1 = fmaxf(mx1, fmaxf(s[nj][2], s[nj][3]));
            }
            mx0 = fmaxf(mx0, __shfl_xor_sync(0xffffffffu, mx0, 1));
            mx0 = fmaxf(mx0, __shfl_xor_sync(0xffffffffu, mx0, 2));
            mx1 = fmaxf(mx1, __shfl_xor_sync(0xffffffffu, mx1, 1));
            mx1 = fmaxf(mx1, __shfl_xor_sync(0xffffffffu, mx1, 2));
            float mn0 = fmaxf(m0, mx0), mn1 = fmaxf(m1, mx1);
            float al0 = __expf(m0 - mn0), al1 = __expf(m1 - mn1);
            m0 = mn0; m1 = mn1;

            float rs0 = 0.f, rs1 = 0.f;
#pragma unroll
            for (int nj = 0; nj < 8; nj++) {
                s[nj][0] = __expf(s[nj][0] - mn0);
                s[nj][1] = __expf(s[nj][1] - mn0);
                s[nj][2] = __expf(s[nj][2] - mn1);
                s[nj][3] = __expf(s[nj][3] - mn1);
                rs0 += s[nj][0] + s[nj][1];
                rs1 += s[nj][2] + s[nj][3];
            }
            rs0 += __shfl_xor_sync(0xffffffffu, rs0, 1);
            rs0 += __shfl_xor_sync(0xffffffffu, rs0, 2);
            rs1 += __shfl_xor_sync(0xffffffffu, rs1, 1);
            rs1 += __shfl_xor_sync(0xffffffffu, rs1, 2);
            l0 = l0 * al0 + rs0;
            l1 = l1 * al1 + rs1;
#pragma unroll
            for (int nj = 0; nj < 8; nj++) {
                o[nj][0] *= al0; o[nj][1] *= al0;
                o[nj][2] *= al1; o[nj][3] *= al1;
            }

            uint32_t pah[4][4], pal[4][4];
#pragma unroll
            for (int ksn = 0; ksn < 4; ksn++) {
                int ja = 2 * ksn, jb = ja + 1;
                pah[ksn][0] = packb(s[ja][0], s[ja][1]);
                pah[ksn][1] = packb(s[ja][2], s[ja][3]);
                pah[ksn][2] = packb(s[jb][0], s[jb][1]);
                pah[ksn][3] = packb(s[jb][2], s[jb][3]);
                pal[ksn][0] = packb(bres(s[ja][0]), bres(s[ja][1]));
                pal[ksn][1] = packb(bres(s[ja][2]), bres(s[ja][3]));
                pal[ksn][2] = packb(bres(s[jb][0]), bres(s[jb][1]));
                pal[ksn][3] = packb(bres(s[jb][2]), bres(s[jb][3]));
            }

#pragma unroll
            for (int nj = 0; nj < 8; nj++) {
                uint32_t ro = base + (uint32_t)(8 * nj) * AT_STRIDE;
#pragma unroll
                for (int ksn = 0; ksn < 4; ksn++) {
                    uint32_t a = ro + ksn * 32;
                    uint32_t b0 = lds32(a + AT_VH), b1 = lds32(a + AT_VH + 16);
                    uint32_t c0 = lds32(a + AT_VL), c1 = lds32(a + AT_VL + 16);
                    MMA_BF16(o[nj], pah[ksn], b0, b1);
                    MMA_BF16(o[nj], pal[ksn], b0, b1);
                    MMA_BF16(o[nj], pah[ksn], c0, c1);
                }
            }
        }
        __syncthreads();
        if (kt + 2 <= ktlast) stage_load(kt + 2);
    }

    const float inv0 = 1.f / l0, inv1 = 1.f / l1;
    const int r0 = qbase + 16 * wid + g;
    const size_t base0 = ((size_t)bidx * S_LEN + r0) * DMODEL + hidx * 64 + 2 * t;
#pragma unroll
    for (int nj = 0; nj < 8; nj++) {
        float f0 = o[nj][0] * inv0, f1 = o[nj][1] * inv0;
        float f2 = o[nj][2] * inv1, f3 = o[nj][3] * inv1;
        size_t o0 = base0 + 8 * nj;
        size_t o1 = o0 + 8 * DMODEL;
        *(uint32_t*)(outh + o0) = packb(f0, f1);
        *(uint32_t*)(outl + o0) = packb(bres(f0), bres(f1));
        *(uint32_t*)(outh + o1) = packb(f2, f3);
        *(uint32_t*)(outl + o1) = packb(bres(f2), bres(f3));
    }
}

// ---------------- launch ----------------
extern "C" void kernel_launch(void* const* d_in, const int* in_sizes, int n_in,
                              void* d_out, int out_size)
{
    const float* x  = (const float*)d_in[0];
    const float* Wq = (const float*)d_in[1];
    const float* Wk = (const float*)d_in[2];
    const float* Wv = (const float*)d_in[3];
    const float* Wo = (const float*)d_in[4];
    float* out = (float*)d_out;

    float* v;
    __nv_bfloat16 *qhi, *qlo, *khi, *klo, *vthi, *vtlo, *ahi, *alo, *wt3hi, *wt3lo;
    cudaGetSymbolAddress((void**)&v,     g_v);
    cudaGetSymbolAddress((void**)&qhi,   g_qhi);
    cudaGetSymbolAddress((void**)&qlo,   g_qlo);
    cudaGetSymbolAddress((void**)&khi,   g_khi);
    cudaGetSymbolAddress((void**)&klo,   g_klo);
    cudaGetSymbolAddress((void**)&vthi,  g_vthi);
    cudaGetSymbolAddress((void**)&vtlo,  g_vtlo);
    cudaGetSymbolAddress((void**)&ahi,   g_ahi);
    cudaGetSymbolAddress((void**)&alo,   g_alo);
    cudaGetSymbolAddress((void**)&wt3hi, g_wt3hi);
    cudaGetSymbolAddress((void**)&wt3lo, g_wt3lo);

    cudaFuncSetAttribute(gemm_mma_kernel, cudaFuncAttributeMaxDynamicSharedMemorySize, GEMM_SMEM);
    cudaFuncSetAttribute(attn_tc_kernel, cudaFuncAttributeMaxDynamicSharedMemorySize, ATT_SMEM);

    const int n4 = NTOK * DMODEL / 4;
    dim3 wtgrid(DMODEL / 32, DMODEL / 32), wtblk(32, 8);
    const size_t WSZ = (size_t)DMODEL * DMODEL;

    // x -> bf16 hi/lo, and Wq/Wk/Wv -> concatenated W^T hi/lo
    convert_split_kernel<<<n4 / 256, 256>>>(x, ahi, alo, n4);
    convert_wt_kernel<<<wtgrid, wtblk>>>(Wq, wt3hi,           wt3lo);
    convert_wt_kernel<<<wtgrid, wtblk>>>(Wk, wt3hi + WSZ,     wt3lo + WSZ);
    convert_wt_kernel<<<wtgrid, wtblk>>>(Wv, wt3hi + 2 * WSZ, wt3lo + 2 * WSZ);

    // fused QKV projection (one launch, N = 3072)
    gemm_mma_kernel<<<dim3(3 * DMODEL / 128, NTOK / 128), 128, GEMM_SMEM>>>(
        ahi, alo, wt3hi, wt3lo, nullptr, qhi, qlo, khi, klo, v, 3);
    vt_kernel<<<dim3(S_LEN / 32, HDIM / 32, NBH), dim3(32, 8)>>>(v, vthi, vtlo);

    // fused causal attention -> att bf16 hi/lo
    attn_tc_kernel<<<dim3(S_LEN / 128, NBH), 256, ATT_SMEM>>>(
        qhi, qlo, khi, klo, vthi, vtlo, ahi, alo);

    // output projection
    convert_wt_kernel<<<wtgrid, wtblk>>>(Wo, wt3hi, wt3lo);
    gemm_mma_kernel<<<dim3(DMODEL / 128, NTOK / 128), 128, GEMM_SMEM>>>(
        ahi, alo, wt3hi, wt3lo, out, nullptr, nullptr, nullptr, nullptr, nullptr, 0);
}

// round 10
// speedup vs baseline: 4.1250x; 1.1916x over previous
#include <cuda_runtime.h>
#include <cuda_bf16.h>
#include <cuda_fp16.h>
#include <cstdint>

#define S_LEN  2048
#define NHEAD  16
#define HDIM   64
#define DMODEL 1024
#define BATCH  4
#define NTOK   (BATCH * S_LEN)   // 8192
#define NBH    (BATCH * NHEAD)   // 64

// ---------------- scratch (no allocations allowed) ----------------
__device__ float         g_v[NBH * S_LEN * HDIM];      // fp32 V [bh][s][hd]
__device__ __nv_bfloat16 g_qhi[NBH * S_LEN * HDIM];    // [bh][s][hd], pre-scaled 1/8
__device__ __nv_bfloat16 g_qlo[NBH * S_LEN * HDIM];
__device__ __nv_bfloat16 g_khi[NBH * S_LEN * HDIM];
__device__ __nv_bfloat16 g_klo[NBH * S_LEN * HDIM];
__device__ __nv_bfloat16 g_vthi[NBH * HDIM * S_LEN];   // [bh][hd][s]
__device__ __nv_bfloat16 g_vtlo[NBH * HDIM * S_LEN];
__device__ __half        g_ahi[NTOK * DMODEL];         // activation hi (x, later att), fp16
__device__ __half        g_alo[NTOK * DMODEL];         // activation lo
__device__ __half        g_wth[4 * DMODEL * DMODEL];   // W^T fp16: [Wq;Wk;Wv;Wo]

// ================= helpers =================
__device__ __forceinline__ uint32_t smem_u32(const void* p) {
    uint32_t a;
    asm("{ .reg .u64 t; cvta.to.shared.u64 t, %1; cvt.u32.u64 %0, t; }" : "=r"(a) : "l"(p));
    return a;
}
__device__ __forceinline__ uint32_t lds32(uint32_t addr) {
    uint32_t v;
    asm volatile("ld.shared.b32 %0, [%1];" : "=r"(v) : "r"(addr));
    return v;
}
#define CP16(dst, src) \
    asm volatile("cp.async.cg.shared.global [%0], [%1], 16;" :: "r"(dst), "l"(src))
#define CP_COMMIT() asm volatile("cp.async.commit_group;" ::: "memory")
#define CP_WAIT1()  asm volatile("cp.async.wait_group 1;" ::: "memory")
#define CP_WAIT0()  asm volatile("cp.async.wait_group 0;" ::: "memory")

// bf16 warp MMA: D(16x8,f32) += A(16x16) * B(16x8)
#define MMA_BF16(d, a, b0, b1) \
    asm volatile("mma.sync.aligned.m16n8k16.row.col.f32.bf16.bf16.f32 " \
        "{%0,%1,%2,%3}, {%4,%5,%6,%7}, {%8,%9}, {%0,%1,%2,%3};" \
        : "+f"((d)[0]), "+f"((d)[1]), "+f"((d)[2]), "+f"((d)[3]) \
        : "r"((a)[0]), "r"((a)[1]), "r"((a)[2]), "r"((a)[3]), "r"(b0), "r"(b1))

// fp16 warp MMA, fp32 accum
#define MMA_F16(d, a, b0, b1) \
    asm volatile("mma.sync.aligned.m16n8k16.row.col.f32.f16.f16.f32 " \
        "{%0,%1,%2,%3}, {%4,%5,%6,%7}, {%8,%9}, {%0,%1,%2,%3};" \
        : "+f"((d)[0]), "+f"((d)[1]), "+f"((d)[2]), "+f"((d)[3]) \
        : "r"((a)[0]), "r"((a)[1]), "r"((a)[2]), "r"((a)[3]), "r"(b0), "r"(b1))

// pack two f32 -> bf16x2 / f16x2; low half = memory-first element
__device__ __forceinline__ uint32_t packb(float lo, float hi) {
    uint32_t r;
    asm("cvt.rn.bf16x2.f32 %0, %1, %2;" : "=r"(r) : "f"(hi), "f"(lo));
    return r;
}
__device__ __forceinline__ uint32_t packh(float lo, float hi) {
    uint32_t r;
    asm("cvt.rn.f16x2.f32 %0, %1, %2;" : "=r"(r) : "f"(hi), "f"(lo));
    return r;
}
__device__ __forceinline__ float bres(float x) {
    return x - __bfloat162float(__float2bfloat16(x));
}
__device__ __forceinline__ float hres(float x) {
    return x - __half2float(__float2half(x));
}

// ================= conversion kernels =================
// fp32 -> fp16 hi/lo split
__global__ void convert_split_kernel(const float* __restrict__ in,
                                     __half* __restrict__ hi,
                                     __half* __restrict__ lo, int n4) {
    int i = blockIdx.x * blockDim.x + threadIdx.x;
    if (i >= n4) return;
    float4 v = ((const float4*)in)[i];
    ((uint32_t*)hi)[2*i]   = packh(v.x, v.y);
    ((uint32_t*)hi)[2*i+1] = packh(v.z, v.w);
    ((uint32_t*)lo)[2*i]   = packh(hres(v.x), hres(v.y));
    ((uint32_t*)lo)[2*i+1] = packh(hres(v.z), hres(v.w));
}

// W [K,N] row-major -> W^T fp16 [N,K]
__global__ void convert_wt_kernel(const float* __restrict__ W,
                                  __half* __restrict__ hT) {
    __shared__ float sm[32][33];
    int n0 = blockIdx.x * 32, k0 = blockIdx.y * 32;
    int tx = threadIdx.x, ty = threadIdx.y;   // 32 x 8
#pragma unroll
    for (int i = 0; i < 4; i++)
        sm[ty + 8*i][tx] = W[(size_t)(k0 + ty + 8*i) * DMODEL + n0 + tx];
    __syncthreads();
#pragma unroll
    for (int i = 0; i < 4; i++)
        hT[(size_t)(n0 + ty + 8*i) * DMODEL + k0 + tx] = __float2half(sm[tx][ty + 8*i]);
}

// V fp32 [bh][s][hd] -> VT bf16 hi/lo [bh][hd][s]
__global__ void vt_kernel(const float* __restrict__ v,
                          __nv_bfloat16* __restrict__ vth,
                          __nv_bfloat16* __restrict__ vtl) {
    __shared__ float sm[32][33];
    int s0 = blockIdx.x * 32, d0 = blockIdx.y * 32, bh = blockIdx.z;
    int tx = threadIdx.x, ty = threadIdx.y;   // 32 x 8
    const float* vb = v + (size_t)bh * S_LEN * HDIM;
#pragma unroll
    for (int i = 0; i < 4; i++)
        sm[ty + 8*i][tx] = vb[(size_t)(s0 + ty + 8*i) * HDIM + d0 + tx];
    __syncthreads();
#pragma unroll
    for (int i = 0; i < 4; i++) {
        float f = sm[tx][ty + 8*i];
        size_t o = (size_t)bh * HDIM * S_LEN + (size_t)(d0 + ty + 8*i) * S_LEN + s0 + tx;
        vth[o] = __float2bfloat16(f);
        vtl[o] = __float2bfloat16(bres(f));
    }
}

// ================= fp16 2-term split GEMM, 64x64 warp tile =================
// C = A*B; A fp16 hi/lo [M,K], B single fp16 transposed [N,K].
// CTA tile 128x128, 4 warps (2x2), K chunk 32, 2-stage cp.async.
// mode 0: fp32 C row-major. mode 3: fused QKV scatter (Q scaled, K bf16, V fp32).
#define SA       80
#define T_AH     0
#define T_AL     (128 * SA)
#define T_B      (2 * 128 * SA)
#define STAGE_SZ (3 * 128 * SA)        // 30720
#define GEMM_SMEM (2 * STAGE_SZ)       // 61440
#define NKCH     (DMODEL / 32)

__global__ __launch_bounds__(128, 2)
void gemm_mma_kernel(const __half* __restrict__ Ahi, const __half* __restrict__ Alo,
                     const __half* __restrict__ B,
                     float* __restrict__ C,
                     __nv_bfloat16* __restrict__ Qhi, __nv_bfloat16* __restrict__ Qlo,
                     __nv_bfloat16* __restrict__ Khi, __nv_bfloat16* __restrict__ Klo,
                     float* __restrict__ Vf, int mode)
{
    extern __shared__ char smem[];
    const uint32_t sb = smem_u32(smem);
    const int tid  = threadIdx.x;
    const int lane = tid & 31;
    const int wid  = tid >> 5;
    const int wm   = wid & 1;        // 2 warps along M, 64 rows each
    const int wn   = wid >> 1;       // 2 warps along N, 64 cols each
    const int m0   = blockIdx.y * 128;
    const int n0   = blockIdx.x * 128;
    const int g    = lane >> 2;
    const int t    = lane & 3;

    const int lrow = tid >> 2;       // 0..31 (+32p)
    const int lch  = tid & 3;        // 16B chunk in 64B row

    float d[4][8][4];
#pragma unroll
    for (int i = 0; i < 4; i++)
#pragma unroll
        for (int j = 0; j < 8; j++)
#pragma unroll
            for (int e = 0; e < 4; e++) d[i][j][e] = 0.f;

    // prologue: stages 0,1
#pragma unroll
    for (int c = 0; c < 2; c++) {
        const int koe = c * 32;
        const uint32_t bufb = sb + c * STAGE_SZ;
#pragma unroll
        for (int p = 0; p < 4; p++) {
            int row = lrow + 32 * p;
            size_t ga = (size_t)(m0 + row) * DMODEL + koe + lch * 8;
            size_t gb = (size_t)(n0 + row) * DMODEL + koe + lch * 8;
            uint32_t so = bufb + (uint32_t)row * SA + lch * 16;
            CP16(so + T_AH, Ahi + ga);
            CP16(so + T_AL, Alo + ga);
            CP16(so + T_B,  B   + gb);
        }
        CP_COMMIT();
    }

    for (int c = 0; c < NKCH; c++) {
        if (c + 1 < NKCH) { CP_WAIT1(); } else { CP_WAIT0(); }
        __syncthreads();
        const uint32_t base = sb + (uint32_t)(c & 1) * STAGE_SZ;

#pragma unroll
        for (int ks = 0; ks < 2; ks++) {
            const uint32_t ko = (uint32_t)ks * 32;
            uint32_t ah[4][4], al[4][4];
#pragma unroll
            for (int mi = 0; mi < 4; mi++) {
                uint32_t r0 = (uint32_t)(64 * wm + 16 * mi + g);
                uint32_t ra = base + r0 * SA + 4 * t + ko;
                ah[mi][0] = lds32(ra + T_AH);
                ah[mi][1] = lds32(ra + T_AH + 8 * SA);
                ah[mi][2] = lds32(ra + T_AH + 16);
                ah[mi][3] = lds32(ra + T_AH + 8 * SA + 16);
                al[mi][0] = lds32(ra + T_AL);
                al[mi][1] = lds32(ra + T_AL + 8 * SA);
                al[mi][2] = lds32(ra + T_AL + 16);
                al[mi][3] = lds32(ra + T_AL + 8 * SA + 16);
            }
#pragma unroll
            for (int nj = 0; nj < 8; nj++) {
                uint32_t rn = (uint32_t)(64 * wn + 8 * nj + g);
                uint32_t rb = base + rn * SA + 4 * t + ko;
                uint32_t b0 = lds32(rb + T_B);
                uint32_t b1 = lds32(rb + T_B + 16);
                // two independent sweeps -> dependent-MMA distance 4
#pragma unroll
                for (int mi = 0; mi < 4; mi++) MMA_F16(d[mi][nj], ah[mi], b0, b1);
#pragma unroll
                for (int mi = 0; mi < 4; mi++) MMA_F16(d[mi][nj], al[mi], b0, b1);
            }
        }
        __syncthreads();

        if (c + 2 < NKCH) {
            const int koe = (c + 2) * 32;
            const uint32_t bufb = sb + (uint32_t)(c & 1) * STAGE_SZ;
#pragma unroll
            for (int p = 0; p < 4; p++) {
                int row = lrow + 32 * p;
                size_t ga = (size_t)(m0 + row) * DMODEL + koe + lch * 8;
                size_t gb = (size_t)(n0 + row) * DMODEL + koe + lch * 8;
                uint32_t so = bufb + (uint32_t)row * SA + lch * 16;
                CP16(so + T_AH, Ahi + ga);
                CP16(so + T_AL, Alo + ga);
                CP16(so + T_B,  B   + gb);
            }
            CP_COMMIT();
        }
    }

    // ---- epilogue ----
#pragma unroll
    for (int mi = 0; mi < 4; mi++) {
        int r0 = m0 + 64 * wm + 16 * mi + g;
#pragma unroll
        for (int nj = 0; nj < 8; nj++) {
            int n = n0 + 64 * wn + 8 * nj + 2 * t;
            float f0 = d[mi][nj][0], f1 = d[mi][nj][1];
            float f2 = d[mi][nj][2], f3 = d[mi][nj][3];
            if (mode == 0) {
                *(float2*)(C + (size_t)r0 * DMODEL + n)       = make_float2(f0, f1);
                *(float2*)(C + (size_t)(r0 + 8) * DMODEL + n) = make_float2(f2, f3);
            } else {
                int proj = n >> 10, nn = n & 1023;
                int h = nn >> 6, dd = nn & 63;
                int b0 = r0 >> 11, s0 = r0 & 2047;
                int b1 = (r0 + 8) >> 11, s1 = (r0 + 8) & 2047;
                size_t o0 = (((size_t)(b0 * NHEAD + h)) * S_LEN + s0) * HDIM + dd;
                size_t o1 = (((size_t)(b1 * NHEAD + h)) * S_LEN + s1) * HDIM + dd;
                if (proj == 0) {           // Q, pre-scaled 1/8
                    f0 *= 0.125f; f1 *= 0.125f; f2 *= 0.125f; f3 *= 0.125f;
                    *(uint32_t*)(Qhi + o0) = packb(f0, f1);
                    *(uint32_t*)(Qlo + o0) = packb(bres(f0), bres(f1));
                    *(uint32_t*)(Qhi + o1) = packb(f2, f3);
                    *(uint32_t*)(Qlo + o1) = packb(bres(f2), bres(f3));
                } else if (proj == 1) {    // K
                    *(uint32_t*)(Khi + o0) = packb(f0, f1);
                    *(uint32_t*)(Klo + o0) = packb(bres(f0), bres(f1));
                    *(uint32_t*)(Khi + o1) = packb(f2, f3);
                    *(uint32_t*)(Klo + o1) = packb(bres(f2), bres(f3));
                } else {                   // V fp32
                    *(float2*)(Vf + o0) = make_float2(f0, f1);
                    *(float2*)(Vf + o1) = make_float2(f2, f3);
                }
            }
        }
    }
}

// ================= tensor-core causal flash-attention (bf16 internals, proven) =================
#define AT_STRIDE 144
#define AT_KH 0
#define AT_KL (64 * AT_STRIDE)
#define AT_VH (2 * 64 * AT_STRIDE)
#define AT_VL (3 * 64 * AT_STRIDE)
#define AT_STAGE (4 * 64 * AT_STRIDE)
#define ATT_SMEM (2 * AT_STAGE)

__global__ __launch_bounds__(256, 2)
void attn_tc_kernel(const __nv_bfloat16* __restrict__ qh_, const __nv_bfloat16* __restrict__ ql_,
                    const __nv_bfloat16* __restrict__ kh_, const __nv_bfloat16* __restrict__ kl_,
                    const __nv_bfloat16* __restrict__ vth_, const __nv_bfloat16* __restrict__ vtl_,
                    __half* __restrict__ outh, __half* __restrict__ outl)
{
    extern __shared__ char smem[];
    const uint32_t sb = smem_u32(smem);
    const int tid = threadIdx.x, lane = tid & 31, wid = tid >> 5;
    const int g = lane >> 2, t = lane & 3;
    const int qt = (int)gridDim.x - 1 - (int)blockIdx.x;
    const int bh = blockIdx.y;
    const int bidx = bh >> 4, hidx = bh & 15;
    const int qbase = qt * 128;
    const int ktlast = 2 * qt + 1;

    const __nv_bfloat16* qh  = qh_  + (size_t)bh * (S_LEN * HDIM);
    const __nv_bfloat16* ql  = ql_  + (size_t)bh * (S_LEN * HDIM);
    const __nv_bfloat16* kh  = kh_  + (size_t)bh * (S_LEN * HDIM);
    const __nv_bfloat16* kl  = kl_  + (size_t)bh * (S_LEN * HDIM);
    const __nv_bfloat16* vth = vth_ + (size_t)bh * (HDIM * S_LEN);
    const __nv_bfloat16* vtl = vtl_ + (size_t)bh * (HDIM * S_LEN);

    uint32_t qfh[4][4], qfl[4][4];
    {
        const int r0 = 16 * wid + g;
        const uint32_t* ph = (const uint32_t*)(qh + (size_t)(qbase + r0) * HDIM);
        const uint32_t* pl = (const uint32_t*)(ql + (size_t)(qbase + r0) * HDIM);
#pragma unroll
        for (int ks = 0; ks < 4; ks++) {
            qfh[ks][0] = ph[8*ks + t];        qfh[ks][2] = ph[8*ks + t + 4];
            qfh[ks][1] = ph[256 + 8*ks + t];  qfh[ks][3] = ph[256 + 8*ks + t + 4];
            qfl[ks][0] = pl[8*ks + t];        qfl[ks][2] = pl[8*ks + t + 4];
            qfl[ks][1] = pl[256 + 8*ks + t];  qfl[ks][3] = pl[256 + 8*ks + t + 4];
        }
    }

    float o[8][4];
#pragma unroll
    for (int j = 0; j < 8; j++)
#pragma unroll
        for (int e = 0; e < 4; e++) o[j][e] = 0.f;
    float m0 = -1e30f, m1 = -1e30f, l0 = 0.f, l1 = 0.f;

    const int lrow = tid >> 3, lch = tid & 7;
    auto stage_load = [&](int kt) {
        const uint32_t dst = sb + (uint32_t)(kt & 1) * AT_STAGE;
#pragma unroll
        for (int p = 0; p < 2; p++) {
            int r = lrow + 32 * p;
            uint32_t so = dst + (uint32_t)r * AT_STRIDE + lch * 16;
            CP16(so + AT_KH, kh  + (size_t)(kt * 64 + r) * HDIM + lch * 8);
            CP16(so + AT_KL, kl  + (size_t)(kt * 64 + r) * HDIM + lch * 8);
            CP16(so + AT_VH, vth + (size_t)r * S_LEN + kt * 64 + lch * 8);
            CP16(so + AT_VL, vtl + (size_t)r * S_LEN + kt * 64 + lch * 8);
        }
        CP_COMMIT();
    };
    stage_load(0);
    stage_load(1);

    for (int kt = 0; kt <= ktlast; kt++) {
        if (kt + 1 <= ktlast) { CP_WAIT1(); } else { CP_WAIT0(); }
        __syncthreads();

        const bool active = !(kt == ktlast && wid < 4);
        if (active) {
            const uint32_t base = sb + (uint32_t)(kt & 1) * AT_STAGE
                                + (uint32_t)g * AT_STRIDE + 4 * t;

            float s[8][4];
#pragma unroll
            for (int j = 0; j < 8; j++)
#pragma unroll
                for (int e = 0; e < 4; e++) s[j][e] = 0.f;
#pragma unroll
            for (int nj = 0; nj < 8; nj++) {
                uint32_t ro = base + (uint32_t)(8 * nj) * AT_STRIDE;
#pragma unroll
                for (int ks = 0; ks < 4; ks++) {
                    uint32_t a = ro + ks * 32;
                    uint32_t b0 = lds32(a + AT_KH), b1 = lds32(a + AT_KH + 16);
                    uint32_t c0 = lds32(a + AT_KL), c1 = lds32(a + AT_KL + 16);
                    MMA_BF16(s[nj], qfh[ks], b0, b1);
                    MMA_BF16(s[nj], qfl[ks], b0, b1);
                    MMA_BF16(s[nj], qfh[ks], c0, c1);
                }
            }

            if (kt >= 2 * qt) {
                const int kb = (kt - 2 * qt) * 64;
                const int r0 = 16 * wid + g, r1 = r0 + 8;
#pragma unroll
                for (int nj = 0; nj < 8; nj++) {
                    int k0 = kb + 8 * nj + 2 * t, k1 = k0 + 1;
                    if (k0 > r0) s[nj][0] = -1e30f;
                    if (k1 > r0) s[nj][1] = -1e30f;
                    if (k0 > r1) s[nj][2] = -1e30f;
                    if (k1 > r1) s[nj][3] = -1e30f;
                }
            }

            float mx0 = -1e30f, mx1 = -1e30f;
#pragma unroll
            for (int nj = 0; nj < 8; nj++) {
                mx0 = fmaxf(mx0, fmaxf(s[nj][0], s[nj][1]));
                mx1 = fmaxf(mx1, fmaxf(s[nj][2], s[nj][3]));
            }
            mx0 = fmaxf(mx0, __shfl_xor_sync(0xffffffffu, mx0, 1));
            mx0 = fmaxf(mx0, __shfl_xor_sync(0xffffffffu, mx0, 2));
            mx1 = fmaxf(mx1, __shfl_xor_sync(0xffffffffu, mx1, 1));
            mx1 = fmaxf(mx1, __shfl_xor_sync(0xffffffffu, mx1, 2));
            float mn0 = fmaxf(m0, mx0), mn1 = fmaxf(m1, mx1);
            float al0 = __expf(m0 - mn0), al1 = __expf(m1 - mn1);
            m0 = mn0; m1 = mn1;

            float rs0 = 0.f, rs1 = 0.f;
#pragma unroll
            for (int nj = 0; nj < 8; nj++) {
                s[nj][0] = __expf(s[nj][0] - mn0);
                s[nj][1] = __expf(s[nj][1] - mn0);
                s[nj][2] = __expf(s[nj][2] - mn1);
                s[nj][3] = __expf(s[nj][3] - mn1);
                rs0 += s[nj][0] + s[nj][1];
                rs1 += s[nj][2] + s[nj][3];
            }
            rs0 += __shfl_xor_sync(0xffffffffu, rs0, 1);
            rs0 += __shfl_xor_sync(0xffffffffu, rs0, 2);
            rs1 += __shfl_xor_sync(0xffffffffu, rs1, 1);
            rs1 += __shfl_xor_sync(0xffffffffu, rs1, 2);
            l0 = l0 * al0 + rs0;
            l1 = l1 * al1 + rs1;
#pragma unroll
            for (int nj = 0; nj < 8; nj++) {
                o[nj][0] *= al0; o[nj][1] *= al0;
                o[nj][2] *= al1; o[nj][3] *= al1;
            }

            uint32_t pah[4][4], pal[4][4];
#pragma unroll
            for (int ksn = 0; ksn < 4; ksn++) {
                int ja = 2 * ksn, jb = ja + 1;
                pah[ksn][0] = packb(s[ja][0], s[ja][1]);
                pah[ksn][1] = packb(s[ja][2], s[ja][3]);
                pah[ksn][2] = packb(s[jb][0], s[jb][1]);
                pah[ksn][3] = packb(s[jb][2], s[jb][3]);
                pal[ksn][0] = packb(bres(s[ja][0]), bres(s[ja][1]));
                pal[ksn][1] = packb(bres(s[ja][2]), bres(s[ja][3]));
                pal[ksn][2] = packb(bres(s[jb][0]), bres(s[jb][1]));
                pal[ksn][3] = packb(bres(s[jb][2]), bres(s[jb][3]));
            }

#pragma unroll
            for (int nj = 0; nj < 8; nj++) {
                uint32_t ro = base + (uint32_t)(8 * nj) * AT_STRIDE;
#pragma unroll
                for (int ksn = 0; ksn < 4; ksn++) {
                    uint32_t a = ro + ksn * 32;
                    uint32_t b0 = lds32(a + AT_VH), b1 = lds32(a + AT_VH + 16);
                    uint32_t c0 = lds32(a + AT_VL), c1 = lds32(a + AT_VL + 16);
                    MMA_BF16(o[nj], pah[ksn], b0, b1);
                    MMA_BF16(o[nj], pal[ksn], b0, b1);
                    MMA_BF16(o[nj], pah[ksn], c0, c1);
                }
            }
        }
        __syncthreads();
        if (kt + 2 <= ktlast) stage_load(kt + 2);
    }

    // ---- epilogue: normalize, emit att as fp16 hi/lo in [b*s][h*hd] ----
    const float inv0 = 1.f / l0, inv1 = 1.f / l1;
    const int r0 = qbase + 16 * wid + g;
    const size_t base0 = ((size_t)bidx * S_LEN + r0) * DMODEL + hidx * 64 + 2 * t;
#pragma unroll
    for (int nj = 0; nj < 8; nj++) {
        float f0 = o[nj][0] * inv0, f1 = o[nj][1] * inv0;
        float f2 = o[nj][2] * inv1, f3 = o[nj][3] * inv1;
        size_t o0 = base0 + 8 * nj;
        size_t o1 = o0 + 8 * DMODEL;
        *(uint32_t*)(outh + o0) = packh(f0, f1);
        *(uint32_t*)(outl + o0) = packh(hres(f0), hres(f1));
        *(uint32_t*)(outh + o1) = packh(f2, f3);
        *(uint32_t*)(outl + o1) = packh(hres(f2), hres(f3));
    }
}

// ---------------- launch ----------------
extern "C" void kernel_launch(void* const* d_in, const int* in_sizes, int n_in,
                              void* d_out, int out_size)
{
    const float* x  = (const float*)d_in[0];
    const float* Wq = (const float*)d_in[1];
    const float* Wk = (const float*)d_in[2];
    const float* Wv = (const float*)d_in[3];
    const float* Wo = (const float*)d_in[4];
    float* out = (float*)d_out;

    float* v;
    __nv_bfloat16 *qhi, *qlo, *khi, *klo, *vthi, *vtlo;
    __half *ahi, *alo, *wth;
    cudaGetSymbolAddress((void**)&v,    g_v);
    cudaGetSymbolAddress((void**)&qhi,  g_qhi);
    cudaGetSymbolAddress((void**)&qlo,  g_qlo);
    cudaGetSymbolAddress((void**)&khi,  g_khi);
    cudaGetSymbolAddress((void**)&klo,  g_klo);
    cudaGetSymbolAddress((void**)&vthi, g_vthi);
    cudaGetSymbolAddress((void**)&vtlo, g_vtlo);
    cudaGetSymbolAddress((void**)&ahi,  g_ahi);
    cudaGetSymbolAddress((void**)&alo,  g_alo);
    cudaGetSymbolAddress((void**)&wth,  g_wth);

    cudaFuncSetAttribute(gemm_mma_kernel, cudaFuncAttributeMaxDynamicSharedMemorySize, GEMM_SMEM);
    cudaFuncSetAttribute(attn_tc_kernel, cudaFuncAttributeMaxDynamicSharedMemorySize, ATT_SMEM);

    const int n4 = NTOK * DMODEL / 4;
    dim3 wtgrid(DMODEL / 32, DMODEL / 32), wtblk(32, 8);
    const size_t WSZ = (size_t)DMODEL * DMODEL;

    // x -> fp16 hi/lo; all 4 weights -> fp16 W^T upfront
    convert_split_kernel<<<n4 / 256, 256>>>(x, ahi, alo, n4);
    convert_wt_kernel<<<wtgrid, wtblk>>>(Wq, wth);
    convert_wt_kernel<<<wtgrid, wtblk>>>(Wk, wth + WSZ);
    convert_wt_kernel<<<wtgrid, wtblk>>>(Wv, wth + 2 * WSZ);
    convert_wt_kernel<<<wtgrid, wtblk>>>(Wo, wth + 3 * WSZ);

    // fused QKV projection (one launch, N = 3072)
    gemm_mma_kernel<<<dim3(3 * DMODEL / 128, NTOK / 128), 128, GEMM_SMEM>>>(
        ahi, alo, wth, nullptr, qhi, qlo, khi, klo, v, 3);
    vt_kernel<<<dim3(S_LEN / 32, HDIM / 32, NBH), dim3(32, 8)>>>(v, vthi, vtlo);

    // fused causal attention -> att fp16 hi/lo
    attn_tc_kernel<<<dim3(S_LEN / 128, NBH), 256, ATT_SMEM>>>(
        qhi, qlo, khi, klo, vthi, vtlo, ahi, alo);

    // output projection
    gemm_mma_kernel<<<dim3(DMODEL / 128, NTOK / 128), 128, GEMM_SMEM>>>(
        ahi, alo, wth + 3 * WSZ, out, nullptr, nullptr, nullptr, nullptr, nullptr, 0);
}

// round 11
// speedup vs baseline: 4.5091x; 1.0931x over previous
#include <cuda_runtime.h>
#include <cuda_bf16.h>
#include <cuda_fp16.h>
#include <cstdint>

#define S_LEN  2048
#define NHEAD  16
#define HDIM   64
#define DMODEL 1024
#define BATCH  4
#define NTOK   (BATCH * S_LEN)   // 8192
#define NBH    (BATCH * NHEAD)   // 64

// ---------------- scratch (no allocations allowed) ----------------
__device__ float         g_v[NBH * S_LEN * HDIM];      // fp32 V [bh][s][hd]
__device__ __nv_bfloat16 g_qhi[NBH * S_LEN * HDIM];    // [bh][s][hd], pre-scaled 1/8
__device__ __nv_bfloat16 g_qlo[NBH * S_LEN * HDIM];
__device__ __nv_bfloat16 g_khi[NBH * S_LEN * HDIM];
__device__ __nv_bfloat16 g_klo[NBH * S_LEN * HDIM];
__device__ __half        g_vth[NBH * HDIM * S_LEN];    // V^T fp16 single [bh][hd][s]
__device__ __half        g_ahi[NTOK * DMODEL];         // activation hi (x, later att), fp16
__device__ __half        g_alo[NTOK * DMODEL];         // activation lo
__device__ __half        g_wth[4 * DMODEL * DMODEL];   // W^T fp16: [Wq;Wk;Wv;Wo]

// ================= helpers =================
__device__ __forceinline__ uint32_t smem_u32(const void* p) {
    uint32_t a;
    asm("{ .reg .u64 t; cvta.to.shared.u64 t, %1; cvt.u32.u64 %0, t; }" : "=r"(a) : "l"(p));
    return a;
}
__device__ __forceinline__ uint32_t lds32(uint32_t addr) {
    uint32_t v;
    asm volatile("ld.shared.b32 %0, [%1];" : "=r"(v) : "r"(addr));
    return v;
}
#define CP16(dst, src) \
    asm volatile("cp.async.cg.shared.global [%0], [%1], 16;" :: "r"(dst), "l"(src))
#define CP_COMMIT() asm volatile("cp.async.commit_group;" ::: "memory")
#define CP_WAIT1()  asm volatile("cp.async.wait_group 1;" ::: "memory")
#define CP_WAIT0()  asm volatile("cp.async.wait_group 0;" ::: "memory")

// bf16 warp MMA: D(16x8,f32) += A(16x16) * B(16x8)
#define MMA_BF16(d, a, b0, b1) \
    asm volatile("mma.sync.aligned.m16n8k16.row.col.f32.bf16.bf16.f32 " \
        "{%0,%1,%2,%3}, {%4,%5,%6,%7}, {%8,%9}, {%0,%1,%2,%3};" \
        : "+f"((d)[0]), "+f"((d)[1]), "+f"((d)[2]), "+f"((d)[3]) \
        : "r"((a)[0]), "r"((a)[1]), "r"((a)[2]), "r"((a)[3]), "r"(b0), "r"(b1))

// fp16 warp MMA, fp32 accum
#define MMA_F16(d, a, b0, b1) \
    asm volatile("mma.sync.aligned.m16n8k16.row.col.f32.f16.f16.f32 " \
        "{%0,%1,%2,%3}, {%4,%5,%6,%7}, {%8,%9}, {%0,%1,%2,%3};" \
        : "+f"((d)[0]), "+f"((d)[1]), "+f"((d)[2]), "+f"((d)[3]) \
        : "r"((a)[0]), "r"((a)[1]), "r"((a)[2]), "r"((a)[3]), "r"(b0), "r"(b1))

// pack two f32 -> bf16x2 / f16x2; low half = memory-first element
__device__ __forceinline__ uint32_t packb(float lo, float hi) {
    uint32_t r;
    asm("cvt.rn.bf16x2.f32 %0, %1, %2;" : "=r"(r) : "f"(hi), "f"(lo));
    return r;
}
__device__ __forceinline__ uint32_t packh(float lo, float hi) {
    uint32_t r;
    asm("cvt.rn.f16x2.f32 %0, %1, %2;" : "=r"(r) : "f"(hi), "f"(lo));
    return r;
}
__device__ __forceinline__ float bres(float x) {
    return x - __bfloat162float(__float2bfloat16(x));
}
__device__ __forceinline__ float hres(float x) {
    return x - __half2float(__float2half(x));
}

// ================= conversion kernels =================
// fp32 -> fp16 hi/lo split
__global__ void convert_split_kernel(const float* __restrict__ in,
                                     __half* __restrict__ hi,
                                     __half* __restrict__ lo, int n4) {
    int i = blockIdx.x * blockDim.x + threadIdx.x;
    if (i >= n4) return;
    float4 v = ((const float4*)in)[i];
    ((uint32_t*)hi)[2*i]   = packh(v.x, v.y);
    ((uint32_t*)hi)[2*i+1] = packh(v.z, v.w);
    ((uint32_t*)lo)[2*i]   = packh(hres(v.x), hres(v.y));
    ((uint32_t*)lo)[2*i+1] = packh(hres(v.z), hres(v.w));
}

// all 4 weights [K,N] row-major -> W^T fp16 [N,K], z selects the weight
__global__ void convert_wt4_kernel(const float* __restrict__ W0, const float* __restrict__ W1,
                                   const float* __restrict__ W2, const float* __restrict__ W3,
                                   __half* __restrict__ dst) {
    __shared__ float sm[32][33];
    const float* W = (blockIdx.z == 0) ? W0 : (blockIdx.z == 1) ? W1
                   : (blockIdx.z == 2) ? W2 : W3;
    __half* hT = dst + (size_t)blockIdx.z * DMODEL * DMODEL;
    int n0 = blockIdx.x * 32, k0 = blockIdx.y * 32;
    int tx = threadIdx.x, ty = threadIdx.y;   // 32 x 8
#pragma unroll
    for (int i = 0; i < 4; i++)
        sm[ty + 8*i][tx] = W[(size_t)(k0 + ty + 8*i) * DMODEL + n0 + tx];
    __syncthreads();
#pragma unroll
    for (int i = 0; i < 4; i++)
        hT[(size_t)(n0 + ty + 8*i) * DMODEL + k0 + tx] = __float2half(sm[tx][ty + 8*i]);
}

// V fp32 [bh][s][hd] -> VT fp16 single [bh][hd][s]
__global__ void vt_kernel(const float* __restrict__ v, __half* __restrict__ vth) {
    __shared__ float sm[32][33];
    int s0 = blockIdx.x * 32, d0 = blockIdx.y * 32, bh = blockIdx.z;
    int tx = threadIdx.x, ty = threadIdx.y;   // 32 x 8
    const float* vb = v + (size_t)bh * S_LEN * HDIM;
#pragma unroll
    for (int i = 0; i < 4; i++)
        sm[ty + 8*i][tx] = vb[(size_t)(s0 + ty + 8*i) * HDIM + d0 + tx];
    __syncthreads();
#pragma unroll
    for (int i = 0; i < 4; i++) {
        float f = sm[tx][ty + 8*i];
        vth[(size_t)bh * HDIM * S_LEN + (size_t)(d0 + ty + 8*i) * S_LEN + s0 + tx]
            = __float2half(f);
    }
}

// ================= fp16 2-term split GEMM, 64x64 warp tile =================
// C = A*B; A fp16 hi/lo [M,K], B single fp16 transposed [N,K].
// CTA tile 128x128, 4 warps (2x2), K chunk 32, 3-stage cp.async ring,
// one __syncthreads per chunk, B fragments preloaded per chunk for ILP.
// mode 0: fp32 C row-major. mode 3: fused QKV scatter (Q scaled, K bf16, V fp32).
#define SA       80
#define T_AH     0
#define T_AL     (128 * SA)
#define T_B      (2 * 128 * SA)
#define STAGE_SZ (3 * 128 * SA)        // 30720
#define GEMM_SMEM (3 * STAGE_SZ)       // 92160
#define NKCH     (DMODEL / 32)

__global__ __launch_bounds__(128, 2)
void gemm_mma_kernel(const __half* __restrict__ Ahi, const __half* __restrict__ Alo,
                     const __half* __restrict__ B,
                     float* __restrict__ C,
                     __nv_bfloat16* __restrict__ Qhi, __nv_bfloat16* __restrict__ Qlo,
                     __nv_bfloat16* __restrict__ Khi, __nv_bfloat16* __restrict__ Klo,
                     float* __restrict__ Vf, int mode)
{
    extern __shared__ char smem[];
    const uint32_t sb = smem_u32(smem);
    const int tid  = threadIdx.x;
    const int lane = tid & 31;
    const int wid  = tid >> 5;
    const int wm   = wid & 1;        // 2 warps along M, 64 rows each
    const int wn   = wid >> 1;       // 2 warps along N, 64 cols each
    const int m0   = blockIdx.y * 128;
    const int n0   = blockIdx.x * 128;
    const int g    = lane >> 2;
    const int t    = lane & 3;

    const int lrow = tid >> 2;       // 0..31 (+32p)
    const int lch  = tid & 3;        // 16B chunk in 64B row

    float d[4][8][4];
#pragma unroll
    for (int i = 0; i < 4; i++)
#pragma unroll
        for (int j = 0; j < 8; j++)
#pragma unroll
            for (int e = 0; e < 4; e++) d[i][j][e] = 0.f;

    auto ld_stage = [&](int c) {
        const int koe = c * 32;
        const uint32_t bufb = sb + (uint32_t)(c % 3) * STAGE_SZ;
#pragma unroll
        for (int p = 0; p < 4; p++) {
            int row = lrow + 32 * p;
            size_t ga = (size_t)(m0 + row) * DMODEL + koe + lch * 8;
            size_t gb = (size_t)(n0 + row) * DMODEL + koe + lch * 8;
            uint32_t so = bufb + (uint32_t)row * SA + lch * 16;
            CP16(so + T_AH, Ahi + ga);
            CP16(so + T_AL, Alo + ga);
            CP16(so + T_B,  B   + gb);
        }
        CP_COMMIT();
    };
    ld_stage(0);
    ld_stage(1);

    for (int c = 0; c < NKCH; c++) {
        if (c + 1 < NKCH) { CP_WAIT1(); } else { CP_WAIT0(); }
        __syncthreads();
        if (c + 2 < NKCH) ld_stage(c + 2);   // overlaps with compute below

        const uint32_t base = sb + (uint32_t)(c % 3) * STAGE_SZ;

        // preload ALL B fragments for this chunk (removes JIT LDS in MMA stream)
        uint32_t bf[2][8][2];
#pragma unroll
        for (int ks = 0; ks < 2; ks++)
#pragma unroll
            for (int nj = 0; nj < 8; nj++) {
                uint32_t rn = (uint32_t)(64 * wn + 8 * nj + g);
                uint32_t rb = base + rn * SA + 4 * t + ks * 32;
                bf[ks][nj][0] = lds32(rb + T_B);
                bf[ks][nj][1] = lds32(rb + T_B + 16);
            }

#pragma unroll
        for (int ks = 0; ks < 2; ks++) {
            const uint32_t ko = (uint32_t)ks * 32;
            uint32_t ah[4][4], al[4][4];
#pragma unroll
            for (int mi = 0; mi < 4; mi++) {
                uint32_t r0 = (uint32_t)(64 * wm + 16 * mi + g);
                uint32_t ra = base + r0 * SA + 4 * t + ko;
                ah[mi][0] = lds32(ra + T_AH);
                ah[mi][1] = lds32(ra + T_AH + 8 * SA);
                ah[mi][2] = lds32(ra + T_AH + 16);
                ah[mi][3] = lds32(ra + T_AH + 8 * SA + 16);
                al[mi][0] = lds32(ra + T_AL);
                al[mi][1] = lds32(ra + T_AL + 8 * SA);
                al[mi][2] = lds32(ra + T_AL + 16);
                al[mi][3] = lds32(ra + T_AL + 8 * SA + 16);
            }
#pragma unroll
            for (int nj = 0; nj < 8; nj++) {
#pragma unroll
                for (int mi = 0; mi < 4; mi++)
                    MMA_F16(d[mi][nj], ah[mi], bf[ks][nj][0], bf[ks][nj][1]);
#pragma unroll
                for (int mi = 0; mi < 4; mi++)
                    MMA_F16(d[mi][nj], al[mi], bf[ks][nj][0], bf[ks][nj][1]);
            }
        }
    }

    // ---- epilogue ----
#pragma unroll
    for (int mi = 0; mi < 4; mi++) {
        int r0 = m0 + 64 * wm + 16 * mi + g;
#pragma unroll
        for (int nj = 0; nj < 8; nj++) {
            int n = n0 + 64 * wn + 8 * nj + 2 * t;
            float f0 = d[mi][nj][0], f1 = d[mi][nj][1];
            float f2 = d[mi][nj][2], f3 = d[mi][nj][3];
            if (mode == 0) {
                *(float2*)(C + (size_t)r0 * DMODEL + n)       = make_float2(f0, f1);
                *(float2*)(C + (size_t)(r0 + 8) * DMODEL + n) = make_float2(f2, f3);
            } else {
                int proj = n >> 10, nn = n & 1023;
                int h = nn >> 6, dd = nn & 63;
                int b0 = r0 >> 11, s0 = r0 & 2047;
                int b1 = (r0 + 8) >> 11, s1 = (r0 + 8) & 2047;
                size_t o0 = (((size_t)(b0 * NHEAD + h)) * S_LEN + s0) * HDIM + dd;
                size_t o1 = (((size_t)(b1 * NHEAD + h)) * S_LEN + s1) * HDIM + dd;
                if (proj == 0) {           // Q, pre-scaled 1/8
                    f0 *= 0.125f; f1 *= 0.125f; f2 *= 0.125f; f3 *= 0.125f;
                    *(uint32_t*)(Qhi + o0) = packb(f0, f1);
                    *(uint32_t*)(Qlo + o0) = packb(bres(f0), bres(f1));
                    *(uint32_t*)(Qhi + o1) = packb(f2, f3);
                    *(uint32_t*)(Qlo + o1) = packb(bres(f2), bres(f3));
                } else if (proj == 1) {    // K
                    *(uint32_t*)(Khi + o0) = packb(f0, f1);
                    *(uint32_t*)(Klo + o0) = packb(bres(f0), bres(f1));
                    *(uint32_t*)(Khi + o1) = packb(f2, f3);
                    *(uint32_t*)(Klo + o1) = packb(bres(f2), bres(f3));
                } else {                   // V fp32
                    *(float2*)(Vf + o0) = make_float2(f0, f1);
                    *(float2*)(Vf + o1) = make_float2(f2, f3);
                }
            }
        }
    }
}

// ================= tensor-core causal flash-attention =================
// QK^T: bf16 hi/lo 3-term (proven). P.V: P fp16 hi/lo x V fp16 single = 2 MMAs.
#define AT_STRIDE 144
#define AT_KH 0
#define AT_KL (64 * AT_STRIDE)
#define AT_V  (2 * 64 * AT_STRIDE)
#define AT_STAGE (3 * 64 * AT_STRIDE)   // 27648
#define ATT_SMEM (2 * AT_STAGE)         // 55296

__global__ __launch_bounds__(256, 2)
void attn_tc_kernel(const __nv_bfloat16* __restrict__ qh_, const __nv_bfloat16* __restrict__ ql_,
                    const __nv_bfloat16* __restrict__ kh_, const __nv_bfloat16* __restrict__ kl_,
                    const __half* __restrict__ vth_,
                    __half* __restrict__ outh, __half* __restrict__ outl)
{
    extern __shared__ char smem[];
    const uint32_t sb = smem_u32(smem);
    const int tid = threadIdx.x, lane = tid & 31, wid = tid >> 5;
    const int g = lane >> 2, t = lane & 3;
    const int qt = (int)gridDim.x - 1 - (int)blockIdx.x;
    const int bh = blockIdx.y;
    const int bidx = bh >> 4, hidx = bh & 15;
    const int qbase = qt * 128;
    const int ktlast = 2 * qt + 1;

    const __nv_bfloat16* qh  = qh_  + (size_t)bh * (S_LEN * HDIM);
    const __nv_bfloat16* ql  = ql_  + (size_t)bh * (S_LEN * HDIM);
    const __nv_bfloat16* kh  = kh_  + (size_t)bh * (S_LEN * HDIM);
    const __nv_bfloat16* kl  = kl_  + (size_t)bh * (S_LEN * HDIM);
    const __half*        vth = vth_ + (size_t)bh * (HDIM * S_LEN);

    uint32_t qfh[4][4], qfl[4][4];
    {
        const int r0 = 16 * wid + g;
        const uint32_t* ph = (const uint32_t*)(qh + (size_t)(qbase + r0) * HDIM);
        const uint32_t* pl = (const uint32_t*)(ql + (size_t)(qbase + r0) * HDIM);
#pragma unroll
        for (int ks = 0; ks < 4; ks++) {
            qfh[ks][0] = ph[8*ks + t];        qfh[ks][2] = ph[8*ks + t + 4];
            qfh[ks][1] = ph[256 + 8*ks + t];  qfh[ks][3] = ph[256 + 8*ks + t + 4];
            qfl[ks][0] = pl[8*ks + t];        qfl[ks][2] = pl[8*ks + t + 4];
            qfl[ks][1] = pl[256 + 8*ks + t];  qfl[ks][3] = pl[256 + 8*ks + t + 4];
        }
    }

    float o[8][4];
#pragma unroll
    for (int j = 0; j < 8; j++)
#pragma unroll
        for (int e = 0; e < 4; e++) o[j][e] = 0.f;
    float m0 = -1e30f, m1 = -1e30f, l0 = 0.f, l1 = 0.f;

    const int lrow = tid >> 3, lch = tid & 7;
    auto stage_load = [&](int kt) {
        const uint32_t dst = sb + (uint32_t)(kt & 1) * AT_STAGE;
#pragma unroll
        for (int p = 0; p < 2; p++) {
            int r = lrow + 32 * p;
            uint32_t so = dst + (uint32_t)r * AT_STRIDE + lch * 16;
            CP16(so + AT_KH, kh  + (size_t)(kt * 64 + r) * HDIM + lch * 8);
            CP16(so + AT_KL, kl  + (size_t)(kt * 64 + r) * HDIM + lch * 8);
            CP16(so + AT_V,  vth + (size_t)r * S_LEN + kt * 64 + lch * 8);
        }
        CP_COMMIT();
    };
    stage_load(0);
    stage_load(1);

    for (int kt = 0; kt <= ktlast; kt++) {
        if (kt + 1 <= ktlast) { CP_WAIT1(); } else { CP_WAIT0(); }
        __syncthreads();

        const bool active = !(kt == ktlast && wid < 4);
        if (active) {
            const uint32_t base = sb + (uint32_t)(kt & 1) * AT_STAGE
                                + (uint32_t)g * AT_STRIDE + 4 * t;

            float s[8][4];
#pragma unroll
            for (int j = 0; j < 8; j++)
#pragma unroll
                for (int e = 0; e < 4; e++) s[j][e] = 0.f;
#pragma unroll
            for (int nj = 0; nj < 8; nj++) {
                uint32_t ro = base + (uint32_t)(8 * nj) * AT_STRIDE;
#pragma unroll
                for (int ks = 0; ks < 4; ks++) {
                    uint32_t a = ro + ks * 32;
                    uint32_t b0 = lds32(a + AT_KH), b1 = lds32(a + AT_KH + 16);
                    uint32_t c0 = lds32(a + AT_KL), c1 = lds32(a + AT_KL + 16);
                    MMA_BF16(s[nj], qfh[ks], b0, b1);
                    MMA_BF16(s[nj], qfl[ks], b0, b1);
                    MMA_BF16(s[nj], qfh[ks], c0, c1);
                }
            }

            if (kt >= 2 * qt) {
                const int kb = (kt - 2 * qt) * 64;
                const int r0 = 16 * wid + g, r1 = r0 + 8;
#pragma unroll
                for (int nj = 0; nj < 8; nj++) {
                    int k0 = kb + 8 * nj + 2 * t, k1 = k0 + 1;
                    if (k0 > r0) s[nj][0] = -1e30f;
                    if (k1 > r0) s[nj][1] = -1e30f;
                    if (k0 > r1) s[nj][2] = -1e30f;
                    if (k1 > r1) s[nj][3] = -1e30f;
                }
            }

            float mx0 = -1e30f, mx1 = -1e30f;
#pragma unroll
            for (int nj = 0; nj < 8; nj++) {
                mx0 = fmaxf(mx0, fmaxf(s[nj][0], s[nj][1]));
                mx1 = fmaxf(mx1, fmaxf(s[nj][2], s[nj][3]));
            }
            mx0 = fmaxf(mx0, __shfl_xor_sync(0xffffffffu, mx0, 1));
            mx0 = fmaxf(mx0, __shfl_xor_sync(0xffffffffu, mx0, 2));
            mx1 = fmaxf(mx1, __shfl_xor_sync(0xffffffffu, mx1, 1));
            mx1 = fmaxf(mx1, __shfl_xor_sync(0xffffffffu, mx1, 2));
            float mn0 = fmaxf(m0, mx0), mn1 = fmaxf(m1, mx1);
            float al0 = __expf(m0 - mn0), al1 = __expf(m1 - mn1);
            m0 = mn0; m1 = mn1;

            float rs0 = 0.f, rs1 = 0.f;
#pragma unroll
            for (int nj = 0; nj < 8; nj++) {
                s[nj][0] = __expf(s[nj][0] - mn0);
                s[nj][1] = __expf(s[nj][1] - mn0);
                s[nj][2] = __expf(s[nj][2] - mn1);
                s[nj][3] = __expf(s[nj][3] - mn1);
                rs0 += s[nj][0] + s[nj][1];
                rs1 += s[nj][2] + s[nj][3];
            }
            rs0 += __shfl_xor_sync(0xffffffffu, rs0, 1);
            rs0 += __shfl_xor_sync(0xffffffffu, rs0, 2);
            rs1 += __shfl_xor_sync(0xffffffffu, rs1, 1);
            rs1 += __shfl_xor_sync(0xffffffffu, rs1, 2);
            l0 = l0 * al0 + rs0;
            l1 = l1 * al1 + rs1;
#pragma unroll
            for (int nj = 0; nj < 8; nj++) {
                o[nj][0] *= al0; o[nj][1] *= al0;
                o[nj][2] *= al1; o[nj][3] *= al1;
            }

            // P -> fp16 A-fragments (hi exact-ish, lo = residual)
            uint32_t ph[4][4], pl[4][4];
#pragma unroll
            for (int ksn = 0; ksn < 4; ksn++) {
                int ja = 2 * ksn, jb = ja + 1;
                ph[ksn][0] = packh(s[ja][0], s[ja][1]);
                ph[ksn][1] = packh(s[ja][2], s[ja][3]);
                ph[ksn][2] = packh(s[jb][0], s[jb][1]);
                ph[ksn][3] = packh(s[jb][2], s[jb][3]);
                pl[ksn][0] = packh(hres(s[ja][0]), hres(s[ja][1]));
                pl[ksn][1] = packh(hres(s[ja][2]), hres(s[ja][3]));
                pl[ksn][2] = packh(hres(s[jb][0]), hres(s[jb][1]));
                pl[ksn][3] = packh(hres(s[jb][2]), hres(s[jb][3]));
            }

            // O += P V : 2 fp16 MMAs per (nj, ksn)
#pragma unroll
            for (int nj = 0; nj < 8; nj++) {
                uint32_t ro = base + (uint32_t)(8 * nj) * AT_STRIDE;
#pragma unroll
                for (int ksn = 0; ksn < 4; ksn++) {
                    uint32_t a = ro + ksn * 32;
                    uint32_t b0 = lds32(a + AT_V), b1 = lds32(a + AT_V + 16);
                    MMA_F16(o[nj], ph[ksn], b0, b1);
                    MMA_F16(o[nj], pl[ksn], b0, b1);
                }
            }
        }
        __syncthreads();
        if (kt + 2 <= ktlast) stage_load(kt + 2);
    }

    // ---- epilogue: normalize, emit att as fp16 hi/lo in [b*s][h*hd] ----
    const float inv0 = 1.f / l0, inv1 = 1.f / l1;
    const int r0 = qbase + 16 * wid + g;
    const size_t base0 = ((size_t)bidx * S_LEN + r0) * DMODEL + hidx * 64 + 2 * t;
#pragma unroll
    for (int nj = 0; nj < 8; nj++) {
        float f0 = o[nj][0] * inv0, f1 = o[nj][1] * inv0;
        float f2 = o[nj][2] * inv1, f3 = o[nj][3] * inv1;
        size_t o0 = base0 + 8 * nj;
        size_t o1 = o0 + 8 * DMODEL;
        *(uint32_t*)(outh + o0) = packh(f0, f1);
        *(uint32_t*)(outl + o0) = packh(hres(f0), hres(f1));
        *(uint32_t*)(outh + o1) = packh(f2, f3);
        *(uint32_t*)(outl + o1) = packh(hres(f2), hres(f3));
    }
}

// ---------------- launch ----------------
extern "C" void kernel_launch(void* const* d_in, const int* in_sizes, int n_in,
                              void* d_out, int out_size)
{
    const float* x  = (const float*)d_in[0];
    const float* Wq = (const float*)d_in[1];
    const float* Wk = (const float*)d_in[2];
    const float* Wv = (const float*)d_in[3];
    const float* Wo = (const float*)d_in[4];
    float* out = (float*)d_out;

    float* v;
    __nv_bfloat16 *qhi, *qlo, *khi, *klo;
    __half *vth, *ahi, *alo, *wth;
    cudaGetSymbolAddress((void**)&v,    g_v);
    cudaGetSymbolAddress((void**)&qhi,  g_qhi);
    cudaGetSymbolAddress((void**)&qlo,  g_qlo);
    cudaGetSymbolAddress((void**)&khi,  g_khi);
    cudaGetSymbolAddress((void**)&klo,  g_klo);
    cudaGetSymbolAddress((void**)&vth,  g_vth);
    cudaGetSymbolAddress((void**)&ahi,  g_ahi);
    cudaGetSymbolAddress((void**)&alo,  g_alo);
    cudaGetSymbolAddress((void**)&wth,  g_wth);

    cudaFuncSetAttribute(gemm_mma_kernel, cudaFuncAttributeMaxDynamicSharedMemorySize, GEMM_SMEM);
    cudaFuncSetAttribute(attn_tc_kernel, cudaFuncAttributeMaxDynamicSharedMemorySize, ATT_SMEM);

    const int n4 = NTOK * DMODEL / 4;
    const size_t WSZ = (size_t)DMODEL * DMODEL;

    // x -> fp16 hi/lo; all 4 weights -> fp16 W^T in one launch
    convert_split_kernel<<<n4 / 256, 256>>>(x, ahi, alo, n4);
    convert_wt4_kernel<<<dim3(DMODEL / 32, DMODEL / 32, 4), dim3(32, 8)>>>(Wq, Wk, Wv, Wo, wth);

    // fused QKV projection (one launch, N = 3072)
    gemm_mma_kernel<<<dim3(3 * DMODEL / 128, NTOK / 128), 128, GEMM_SMEM>>>(
        ahi, alo, wth, nullptr, qhi, qlo, khi, klo, v, 3);
    vt_kernel<<<dim3(S_LEN / 32, HDIM / 32, NBH), dim3(32, 8)>>>(v, vth);

    // fused causal attention -> att fp16 hi/lo
    attn_tc_kernel<<<dim3(S_LEN / 128, NBH), 256, ATT_SMEM>>>(
        qhi, qlo, khi, klo, vth, ahi, alo);

    // output projection
    gemm_mma_kernel<<<dim3(DMODEL / 128, NTOK / 128), 128, GEMM_SMEM>>>(
        ahi, alo, wth + 3 * WSZ, out, nullptr, nullptr, nullptr, nullptr, nullptr, 0);
}

// round 12
// speedup vs baseline: 5.4327x; 1.2048x over previous
#include <cuda_runtime.h>
#include <cuda_bf16.h>
#include <cuda_fp16.h>
#include <cstdint>

#define S_LEN  2048
#define NHEAD  16
#define HDIM   64
#define DMODEL 1024
#define BATCH  4
#define NTOK   (BATCH * S_LEN)   // 8192
#define NBH    (BATCH * NHEAD)   // 64

// ---------------- scratch (no allocations allowed) ----------------
__device__ float  g_v[NBH * S_LEN * HDIM];        // fp32 V [bh][s][hd]
__device__ __half g_qhi[NBH * S_LEN * HDIM];      // Q fp16 hi [bh][s][hd], pre-scaled 1/8
__device__ __half g_qlo[NBH * S_LEN * HDIM];      // Q fp16 lo
__device__ __half g_kh [NBH * S_LEN * HDIM];      // K fp16 single
__device__ __half g_vth[NBH * HDIM * S_LEN];      // V^T fp16 single [bh][hd][s]
__device__ __half g_ahi[NTOK * DMODEL];           // activation hi (x, later att)
__device__ __half g_alo[NTOK * DMODEL];           // activation lo
__device__ __half g_wth[4 * DMODEL * DMODEL];     // W^T fp16: [Wq;Wk;Wv;Wo]

// ================= helpers =================
__device__ __forceinline__ uint32_t smem_u32(const void* p) {
    uint32_t a;
    asm("{ .reg .u64 t; cvta.to.shared.u64 t, %1; cvt.u32.u64 %0, t; }" : "=r"(a) : "l"(p));
    return a;
}
#define CP16(dst, src) \
    asm volatile("cp.async.cg.shared.global [%0], [%1], 16;" :: "r"(dst), "l"(src))
#define CP_COMMIT() asm volatile("cp.async.commit_group;" ::: "memory")
#define CP_WAIT1()  asm volatile("cp.async.wait_group 1;" ::: "memory")
#define CP_WAIT0()  asm volatile("cp.async.wait_group 0;" ::: "memory")

#define LDSM_X4(r0, r1, r2, r3, addr) \
    asm volatile("ldmatrix.sync.aligned.m8n8.x4.shared.b16 {%0,%1,%2,%3}, [%4];" \
        : "=r"(r0), "=r"(r1), "=r"(r2), "=r"(r3) : "r"(addr))
#define LDSM_X2(r0, r1, addr) \
    asm volatile("ldmatrix.sync.aligned.m8n8.x2.shared.b16 {%0,%1}, [%2];" \
        : "=r"(r0), "=r"(r1) : "r"(addr))

// fp16 warp MMA, fp32 accum: D(16x8) += A(16x16) * B(16x8)
#define MMA_F16(d, a, b0, b1) \
    asm volatile("mma.sync.aligned.m16n8k16.row.col.f32.f16.f16.f32 " \
        "{%0,%1,%2,%3}, {%4,%5,%6,%7}, {%8,%9}, {%0,%1,%2,%3};" \
        : "+f"((d)[0]), "+f"((d)[1]), "+f"((d)[2]), "+f"((d)[3]) \
        : "r"((a)[0]), "r"((a)[1]), "r"((a)[2]), "r"((a)[3]), "r"(b0), "r"(b1))

__device__ __forceinline__ uint32_t packh(float lo, float hi) {
    uint32_t r;
    asm("cvt.rn.f16x2.f32 %0, %1, %2;" : "=r"(r) : "f"(hi), "f"(lo));
    return r;
}
__device__ __forceinline__ float hres(float x) {
    return x - __half2float(__float2half(x));
}

// ================= conversion kernels =================
__global__ void convert_split_kernel(const float* __restrict__ in,
                                     __half* __restrict__ hi,
                                     __half* __restrict__ lo, int n4) {
    int i = blockIdx.x * blockDim.x + threadIdx.x;
    if (i >= n4) return;
    float4 v = ((const float4*)in)[i];
    ((uint32_t*)hi)[2*i]   = packh(v.x, v.y);
    ((uint32_t*)hi)[2*i+1] = packh(v.z, v.w);
    ((uint32_t*)lo)[2*i]   = packh(hres(v.x), hres(v.y));
    ((uint32_t*)lo)[2*i+1] = packh(hres(v.z), hres(v.w));
}

// all 4 weights [K,N] row-major -> W^T fp16 [N,K], z selects the weight
__global__ void convert_wt4_kernel(const float* __restrict__ W0, const float* __restrict__ W1,
                                   const float* __restrict__ W2, const float* __restrict__ W3,
                                   __half* __restrict__ dst) {
    __shared__ float sm[32][33];
    const float* W = (blockIdx.z == 0) ? W0 : (blockIdx.z == 1) ? W1
                   : (blockIdx.z == 2) ? W2 : W3;
    __half* hT = dst + (size_t)blockIdx.z * DMODEL * DMODEL;
    int n0 = blockIdx.x * 32, k0 = blockIdx.y * 32;
    int tx = threadIdx.x, ty = threadIdx.y;   // 32 x 8
#pragma unroll
    for (int i = 0; i < 4; i++)
        sm[ty + 8*i][tx] = W[(size_t)(k0 + ty + 8*i) * DMODEL + n0 + tx];
    __syncthreads();
#pragma unroll
    for (int i = 0; i < 4; i++)
        hT[(size_t)(n0 + ty + 8*i) * DMODEL + k0 + tx] = __float2half(sm[tx][ty + 8*i]);
}

// V fp32 [bh][s][hd] -> VT fp16 single [bh][hd][s]
__global__ void vt_kernel(const float* __restrict__ v, __half* __restrict__ vth) {
    __shared__ float sm[32][33];
    int s0 = blockIdx.x * 32, d0 = blockIdx.y * 32, bh = blockIdx.z;
    int tx = threadIdx.x, ty = threadIdx.y;   // 32 x 8
    const float* vb = v + (size_t)bh * S_LEN * HDIM;
#pragma unroll
    for (int i = 0; i < 4; i++)
        sm[ty + 8*i][tx] = vb[(size_t)(s0 + ty + 8*i) * HDIM + d0 + tx];
    __syncthreads();
#pragma unroll
    for (int i = 0; i < 4; i++) {
        float f = sm[tx][ty + 8*i];
        vth[(size_t)bh * HDIM * S_LEN + (size_t)(d0 + ty + 8*i) * S_LEN + s0 + tx]
            = __float2half(f);
    }
}

// ================= fp16 2-term split GEMM, 64x64 warp tile, ldmatrix =================
// C = A*B; A fp16 hi/lo [M,K], B single fp16 transposed [N,K].
// CTA tile 128x128, 4 warps (2x2), K chunk 32, 3-stage cp.async ring.
// mode 0: fp32 C row-major. mode 3: fused QKV scatter (Q fp16 hi/lo, K fp16, V fp32).
#define SA       80
#define T_AH     0
#define T_AL     (128 * SA)
#define T_B      (2 * 128 * SA)
#define STAGE_SZ (3 * 128 * SA)        // 30720
#define GEMM_SMEM (3 * STAGE_SZ)       // 92160
#define NKCH     (DMODEL / 32)

__global__ __launch_bounds__(128, 2)
void gemm_mma_kernel(const __half* __restrict__ Ahi, const __half* __restrict__ Alo,
                     const __half* __restrict__ B,
                     float* __restrict__ C,
                     __half* __restrict__ Qhi, __half* __restrict__ Qlo,
                     __half* __restrict__ Kh, float* __restrict__ Vf, int mode)
{
    extern __shared__ char smem[];
    const uint32_t sb = smem_u32(smem);
    const int tid  = threadIdx.x;
    const int lane = tid & 31;
    const int wid  = tid >> 5;
    const int wm   = wid & 1;        // 2 warps along M, 64 rows each
    const int wn   = wid >> 1;       // 2 warps along N, 64 cols each
    const int m0   = blockIdx.y * 128;
    const int n0   = blockIdx.x * 128;
    const int g    = lane >> 2;
    const int t    = lane & 3;

    const int lrow = tid >> 2;       // 0..31 (+32p)
    const int lch  = tid & 3;        // 16B chunk in 64B row

    // ldmatrix per-lane address offsets (verified equal to manual fragment layout)
    const uint32_t aoffA = (uint32_t)(lane & 15) * SA + ((uint32_t)(lane >> 4) << 4);
    const uint32_t aoffB = (uint32_t)(lane & 7) * SA + ((uint32_t)((lane >> 3) & 1) << 4);

    float d[4][8][4];
#pragma unroll
    for (int i = 0; i < 4; i++)
#pragma unroll
        for (int j = 0; j < 8; j++)
#pragma unroll
            for (int e = 0; e < 4; e++) d[i][j][e] = 0.f;

    auto ld_stage = [&](int c) {
        const int koe = c * 32;
        const uint32_t bufb = sb + (uint32_t)(c % 3) * STAGE_SZ;
#pragma unroll
        for (int p = 0; p < 4; p++) {
            int row = lrow + 32 * p;
            size_t ga = (size_t)(m0 + row) * DMODEL + koe + lch * 8;
            size_t gb = (size_t)(n0 + row) * DMODEL + koe + lch * 8;
            uint32_t so = bufb + (uint32_t)row * SA + lch * 16;
            CP16(so + T_AH, Ahi + ga);
            CP16(so + T_AL, Alo + ga);
            CP16(so + T_B,  B   + gb);
        }
        CP_COMMIT();
    };
    ld_stage(0);
    ld_stage(1);

    for (int c = 0; c < NKCH; c++) {
        if (c + 1 < NKCH) { CP_WAIT1(); } else { CP_WAIT0(); }
        __syncthreads();
        if (c + 2 < NKCH) ld_stage(c + 2);   // overlaps with compute below

        const uint32_t base = sb + (uint32_t)(c % 3) * STAGE_SZ;

        // preload ALL B fragments for this chunk (ldmatrix.x2 each)
        uint32_t bf[2][8][2];
#pragma unroll
        for (int ks = 0; ks < 2; ks++)
#pragma unroll
            for (int nj = 0; nj < 8; nj++) {
                uint32_t rb = base + T_B + (uint32_t)(64 * wn + 8 * nj) * SA
                            + (uint32_t)ks * 32 + aoffB;
                LDSM_X2(bf[ks][nj][0], bf[ks][nj][1], rb);
            }

#pragma unroll
        for (int ks = 0; ks < 2; ks++) {
            uint32_t ah[4][4], al[4][4];
#pragma unroll
            for (int mi = 0; mi < 4; mi++) {
                uint32_t ra = base + (uint32_t)(64 * wm + 16 * mi) * SA
                            + (uint32_t)ks * 32 + aoffA;
                LDSM_X4(ah[mi][0], ah[mi][1], ah[mi][2], ah[mi][3], ra + T_AH);
                LDSM_X4(al[mi][0], al[mi][1], al[mi][2], al[mi][3], ra + T_AL);
            }
#pragma unroll
            for (int nj = 0; nj < 8; nj++) {
#pragma unroll
                for (int mi = 0; mi < 4; mi++)
                    MMA_F16(d[mi][nj], ah[mi], bf[ks][nj][0], bf[ks][nj][1]);
#pragma unroll
                for (int mi = 0; mi < 4; mi++)
                    MMA_F16(d[mi][nj], al[mi], bf[ks][nj][0], bf[ks][nj][1]);
            }
        }
    }

    // ---- epilogue ----
#pragma unroll
    for (int mi = 0; mi < 4; mi++) {
        int r0 = m0 + 64 * wm + 16 * mi + g;
#pragma unroll
        for (int nj = 0; nj < 8; nj++) {
            int n = n0 + 64 * wn + 8 * nj + 2 * t;
            float f0 = d[mi][nj][0], f1 = d[mi][nj][1];
            float f2 = d[mi][nj][2], f3 = d[mi][nj][3];
            if (mode == 0) {
                *(float2*)(C + (size_t)r0 * DMODEL + n)       = make_float2(f0, f1);
                *(float2*)(C + (size_t)(r0 + 8) * DMODEL + n) = make_float2(f2, f3);
            } else {
                int proj = n >> 10, nn = n & 1023;
                int h = nn >> 6, dd = nn & 63;
                int b0 = r0 >> 11, s0 = r0 & 2047;
                int b1 = (r0 + 8) >> 11, s1 = (r0 + 8) & 2047;
                size_t o0 = (((size_t)(b0 * NHEAD + h)) * S_LEN + s0) * HDIM + dd;
                size_t o1 = (((size_t)(b1 * NHEAD + h)) * S_LEN + s1) * HDIM + dd;
                if (proj == 0) {           // Q fp16 hi/lo, pre-scaled 1/8
                    f0 *= 0.125f; f1 *= 0.125f; f2 *= 0.125f; f3 *= 0.125f;
                    *(uint32_t*)(Qhi + o0) = packh(f0, f1);
                    *(uint32_t*)(Qlo + o0) = packh(hres(f0), hres(f1));
                    *(uint32_t*)(Qhi + o1) = packh(f2, f3);
                    *(uint32_t*)(Qlo + o1) = packh(hres(f2), hres(f3));
                } else if (proj == 1) {    // K fp16 single
                    *(uint32_t*)(Kh + o0) = packh(f0, f1);
                    *(uint32_t*)(Kh + o1) = packh(f2, f3);
                } else {                   // V fp32
                    *(float2*)(Vf + o0) = make_float2(f0, f1);
                    *(float2*)(Vf + o1) = make_float2(f2, f3);
                }
            }
        }
    }
}

// ================= tensor-core causal flash-attention =================
// QK^T: Q fp16 hi/lo x K fp16 single = 2 MMAs. P.V: P fp16 hi/lo x V fp16 = 2 MMAs.
#define AT_STRIDE 144
#define AT_K 0
#define AT_V (64 * AT_STRIDE)
#define AT_STAGE (2 * 64 * AT_STRIDE)   // 18432
#define ATT_SMEM (2 * AT_STAGE)         // 36864

__global__ __launch_bounds__(256, 2)
void attn_tc_kernel(const __half* __restrict__ qh_, const __half* __restrict__ ql_,
                    const __half* __restrict__ kh_, const __half* __restrict__ vth_,
                    __half* __restrict__ outh, __half* __restrict__ outl)
{
    extern __shared__ char smem[];
    const uint32_t sb = smem_u32(smem);
    const int tid = threadIdx.x, lane = tid & 31, wid = tid >> 5;
    const int g = lane >> 2, t = lane & 3;
    const int qt = (int)gridDim.x - 1 - (int)blockIdx.x;   // heavy tiles first
    const int bh = blockIdx.y;
    const int bidx = bh >> 4, hidx = bh & 15;
    const int qbase = qt * 128;
    const int ktlast = 2 * qt + 1;

    const __half* qh  = qh_  + (size_t)bh * (S_LEN * HDIM);
    const __half* ql  = ql_  + (size_t)bh * (S_LEN * HDIM);
    const __half* kh  = kh_  + (size_t)bh * (S_LEN * HDIM);
    const __half* vth = vth_ + (size_t)bh * (HDIM * S_LEN);

    // ldmatrix B-operand per-lane offset
    const uint32_t aoffB = (uint32_t)(lane & 7) * AT_STRIDE
                         + ((uint32_t)((lane >> 3) & 1) << 4);

    // ---- persistent Q fragments (16 rows x 64 hd, fp16 hi/lo) ----
    uint32_t qfh[4][4], qfl[4][4];
    {
        const int r0 = 16 * wid + g;
        const uint32_t* ph = (const uint32_t*)(qh + (size_t)(qbase + r0) * HDIM);
        const uint32_t* pl = (const uint32_t*)(ql + (size_t)(qbase + r0) * HDIM);
#pragma unroll
        for (int ks = 0; ks < 4; ks++) {
            qfh[ks][0] = ph[8*ks + t];        qfh[ks][2] = ph[8*ks + t + 4];
            qfh[ks][1] = ph[256 + 8*ks + t];  qfh[ks][3] = ph[256 + 8*ks + t + 4];
            qfl[ks][0] = pl[8*ks + t];        qfl[ks][2] = pl[8*ks + t + 4];
            qfl[ks][1] = pl[256 + 8*ks + t];  qfl[ks][3] = pl[256 + 8*ks + t + 4];
        }
    }

    float o[8][4];
#pragma unroll
    for (int j = 0; j < 8; j++)
#pragma unroll
        for (int e = 0; e < 4; e++) o[j][e] = 0.f;
    float m0 = -1e30f, m1 = -1e30f, l0 = 0.f, l1 = 0.f;

    const int lrow = tid >> 3, lch = tid & 7;
    auto stage_load = [&](int kt) {
        const uint32_t dst = sb + (uint32_t)(kt & 1) * AT_STAGE;
#pragma unroll
        for (int p = 0; p < 2; p++) {
            int r = lrow + 32 * p;
            uint32_t so = dst + (uint32_t)r * AT_STRIDE + lch * 16;
            CP16(so + AT_K, kh  + (size_t)(kt * 64 + r) * HDIM + lch * 8);
            CP16(so + AT_V, vth + (size_t)r * S_LEN + kt * 64 + lch * 8);
        }
        CP_COMMIT();
    };
    stage_load(0);
    stage_load(1);

    for (int kt = 0; kt <= ktlast; kt++) {
        if (kt + 1 <= ktlast) { CP_WAIT1(); } else { CP_WAIT0(); }
        __syncthreads();

        // last (diagonal-upper) tile: lower warp half fully masked -> skip
        const bool active = !(kt == ktlast && wid < 4);
        if (active) {
            const uint32_t tb = sb + (uint32_t)(kt & 1) * AT_STAGE;

            // ---- S = Q K^T : 2 fp16 MMAs per (nj, ks) ----
            float s[8][4];
#pragma unroll
            for (int j = 0; j < 8; j++)
#pragma unroll
                for (int e = 0; e < 4; e++) s[j][e] = 0.f;
#pragma unroll
            for (int nj = 0; nj < 8; nj++) {
                uint32_t ro = tb + AT_K + (uint32_t)(8 * nj) * AT_STRIDE + aoffB;
#pragma unroll
                for (int ks = 0; ks < 4; ks++) {
                    uint32_t b0, b1;
                    LDSM_X2(b0, b1, ro + (uint32_t)ks * 32);
                    MMA_F16(s[nj], qfh[ks], b0, b1);
                    MMA_F16(s[nj], qfl[ks], b0, b1);
                }
            }

            // ---- causal mask (only top 2 k-tiles intersect diagonal) ----
            if (kt >= 2 * qt) {
                const int kb = (kt - 2 * qt) * 64;
                const int r0 = 16 * wid + g, r1 = r0 + 8;
#pragma unroll
                for (int nj = 0; nj < 8; nj++) {
                    int k0 = kb + 8 * nj + 2 * t, k1 = k0 + 1;
                    if (k0 > r0) s[nj][0] = -1e30f;
                    if (k1 > r0) s[nj][1] = -1e30f;
                    if (k0 > r1) s[nj][2] = -1e30f;
                    if (k1 > r1) s[nj][3] = -1e30f;
                }
            }

            // ---- online softmax ----
            float mx0 = -1e30f, mx1 = -1e30f;
#pragma unroll
            for (int nj = 0; nj < 8; nj++) {
                mx0 = fmaxf(mx0, fmaxf(s[nj][0], s[nj][1]));
                mx1 = fmaxf(mx1, fmaxf(s[nj][2], s[nj][3]));
            }
            mx0 = fmaxf(mx0, __shfl_xor_sync(0xffffffffu, mx0, 1));
            mx0 = fmaxf(mx0, __shfl_xor_sync(0xffffffffu, mx0, 2));
            mx1 = fmaxf(mx1, __shfl_xor_sync(0xffffffffu, mx1, 1));
            mx1 = fmaxf(mx1, __shfl_xor_sync(0xffffffffu, mx1, 2));
            float mn0 = fmaxf(m0, mx0), mn1 = fmaxf(m1, mx1);
            float al0 = __expf(m0 - mn0), al1 = __expf(m1 - mn1);
            m0 = mn0; m1 = mn1;

            float rs0 = 0.f, rs1 = 0.f;
#pragma unroll
            for (int nj = 0; nj < 8; nj++) {
                s[nj][0] = __expf(s[nj][0] - mn0);
                s[nj][1] = __expf(s[nj][1] - mn0);
                s[nj][2] = __expf(s[nj][2] - mn1);
                s[nj][3] = __expf(s[nj][3] - mn1);
                rs0 += s[nj][0] + s[nj][1];
                rs1 += s[nj][2] + s[nj][3];
            }
            rs0 += __shfl_xor_sync(0xffffffffu, rs0, 1);
            rs0 += __shfl_xor_sync(0xffffffffu, rs0, 2);
            rs1 += __shfl_xor_sync(0xffffffffu, rs1, 1);
            rs1 += __shfl_xor_sync(0xffffffffu, rs1, 2);
            l0 = l0 * al0 + rs0;
            l1 = l1 * al1 + rs1;
#pragma unroll
            for (int nj = 0; nj < 8; nj++) {
                o[nj][0] *= al0; o[nj][1] *= al0;
                o[nj][2] *= al1; o[nj][3] *= al1;
            }

            // ---- P -> fp16 A-fragments (hi + residual lo), regs only ----
            uint32_t pfh[4][4], pfl[4][4];
#pragma unroll
            for (int ksn = 0; ksn < 4; ksn++) {
                int ja = 2 * ksn, jb = ja + 1;
                pfh[ksn][0] = packh(s[ja][0], s[ja][1]);
                pfh[ksn][1] = packh(s[ja][2], s[ja][3]);
                pfh[ksn][2] = packh(s[jb][0], s[jb][1]);
                pfh[ksn][3] = packh(s[jb][2], s[jb][3]);
                pfl[ksn][0] = packh(hres(s[ja][0]), hres(s[ja][1]));
                pfl[ksn][1] = packh(hres(s[ja][2]), hres(s[ja][3]));
                pfl[ksn][2] = packh(hres(s[jb][0]), hres(s[jb][1]));
                pfl[ksn][3] = packh(hres(s[jb][2]), hres(s[jb][3]));
            }

            // ---- O += P V : 2 fp16 MMAs per (nj, ksn) ----
#pragma unroll
            for (int nj = 0; nj < 8; nj++) {
                uint32_t ro = tb + AT_V + (uint32_t)(8 * nj) * AT_STRIDE + aoffB;
#pragma unroll
                for (int ksn = 0; ksn < 4; ksn++) {
                    uint32_t b0, b1;
                    LDSM_X2(b0, b1, ro + (uint32_t)ksn * 32);
                    MMA_F16(o[nj], pfh[ksn], b0, b1);
                    MMA_F16(o[nj], pfl[ksn], b0, b1);
                }
            }
        }
        __syncthreads();
        if (kt + 2 <= ktlast) stage_load(kt + 2);
    }

    // ---- epilogue: normalize, emit att as fp16 hi/lo in [b*s][h*hd] ----
    const float inv0 = 1.f / l0, inv1 = 1.f / l1;
    const int r0 = qbase + 16 * wid + g;
    const size_t base0 = ((size_t)bidx * S_LEN + r0) * DMODEL + hidx * 64 + 2 * t;
#pragma unroll
    for (int nj = 0; nj < 8; nj++) {
        float f0 = o[nj][0] * inv0, f1 = o[nj][1] * inv0;
        float f2 = o[nj][2] * inv1, f3 = o[nj][3] * inv1;
        size_t o0 = base0 + 8 * nj;
        size_t o1 = o0 + 8 * DMODEL;
        *(uint32_t*)(outh + o0) = packh(f0, f1);
        *(uint32_t*)(outl + o0) = packh(hres(f0), hres(f1));
        *(uint32_t*)(outh + o1) = packh(f2, f3);
        *(uint32_t*)(outl + o1) = packh(hres(f2), hres(f3));
    }
}

// ---------------- launch ----------------
extern "C" void kernel_launch(void* const* d_in, const int* in_sizes, int n_in,
                              void* d_out, int out_size)
{
    const float* x  = (const float*)d_in[0];
    const float* Wq = (const float*)d_in[1];
    const float* Wk = (const float*)d_in[2];
    const float* Wv = (const float*)d_in[3];
    const float* Wo = (const float*)d_in[4];
    float* out = (float*)d_out;

    float* v;
    __half *qhi, *qlo, *kh, *vth, *ahi, *alo, *wth;
    cudaGetSymbolAddress((void**)&v,    g_v);
    cudaGetSymbolAddress((void**)&qhi,  g_qhi);
    cudaGetSymbolAddress((void**)&qlo,  g_qlo);
    cudaGetSymbolAddress((void**)&kh,   g_kh);
    cudaGetSymbolAddress((void**)&vth,  g_vth);
    cudaGetSymbolAddress((void**)&ahi,  g_ahi);
    cudaGetSymbolAddress((void**)&alo,  g_alo);
    cudaGetSymbolAddress((void**)&wth,  g_wth);

    cudaFuncSetAttribute(gemm_mma_kernel, cudaFuncAttributeMaxDynamicSharedMemorySize, GEMM_SMEM);
    cudaFuncSetAttribute(attn_tc_kernel, cudaFuncAttributeMaxDynamicSharedMemorySize, ATT_SMEM);

    const int n4 = NTOK * DMODEL / 4;
    const size_t WSZ = (size_t)DMODEL * DMODEL;

    // x -> fp16 hi/lo; all 4 weights -> fp16 W^T in one launch
    convert_split_kernel<<<n4 / 256, 256>>>(x, ahi, alo, n4);
    convert_wt4_kernel<<<dim3(DMODEL / 32, DMODEL / 32, 4), dim3(32, 8)>>>(Wq, Wk, Wv, Wo, wth);

    // fused QKV projection (one launch, N = 3072)
    gemm_mma_kernel<<<dim3(3 * DMODEL / 128, NTOK / 128), 128, GEMM_SMEM>>>(
        ahi, alo, wth, nullptr, qhi, qlo, kh, v, 3);
    vt_kernel<<<dim3(S_LEN / 32, HDIM / 32, NBH), dim3(32, 8)>>>(v, vth);

    // fused causal attention -> att fp16 hi/lo
    attn_tc_kernel<<<dim3(S_LEN / 128, NBH), 256, ATT_SMEM>>>(
        qhi, qlo, kh, vth, ahi, alo);

    // output projection
    gemm_mma_kernel<<<dim3(DMODEL / 128, NTOK / 128), 128, GEMM_SMEM>>>(
        ahi, alo, wth + 3 * WSZ, out, nullptr, nullptr, nullptr, nullptr, 0);
}

// round 13
// speedup vs baseline: 7.3531x; 1.3535x over previous
#include <cuda_runtime.h>
#include <cuda_bf16.h>
#include <cuda_fp16.h>
#include <cstdint>

#define S_LEN  2048
#define NHEAD  16
#define HDIM   64
#define DMODEL 1024
#define BATCH  4
#define NTOK   (BATCH * S_LEN)   // 8192
#define NBH    (BATCH * NHEAD)   // 64

// ---------------- scratch (no allocations allowed) ----------------
__device__ float  g_v[NBH * S_LEN * HDIM];        // fp32 V [bh][s][hd]
__device__ __half g_qhi[NBH * S_LEN * HDIM];      // Q fp16 hi [bh][s][hd], pre-scaled 1/8
__device__ __half g_qlo[NBH * S_LEN * HDIM];      // Q fp16 lo
__device__ __half g_kh [NBH * S_LEN * HDIM];      // K fp16 single
__device__ __half g_vth[NBH * HDIM * S_LEN];      // V^T fp16 single [bh][hd][s]
__device__ __half g_ah [NTOK * DMODEL];           // activation fp16 single (x, later att)
__device__ __half g_wth[4 * DMODEL * DMODEL];     // W^T fp16: [Wq;Wk;Wv;Wo]

// ================= helpers =================
__device__ __forceinline__ uint32_t smem_u32(const void* p) {
    uint32_t a;
    asm("{ .reg .u64 t; cvta.to.shared.u64 t, %1; cvt.u32.u64 %0, t; }" : "=r"(a) : "l"(p));
    return a;
}
#define CP16(dst, src) \
    asm volatile("cp.async.cg.shared.global [%0], [%1], 16;" :: "r"(dst), "l"(src))
#define CP_COMMIT() asm volatile("cp.async.commit_group;" ::: "memory")
#define CP_WAIT1()  asm volatile("cp.async.wait_group 1;" ::: "memory")
#define CP_WAIT0()  asm volatile("cp.async.wait_group 0;" ::: "memory")

#define LDSM_X4(r0, r1, r2, r3, addr) \
    asm volatile("ldmatrix.sync.aligned.m8n8.x4.shared.b16 {%0,%1,%2,%3}, [%4];" \
        : "=r"(r0), "=r"(r1), "=r"(r2), "=r"(r3) : "r"(addr))
#define LDSM_X2(r0, r1, addr) \
    asm volatile("ldmatrix.sync.aligned.m8n8.x2.shared.b16 {%0,%1}, [%2];" \
        : "=r"(r0), "=r"(r1) : "r"(addr))

// fp16 warp MMA, fp32 accum: D(16x8) += A(16x16) * B(16x8)
#define MMA_F16(d, a, b0, b1) \
    asm volatile("mma.sync.aligned.m16n8k16.row.col.f32.f16.f16.f32 " \
        "{%0,%1,%2,%3}, {%4,%5,%6,%7}, {%8,%9}, {%0,%1,%2,%3};" \
        : "+f"((d)[0]), "+f"((d)[1]), "+f"((d)[2]), "+f"((d)[3]) \
        : "r"((a)[0]), "r"((a)[1]), "r"((a)[2]), "r"((a)[3]), "r"(b0), "r"(b1))

__device__ __forceinline__ uint32_t packh(float lo, float hi) {
    uint32_t r;
    asm("cvt.rn.f16x2.f32 %0, %1, %2;" : "=r"(r) : "f"(hi), "f"(lo));
    return r;
}
__device__ __forceinline__ float hres(float x) {
    return x - __half2float(__float2half(x));
}

// ================= conversion kernels =================
// fp32 -> fp16 single (pure cast)
__global__ void convert_h_kernel(const float* __restrict__ in,
                                 __half* __restrict__ out, int n4) {
    int i = blockIdx.x * blockDim.x + threadIdx.x;
    if (i >= n4) return;
    float4 v = ((const float4*)in)[i];
    ((uint32_t*)out)[2*i]   = packh(v.x, v.y);
    ((uint32_t*)out)[2*i+1] = packh(v.z, v.w);
}

// all 4 weights [K,N] row-major -> W^T fp16 [N,K], z selects the weight
__global__ void convert_wt4_kernel(const float* __restrict__ W0, const float* __restrict__ W1,
                                   const float* __restrict__ W2, const float* __restrict__ W3,
                                   __half* __restrict__ dst) {
    __shared__ float sm[32][33];
    const float* W = (blockIdx.z == 0) ? W0 : (blockIdx.z == 1) ? W1
                   : (blockIdx.z == 2) ? W2 : W3;
    __half* hT = dst + (size_t)blockIdx.z * DMODEL * DMODEL;
    int n0 = blockIdx.x * 32, k0 = blockIdx.y * 32;
    int tx = threadIdx.x, ty = threadIdx.y;   // 32 x 8
#pragma unroll
    for (int i = 0; i < 4; i++)
        sm[ty + 8*i][tx] = W[(size_t)(k0 + ty + 8*i) * DMODEL + n0 + tx];
    __syncthreads();
#pragma unroll
    for (int i = 0; i < 4; i++)
        hT[(size_t)(n0 + ty + 8*i) * DMODEL + k0 + tx] = __float2half(sm[tx][ty + 8*i]);
}

// V fp32 [bh][s][hd] -> VT fp16 single [bh][hd][s]
__global__ void vt_kernel(const float* __restrict__ v, __half* __restrict__ vth) {
    __shared__ float sm[32][33];
    int s0 = blockIdx.x * 32, d0 = blockIdx.y * 32, bh = blockIdx.z;
    int tx = threadIdx.x, ty = threadIdx.y;   // 32 x 8
    const float* vb = v + (size_t)bh * S_LEN * HDIM;
#pragma unroll
    for (int i = 0; i < 4; i++)
        sm[ty + 8*i][tx] = vb[(size_t)(s0 + ty + 8*i) * HDIM + d0 + tx];
    __syncthreads();
#pragma unroll
    for (int i = 0; i < 4; i++) {
        float f = sm[tx][ty + 8*i];
        vth[(size_t)bh * HDIM * S_LEN + (size_t)(d0 + ty + 8*i) * S_LEN + s0 + tx]
            = __float2half(f);
    }
}

// ================= fp16 single GEMM, 64x64 warp tile, ldmatrix =================
// C = A*B; A fp16 single [M,K], B fp16 single transposed [N,K]. 1 MMA per tile op.
// CTA tile 128x128, 4 warps (2x2), K chunk 32, 3-stage cp.async ring.
// mode 0: fp32 C row-major. mode 3: fused QKV scatter (Q fp16 hi/lo, K fp16, V fp32).
#define SA       80
#define T_A      0
#define T_B      (128 * SA)
#define STAGE_SZ (2 * 128 * SA)        // 20480
#define GEMM_SMEM (3 * STAGE_SZ)       // 61440
#define NKCH     (DMODEL / 32)

__global__ __launch_bounds__(128, 2)
void gemm_mma_kernel(const __half* __restrict__ A, const __half* __restrict__ B,
                     float* __restrict__ C,
                     __half* __restrict__ Qhi, __half* __restrict__ Qlo,
                     __half* __restrict__ Kh, float* __restrict__ Vf, int mode)
{
    extern __shared__ char smem[];
    const uint32_t sb = smem_u32(smem);
    const int tid  = threadIdx.x;
    const int lane = tid & 31;
    const int wid  = tid >> 5;
    const int wm   = wid & 1;        // 2 warps along M, 64 rows each
    const int wn   = wid >> 1;       // 2 warps along N, 64 cols each
    const int m0   = blockIdx.y * 128;
    const int n0   = blockIdx.x * 128;
    const int g    = lane >> 2;
    const int t    = lane & 3;

    const int lrow = tid >> 2;       // 0..31 (+32p)
    const int lch  = tid & 3;        // 16B chunk in 64B row

    const uint32_t aoffA = (uint32_t)(lane & 15) * SA + ((uint32_t)(lane >> 4) << 4);
    const uint32_t aoffB = (uint32_t)(lane & 7) * SA + ((uint32_t)((lane >> 3) & 1) << 4);

    float d[4][8][4];
#pragma unroll
    for (int i = 0; i < 4; i++)
#pragma unroll
        for (int j = 0; j < 8; j++)
#pragma unroll
            for (int e = 0; e < 4; e++) d[i][j][e] = 0.f;

    auto ld_stage = [&](int c) {
        const int koe = c * 32;
        const uint32_t bufb = sb + (uint32_t)(c % 3) * STAGE_SZ;
#pragma unroll
        for (int p = 0; p < 4; p++) {
            int row = lrow + 32 * p;
            size_t ga = (size_t)(m0 + row) * DMODEL + koe + lch * 8;
            size_t gb = (size_t)(n0 + row) * DMODEL + koe + lch * 8;
            uint32_t so = bufb + (uint32_t)row * SA + lch * 16;
            CP16(so + T_A, A + ga);
            CP16(so + T_B, B + gb);
        }
        CP_COMMIT();
    };
    ld_stage(0);
    ld_stage(1);

    for (int c = 0; c < NKCH; c++) {
        if (c + 1 < NKCH) { CP_WAIT1(); } else { CP_WAIT0(); }
        __syncthreads();
        if (c + 2 < NKCH) ld_stage(c + 2);   // overlaps with compute below

        const uint32_t base = sb + (uint32_t)(c % 3) * STAGE_SZ;

        // preload ALL B fragments for this chunk
        uint32_t bf[2][8][2];
#pragma unroll
        for (int ks = 0; ks < 2; ks++)
#pragma unroll
            for (int nj = 0; nj < 8; nj++) {
                uint32_t rb = base + T_B + (uint32_t)(64 * wn + 8 * nj) * SA
                            + (uint32_t)ks * 32 + aoffB;
                LDSM_X2(bf[ks][nj][0], bf[ks][nj][1], rb);
            }

#pragma unroll
        for (int ks = 0; ks < 2; ks++) {
            uint32_t a[4][4];
#pragma unroll
            for (int mi = 0; mi < 4; mi++) {
                uint32_t ra = base + T_A + (uint32_t)(64 * wm + 16 * mi) * SA
                            + (uint32_t)ks * 32 + aoffA;
                LDSM_X4(a[mi][0], a[mi][1], a[mi][2], a[mi][3], ra);
            }
#pragma unroll
            for (int nj = 0; nj < 8; nj++)
#pragma unroll
                for (int mi = 0; mi < 4; mi++)
                    MMA_F16(d[mi][nj], a[mi], bf[ks][nj][0], bf[ks][nj][1]);
        }
    }

    // ---- epilogue ----
#pragma unroll
    for (int mi = 0; mi < 4; mi++) {
        int r0 = m0 + 64 * wm + 16 * mi + g;
#pragma unroll
        for (int nj = 0; nj < 8; nj++) {
            int n = n0 + 64 * wn + 8 * nj + 2 * t;
            float f0 = d[mi][nj][0], f1 = d[mi][nj][1];
            float f2 = d[mi][nj][2], f3 = d[mi][nj][3];
            if (mode == 0) {
                *(float2*)(C + (size_t)r0 * DMODEL + n)       = make_float2(f0, f1);
                *(float2*)(C + (size_t)(r0 + 8) * DMODEL + n) = make_float2(f2, f3);
            } else {
                int proj = n >> 10, nn = n & 1023;
                int h = nn >> 6, dd = nn & 63;
                int b0 = r0 >> 11, s0 = r0 & 2047;
                int b1 = (r0 + 8) >> 11, s1 = (r0 + 8) & 2047;
                size_t o0 = (((size_t)(b0 * NHEAD + h)) * S_LEN + s0) * HDIM + dd;
                size_t o1 = (((size_t)(b1 * NHEAD + h)) * S_LEN + s1) * HDIM + dd;
                if (proj == 0) {           // Q fp16 hi/lo, pre-scaled 1/8
                    f0 *= 0.125f; f1 *= 0.125f; f2 *= 0.125f; f3 *= 0.125f;
                    *(uint32_t*)(Qhi + o0) = packh(f0, f1);
                    *(uint32_t*)(Qlo + o0) = packh(hres(f0), hres(f1));
                    *(uint32_t*)(Qhi + o1) = packh(f2, f3);
                    *(uint32_t*)(Qlo + o1) = packh(hres(f2), hres(f3));
                } else if (proj == 1) {    // K fp16 single
                    *(uint32_t*)(Kh + o0) = packh(f0, f1);
                    *(uint32_t*)(Kh + o1) = packh(f2, f3);
                } else {                   // V fp32
                    *(float2*)(Vf + o0) = make_float2(f0, f1);
                    *(float2*)(Vf + o1) = make_float2(f2, f3);
                }
            }
        }
    }
}

// ================= tensor-core causal flash-attention =================
// QK^T: Q fp16 hi/lo x K fp16 single = 2 MMAs. P.V: P fp16 hi/lo x V fp16 = 2 MMAs.
#define AT_STRIDE 144
#define AT_K 0
#define AT_V (64 * AT_STRIDE)
#define AT_STAGE (2 * 64 * AT_STRIDE)   // 18432
#define ATT_SMEM (2 * AT_STAGE)         // 36864

__global__ __launch_bounds__(256, 2)
void attn_tc_kernel(const __half* __restrict__ qh_, const __half* __restrict__ ql_,
                    const __half* __restrict__ kh_, const __half* __restrict__ vth_,
                    __half* __restrict__ outh)
{
    extern __shared__ char smem[];
    const uint32_t sb = smem_u32(smem);
    const int tid = threadIdx.x, lane = tid & 31, wid = tid >> 5;
    const int g = lane >> 2, t = lane & 3;
    const int qt = (int)gridDim.x - 1 - (int)blockIdx.x;   // heavy tiles first
    const int bh = blockIdx.y;
    const int bidx = bh >> 4, hidx = bh & 15;
    const int qbase = qt * 128;
    const int ktlast = 2 * qt + 1;

    const __half* qh  = qh_  + (size_t)bh * (S_LEN * HDIM);
    const __half* ql  = ql_  + (size_t)bh * (S_LEN * HDIM);
    const __half* kh  = kh_  + (size_t)bh * (S_LEN * HDIM);
    const __half* vth = vth_ + (size_t)bh * (HDIM * S_LEN);

    const uint32_t aoffB = (uint32_t)(lane & 7) * AT_STRIDE
                         + ((uint32_t)((lane >> 3) & 1) << 4);

    // ---- persistent Q fragments (16 rows x 64 hd, fp16 hi/lo) ----
    uint32_t qfh[4][4], qfl[4][4];
    {
        const int r0 = 16 * wid + g;
        const uint32_t* ph = (const uint32_t*)(qh + (size_t)(qbase + r0) * HDIM);
        const uint32_t* pl = (const uint32_t*)(ql + (size_t)(qbase + r0) * HDIM);
#pragma unroll
        for (int ks = 0; ks < 4; ks++) {
            qfh[ks][0] = ph[8*ks + t];        qfh[ks][2] = ph[8*ks + t + 4];
            qfh[ks][1] = ph[256 + 8*ks + t];  qfh[ks][3] = ph[256 + 8*ks + t + 4];
            qfl[ks][0] = pl[8*ks + t];        qfl[ks][2] = pl[8*ks + t + 4];
            qfl[ks][1] = pl[256 + 8*ks + t];  qfl[ks][3] = pl[256 + 8*ks + t + 4];
        }
    }

    float o[8][4];
#pragma unroll
    for (int j = 0; j < 8; j++)
#pragma unroll
        for (int e = 0; e < 4; e++) o[j][e] = 0.f;
    float m0 = -1e30f, m1 = -1e30f, l0 = 0.f, l1 = 0.f;

    const int lrow = tid >> 3, lch = tid & 7;
    auto stage_load = [&](int kt) {
        const uint32_t dst = sb + (uint32_t)(kt & 1) * AT_STAGE;
#pragma unroll
        for (int p = 0; p < 2; p++) {
            int r = lrow + 32 * p;
            uint32_t so = dst + (uint32_t)r * AT_STRIDE + lch * 16;
            CP16(so + AT_K, kh  + (size_t)(kt * 64 + r) * HDIM + lch * 8);
            CP16(so + AT_V, vth + (size_t)r * S_LEN + kt * 64 + lch * 8);
        }
        CP_COMMIT();
    };
    stage_load(0);
    stage_load(1);

    for (int kt = 0; kt <= ktlast; kt++) {
        if (kt + 1 <= ktlast) { CP_WAIT1(); } else { CP_WAIT0(); }
        __syncthreads();

        const bool active = !(kt == ktlast && wid < 4);
        if (active) {
            const uint32_t tb = sb + (uint32_t)(kt & 1) * AT_STAGE;

            float s[8][4];
#pragma unroll
            for (int j = 0; j < 8; j++)
#pragma unroll
                for (int e = 0; e < 4; e++) s[j][e] = 0.f;
#pragma unroll
            for (int nj = 0; nj < 8; nj++) {
                uint32_t ro = tb + AT_K + (uint32_t)(8 * nj) * AT_STRIDE + aoffB;
#pragma unroll
                for (int ks = 0; ks < 4; ks++) {
                    uint32_t b0, b1;
                    LDSM_X2(b0, b1, ro + (uint32_t)ks * 32);
                    MMA_F16(s[nj], qfh[ks], b0, b1);
                    MMA_F16(s[nj], qfl[ks], b0, b1);
                }
            }

            if (kt >= 2 * qt) {
                const int kb = (kt - 2 * qt) * 64;
                const int r0 = 16 * wid + g, r1 = r0 + 8;
#pragma unroll
                for (int nj = 0; nj < 8; nj++) {
                    int k0 = kb + 8 * nj + 2 * t, k1 = k0 + 1;
                    if (k0 > r0) s[nj][0] = -1e30f;
                    if (k1 > r0) s[nj][1] = -1e30f;
                    if (k0 > r1) s[nj][2] = -1e30f;
                    if (k1 > r1) s[nj][3] = -1e30f;
                }
            }

            float mx0 = -1e30f, mx1 = -1e30f;
#pragma unroll
            for (int nj = 0; nj < 8; nj++) {
                mx0 = fmaxf(mx0, fmaxf(s[nj][0], s[nj][1]));
                mx1 = fmaxf(mx1, fmaxf(s[nj][2], s[nj][3]));
            }
            mx0 = fmaxf(mx0, __shfl_xor_sync(0xffffffffu, mx0, 1));
            mx0 = fmaxf(mx0, __shfl_xor_sync(0xffffffffu, mx0, 2));
            mx1 = fmaxf(mx1, __shfl_xor_sync(0xffffffffu, mx1, 1));
            mx1 = fmaxf(mx1, __shfl_xor_sync(0xffffffffu, mx1, 2));
            float mn0 = fmaxf(m0, mx0), mn1 = fmaxf(m1, mx1);
            float al0 = __expf(m0 - mn0), al1 = __expf(m1 - mn1);
            m0 = mn0; m1 = mn1;

            float rs0 = 0.f, rs1 = 0.f;
#pragma unroll
            for (int nj = 0; nj < 8; nj++) {
                s[nj][0] = __expf(s[nj][0] - mn0);
                s[nj][1] = __expf(s[nj][1] - mn0);
                s[nj][2] = __expf(s[nj][2] - mn1);
                s[nj][3] = __expf(s[nj][3] - mn1);
                rs0 += s[nj][0] + s[nj][1];
                rs1 += s[nj][2] + s[nj][3];
            }
            rs0 += __shfl_xor_sync(0xffffffffu, rs0, 1);
            rs0 += __shfl_xor_sync(0xffffffffu, rs0, 2);
            rs1 += __shfl_xor_sync(0xffffffffu, rs1, 1);
            rs1 += __shfl_xor_sync(0xffffffffu, rs1, 2);
            l0 = l0 * al0 + rs0;
            l1 = l1 * al1 + rs1;
#pragma unroll
            for (int nj = 0; nj < 8; nj++) {
                o[nj][0] *= al0; o[nj][1] *= al0;
                o[nj][2] *= al1; o[nj][3] *= al1;
            }

            uint32_t pfh[4][4], pfl[4][4];
#pragma unroll
            for (int ksn = 0; ksn < 4; ksn++) {
                int ja = 2 * ksn, jb = ja + 1;
                pfh[ksn][0] = packh(s[ja][0], s[ja][1]);
                pfh[ksn][1] = packh(s[ja][2], s[ja][3]);
                pfh[ksn][2] = packh(s[jb][0], s[jb][1]);
                pfh[ksn][3] = packh(s[jb][2], s[jb][3]);
                pfl[ksn][0] = packh(hres(s[ja][0]), hres(s[ja][1]));
                pfl[ksn][1] = packh(hres(s[ja][2]), hres(s[ja][3]));
                pfl[ksn][2] = packh(hres(s[jb][0]), hres(s[jb][1]));
                pfl[ksn][3] = packh(hres(s[jb][2]), hres(s[jb][3]));
            }

#pragma unroll
            for (int nj = 0; nj < 8; nj++) {
                uint32_t ro = tb + AT_V + (uint32_t)(8 * nj) * AT_STRIDE + aoffB;
#pragma unroll
                for (int ksn = 0; ksn < 4; ksn++) {
                    uint32_t b0, b1;
                    LDSM_X2(b0, b1, ro + (uint32_t)ksn * 32);
                    MMA_F16(o[nj], pfh[ksn], b0, b1);
                    MMA_F16(o[nj], pfl[ksn], b0, b1);
                }
            }
        }
        __syncthreads();
        if (kt + 2 <= ktlast) stage_load(kt + 2);
    }

    // ---- epilogue: normalize, emit att as fp16 single in [b*s][h*hd] ----
    const float inv0 = 1.f / l0, inv1 = 1.f / l1;
    const int r0 = qbase + 16 * wid + g;
    const size_t base0 = ((size_t)bidx * S_LEN + r0) * DMODEL + hidx * 64 + 2 * t;
#pragma unroll
    for (int nj = 0; nj < 8; nj++) {
        float f0 = o[nj][0] * inv0, f1 = o[nj][1] * inv0;
        float f2 = o[nj][2] * inv1, f3 = o[nj][3] * inv1;
        size_t o0 = base0 + 8 * nj;
        size_t o1 = o0 + 8 * DMODEL;
        *(uint32_t*)(outh + o0) = packh(f0, f1);
        *(uint32_t*)(outh + o1) = packh(f2, f3);
    }
}

// ---------------- launch ----------------
extern "C" void kernel_launch(void* const* d_in, const int* in_sizes, int n_in,
                              void* d_out, int out_size)
{
    const float* x  = (const float*)d_in[0];
    const float* Wq = (const float*)d_in[1];
    const float* Wk = (const float*)d_in[2];
    const float* Wv = (const float*)d_in[3];
    const float* Wo = (const float*)d_in[4];
    float* out = (float*)d_out;

    float* v;
    __half *qhi, *qlo, *kh, *vth, *ah, *wth;
    cudaGetSymbolAddress((void**)&v,   g_v);
    cudaGetSymbolAddress((void**)&qhi, g_qhi);
    cudaGetSymbolAddress((void**)&qlo, g_qlo);
    cudaGetSymbolAddress((void**)&kh,  g_kh);
    cudaGetSymbolAddress((void**)&vth, g_vth);
    cudaGetSymbolAddress((void**)&ah,  g_ah);
    cudaGetSymbolAddress((void**)&wth, g_wth);

    cudaFuncSetAttribute(gemm_mma_kernel, cudaFuncAttributeMaxDynamicSharedMemorySize, GEMM_SMEM);
    cudaFuncSetAttribute(attn_tc_kernel, cudaFuncAttributeMaxDynamicSharedMemorySize, ATT_SMEM);

    const int n4 = NTOK * DMODEL / 4;
    const size_t WSZ = (size_t)DMODEL * DMODEL;

    // x -> fp16 single; all 4 weights -> fp16 W^T in one launch
    convert_h_kernel<<<n4 / 256, 256>>>(x, ah, n4);
    convert_wt4_kernel<<<dim3(DMODEL / 32, DMODEL / 32, 4), dim3(32, 8)>>>(Wq, Wk, Wv, Wo, wth);

    // fused QKV projection (one launch, N = 3072)
    gemm_mma_kernel<<<dim3(3 * DMODEL / 128, NTOK / 128), 128, GEMM_SMEM>>>(
        ah, wth, nullptr, qhi, qlo, kh, v, 3);
    vt_kernel<<<dim3(S_LEN / 32, HDIM / 32, NBH), dim3(32, 8)>>>(v, vth);

    // fused causal attention -> att fp16 single
    attn_tc_kernel<<<dim3(S_LEN / 128, NBH), 256, ATT_SMEM>>>(
        qhi, qlo, kh, vth, ah);

    // output projection
    gemm_mma_kernel<<<dim3(DMODEL / 128, NTOK / 128), 128, GEMM_SMEM>>>(
        ah, wth + 3 * WSZ, out, nullptr, nullptr, nullptr, nullptr, 0);
}

// round 14
// speedup vs baseline: 9.2338x; 1.2558x over previous
#include <cuda_runtime.h>
#include <cuda_bf16.h>
#include <cuda_fp16.h>
#include <cstdint>

#define S_LEN  2048
#define NHEAD  16
#define HDIM   64
#define DMODEL 1024
#define BATCH  4
#define NTOK   (BATCH * S_LEN)   // 8192
#define NBH    (BATCH * NHEAD)   // 64

// ---------------- scratch (no allocations allowed) ----------------
__device__ float  g_v[NBH * S_LEN * HDIM];        // fp32 V [bh][s][hd]
__device__ __half g_qh [NBH * S_LEN * HDIM];      // Q fp16 single [bh][s][hd], pre-scaled 1/8
__device__ __half g_kh [NBH * S_LEN * HDIM];      // K fp16 single
__device__ __half g_vth[NBH * HDIM * S_LEN];      // V^T fp16 single [bh][hd][s]
__device__ __half g_ah [NTOK * DMODEL];           // activation fp16 single (x, later att)
__device__ __half g_wth[4 * DMODEL * DMODEL];     // W^T fp16: [Wq;Wk;Wv;Wo]

// ================= helpers =================
__device__ __forceinline__ uint32_t smem_u32(const void* p) {
    uint32_t a;
    asm("{ .reg .u64 t; cvta.to.shared.u64 t, %1; cvt.u32.u64 %0, t; }" : "=r"(a) : "l"(p));
    return a;
}
#define CP16(dst, src) \
    asm volatile("cp.async.cg.shared.global [%0], [%1], 16;" :: "r"(dst), "l"(src))
#define CP_COMMIT() asm volatile("cp.async.commit_group;" ::: "memory")
#define CP_WAIT1()  asm volatile("cp.async.wait_group 1;" ::: "memory")
#define CP_WAIT0()  asm volatile("cp.async.wait_group 0;" ::: "memory")

#define LDSM_X4(r0, r1, r2, r3, addr) \
    asm volatile("ldmatrix.sync.aligned.m8n8.x4.shared.b16 {%0,%1,%2,%3}, [%4];" \
        : "=r"(r0), "=r"(r1), "=r"(r2), "=r"(r3) : "r"(addr))
#define LDSM_X2(r0, r1, addr) \
    asm volatile("ldmatrix.sync.aligned.m8n8.x2.shared.b16 {%0,%1}, [%2];" \
        : "=r"(r0), "=r"(r1) : "r"(addr))

// fp16 warp MMA, fp32 accum: D(16x8) += A(16x16) * B(16x8)
#define MMA_F16(d, a, b0, b1) \
    asm volatile("mma.sync.aligned.m16n8k16.row.col.f32.f16.f16.f32 " \
        "{%0,%1,%2,%3}, {%4,%5,%6,%7}, {%8,%9}, {%0,%1,%2,%3};" \
        : "+f"((d)[0]), "+f"((d)[1]), "+f"((d)[2]), "+f"((d)[3]) \
        : "r"((a)[0]), "r"((a)[1]), "r"((a)[2]), "r"((a)[3]), "r"(b0), "r"(b1))

__device__ __forceinline__ uint32_t packh(float lo, float hi) {
    uint32_t r;
    asm("cvt.rn.f16x2.f32 %0, %1, %2;" : "=r"(r) : "f"(hi), "f"(lo));
    return r;
}

// ================= conversion kernels =================
// fp32 -> fp16 single (pure cast)
__global__ void convert_h_kernel(const float* __restrict__ in,
                                 __half* __restrict__ out, int n4) {
    int i = blockIdx.x * blockDim.x + threadIdx.x;
    if (i >= n4) return;
    float4 v = ((const float4*)in)[i];
    ((uint32_t*)out)[2*i]   = packh(v.x, v.y);
    ((uint32_t*)out)[2*i+1] = packh(v.z, v.w);
}

// all 4 weights [K,N] row-major -> W^T fp16 [N,K], z selects the weight
__global__ void convert_wt4_kernel(const float* __restrict__ W0, const float* __restrict__ W1,
                                   const float* __restrict__ W2, const float* __restrict__ W3,
                                   __half* __restrict__ dst) {
    __shared__ float sm[32][33];
    const float* W = (blockIdx.z == 0) ? W0 : (blockIdx.z == 1) ? W1
                   : (blockIdx.z == 2) ? W2 : W3;
    __half* hT = dst + (size_t)blockIdx.z * DMODEL * DMODEL;
    int n0 = blockIdx.x * 32, k0 = blockIdx.y * 32;
    int tx = threadIdx.x, ty = threadIdx.y;   // 32 x 8
#pragma unroll
    for (int i = 0; i < 4; i++)
        sm[ty + 8*i][tx] = W[(size_t)(k0 + ty + 8*i) * DMODEL + n0 + tx];
    __syncthreads();
#pragma unroll
    for (int i = 0; i < 4; i++)
        hT[(size_t)(n0 + ty + 8*i) * DMODEL + k0 + tx] = __float2half(sm[tx][ty + 8*i]);
}

// V fp32 [bh][s][hd] -> VT fp16 single [bh][hd][s]
__global__ void vt_kernel(const float* __restrict__ v, __half* __restrict__ vth) {
    __shared__ float sm[32][33];
    int s0 = blockIdx.x * 32, d0 = blockIdx.y * 32, bh = blockIdx.z;
    int tx = threadIdx.x, ty = threadIdx.y;   // 32 x 8
    const float* vb = v + (size_t)bh * S_LEN * HDIM;
#pragma unroll
    for (int i = 0; i < 4; i++)
        sm[ty + 8*i][tx] = vb[(size_t)(s0 + ty + 8*i) * HDIM + d0 + tx];
    __syncthreads();
#pragma unroll
    for (int i = 0; i < 4; i++) {
        float f = sm[tx][ty + 8*i];
        vth[(size_t)bh * HDIM * S_LEN + (size_t)(d0 + ty + 8*i) * S_LEN + s0 + tx]
            = __float2half(f);
    }
}

// ================= fp16 single GEMM, 64x64 warp tile, ldmatrix =================
// C = A*B; A fp16 single [M,K], B fp16 single transposed [N,K]. 1 MMA per tile op.
// CTA tile 128x128, 4 warps (2x2), K chunk 32, 3-stage cp.async ring.
// mode 0: fp32 C row-major. mode 3: fused QKV scatter (Q fp16, K fp16, V fp32).
#define SA       80
#define T_A      0
#define T_B      (128 * SA)
#define STAGE_SZ (2 * 128 * SA)        // 20480
#define GEMM_SMEM (3 * STAGE_SZ)       // 61440
#define NKCH     (DMODEL / 32)

__global__ __launch_bounds__(128, 2)
void gemm_mma_kernel(const __half* __restrict__ A, const __half* __restrict__ B,
                     float* __restrict__ C,
                     __half* __restrict__ Qh, __half* __restrict__ Kh,
                     float* __restrict__ Vf, int mode)
{
    extern __shared__ char smem[];
    const uint32_t sb = smem_u32(smem);
    const int tid  = threadIdx.x;
    const int lane = tid & 31;
    const int wid  = tid >> 5;
    const int wm   = wid & 1;        // 2 warps along M, 64 rows each
    const int wn   = wid >> 1;       // 2 warps along N, 64 cols each
    const int m0   = blockIdx.y * 128;
    const int n0   = blockIdx.x * 128;
    const int g    = lane >> 2;
    const int t    = lane & 3;

    const int lrow = tid >> 2;       // 0..31 (+32p)
    const int lch  = tid & 3;        // 16B chunk in 64B row

    const uint32_t aoffA = (uint32_t)(lane & 15) * SA + ((uint32_t)(lane >> 4) << 4);
    const uint32_t aoffB = (uint32_t)(lane & 7) * SA + ((uint32_t)((lane >> 3) & 1) << 4);

    float d[4][8][4];
#pragma unroll
    for (int i = 0; i < 4; i++)
#pragma unroll
        for (int j = 0; j < 8; j++)
#pragma unroll
            for (int e = 0; e < 4; e++) d[i][j][e] = 0.f;

    auto ld_stage = [&](int c) {
        const int koe = c * 32;
        const uint32_t bufb = sb + (uint32_t)(c % 3) * STAGE_SZ;
#pragma unroll
        for (int p = 0; p < 4; p++) {
            int row = lrow + 32 * p;
            size_t ga = (size_t)(m0 + row) * DMODEL + koe + lch * 8;
            size_t gb = (size_t)(n0 + row) * DMODEL + koe + lch * 8;
            uint32_t so = bufb + (uint32_t)row * SA + lch * 16;
            CP16(so + T_A, A + ga);
            CP16(so + T_B, B + gb);
        }
        CP_COMMIT();
    };
    ld_stage(0);
    ld_stage(1);

    for (int c = 0; c < NKCH; c++) {
        if (c + 1 < NKCH) { CP_WAIT1(); } else { CP_WAIT0(); }
        __syncthreads();
        if (c + 2 < NKCH) ld_stage(c + 2);   // overlaps with compute below

        const uint32_t base = sb + (uint32_t)(c % 3) * STAGE_SZ;

        // preload ALL B fragments for this chunk
        uint32_t bf[2][8][2];
#pragma unroll
        for (int ks = 0; ks < 2; ks++)
#pragma unroll
            for (int nj = 0; nj < 8; nj++) {
                uint32_t rb = base + T_B + (uint32_t)(64 * wn + 8 * nj) * SA
                            + (uint32_t)ks * 32 + aoffB;
                LDSM_X2(bf[ks][nj][0], bf[ks][nj][1], rb);
            }

#pragma unroll
        for (int ks = 0; ks < 2; ks++) {
            uint32_t a[4][4];
#pragma unroll
            for (int mi = 0; mi < 4; mi++) {
                uint32_t ra = base + T_A + (uint32_t)(64 * wm + 16 * mi) * SA
                            + (uint32_t)ks * 32 + aoffA;
                LDSM_X4(a[mi][0], a[mi][1], a[mi][2], a[mi][3], ra);
            }
#pragma unroll
            for (int nj = 0; nj < 8; nj++)
#pragma unroll
                for (int mi = 0; mi < 4; mi++)
                    MMA_F16(d[mi][nj], a[mi], bf[ks][nj][0], bf[ks][nj][1]);
        }
    }

    // ---- epilogue ----
#pragma unroll
    for (int mi = 0; mi < 4; mi++) {
        int r0 = m0 + 64 * wm + 16 * mi + g;
#pragma unroll
        for (int nj = 0; nj < 8; nj++) {
            int n = n0 + 64 * wn + 8 * nj + 2 * t;
            float f0 = d[mi][nj][0], f1 = d[mi][nj][1];
            float f2 = d[mi][nj][2], f3 = d[mi][nj][3];
            if (mode == 0) {
                *(float2*)(C + (size_t)r0 * DMODEL + n)       = make_float2(f0, f1);
                *(float2*)(C + (size_t)(r0 + 8) * DMODEL + n) = make_float2(f2, f3);
            } else {
                int proj = n >> 10, nn = n & 1023;
                int h = nn >> 6, dd = nn & 63;
                int b0 = r0 >> 11, s0 = r0 & 2047;
                int b1 = (r0 + 8) >> 11, s1 = (r0 + 8) & 2047;
                size_t o0 = (((size_t)(b0 * NHEAD + h)) * S_LEN + s0) * HDIM + dd;
                size_t o1 = (((size_t)(b1 * NHEAD + h)) * S_LEN + s1) * HDIM + dd;
                if (proj == 0) {           // Q fp16 single, pre-scaled 1/8
                    *(uint32_t*)(Qh + o0) = packh(f0 * 0.125f, f1 * 0.125f);
                    *(uint32_t*)(Qh + o1) = packh(f2 * 0.125f, f3 * 0.125f);
                } else if (proj == 1) {    // K fp16 single
                    *(uint32_t*)(Kh + o0) = packh(f0, f1);
                    *(uint32_t*)(Kh + o1) = packh(f2, f3);
                } else {                   // V fp32
                    *(float2*)(Vf + o0) = make_float2(f0, f1);
                    *(float2*)(Vf + o1) = make_float2(f2, f3);
                }
            }
        }
    }
}

// ================= tensor-core causal flash-attention =================
// QK^T: Q fp16 single x K fp16 single = 1 MMA. P.V: P fp16 single x V fp16 = 1 MMA.
#define AT_STRIDE 144
#define AT_K 0
#define AT_V (64 * AT_STRIDE)
#define AT_STAGE (2 * 64 * AT_STRIDE)   // 18432
#define ATT_SMEM (2 * AT_STAGE)         // 36864

__global__ __launch_bounds__(256, 2)
void attn_tc_kernel(const __half* __restrict__ qh_, const __half* __restrict__ kh_,
                    const __half* __restrict__ vth_, __half* __restrict__ outh)
{
    extern __shared__ char smem[];
    const uint32_t sb = smem_u32(smem);
    const int tid = threadIdx.x, lane = tid & 31, wid = tid >> 5;
    const int g = lane >> 2, t = lane & 3;
    const int qt = (int)gridDim.x - 1 - (int)blockIdx.x;   // heavy tiles first
    const int bh = blockIdx.y;
    const int bidx = bh >> 4, hidx = bh & 15;
    const int qbase = qt * 128;
    const int ktlast = 2 * qt + 1;

    const __half* qh  = qh_  + (size_t)bh * (S_LEN * HDIM);
    const __half* kh  = kh_  + (size_t)bh * (S_LEN * HDIM);
    const __half* vth = vth_ + (size_t)bh * (HDIM * S_LEN);

    const uint32_t aoffB = (uint32_t)(lane & 7) * AT_STRIDE
                         + ((uint32_t)((lane >> 3) & 1) << 4);

    // ---- persistent Q fragments (16 rows x 64 hd, fp16 single) ----
    uint32_t qf[4][4];
    {
        const int r0 = 16 * wid + g;
        const uint32_t* ph = (const uint32_t*)(qh + (size_t)(qbase + r0) * HDIM);
#pragma unroll
        for (int ks = 0; ks < 4; ks++) {
            qf[ks][0] = ph[8*ks + t];        qf[ks][2] = ph[8*ks + t + 4];
            qf[ks][1] = ph[256 + 8*ks + t];  qf[ks][3] = ph[256 + 8*ks + t + 4];
        }
    }

    float o[8][4];
#pragma unroll
    for (int j = 0; j < 8; j++)
#pragma unroll
        for (int e = 0; e < 4; e++) o[j][e] = 0.f;
    float m0 = -1e30f, m1 = -1e30f, l0 = 0.f, l1 = 0.f;

    const int lrow = tid >> 3, lch = tid & 7;
    auto stage_load = [&](int kt) {
        const uint32_t dst = sb + (uint32_t)(kt & 1) * AT_STAGE;
#pragma unroll
        for (int p = 0; p < 2; p++) {
            int r = lrow + 32 * p;
            uint32_t so = dst + (uint32_t)r * AT_STRIDE + lch * 16;
            CP16(so + AT_K, kh  + (size_t)(kt * 64 + r) * HDIM + lch * 8);
            CP16(so + AT_V, vth + (size_t)r * S_LEN + kt * 64 + lch * 8);
        }
        CP_COMMIT();
    };
    stage_load(0);
    stage_load(1);

    for (int kt = 0; kt <= ktlast; kt++) {
        if (kt + 1 <= ktlast) { CP_WAIT1(); } else { CP_WAIT0(); }
        __syncthreads();

        // last (diagonal-upper) tile: lower warp half fully masked -> skip
        const bool active = !(kt == ktlast && wid < 4);
        if (active) {
            const uint32_t tb = sb + (uint32_t)(kt & 1) * AT_STAGE;

            // ---- S = Q K^T : 1 fp16 MMA per (nj, ks) ----
            float s[8][4];
#pragma unroll
            for (int j = 0; j < 8; j++)
#pragma unroll
                for (int e = 0; e < 4; e++) s[j][e] = 0.f;
#pragma unroll
            for (int nj = 0; nj < 8; nj++) {
                uint32_t ro = tb + AT_K + (uint32_t)(8 * nj) * AT_STRIDE + aoffB;
#pragma unroll
                for (int ks = 0; ks < 4; ks++) {
                    uint32_t b0, b1;
                    LDSM_X2(b0, b1, ro + (uint32_t)ks * 32);
                    MMA_F16(s[nj], qf[ks], b0, b1);
                }
            }

            // ---- causal mask (only top 2 k-tiles intersect diagonal) ----
            if (kt >= 2 * qt) {
                const int kb = (kt - 2 * qt) * 64;
                const int r0 = 16 * wid + g, r1 = r0 + 8;
#pragma unroll
                for (int nj = 0; nj < 8; nj++) {
                    int k0 = kb + 8 * nj + 2 * t, k1 = k0 + 1;
                    if (k0 > r0) s[nj][0] = -1e30f;
                    if (k1 > r0) s[nj][1] = -1e30f;
                    if (k0 > r1) s[nj][2] = -1e30f;
                    if (k1 > r1) s[nj][3] = -1e30f;
                }
            }

            // ---- online softmax ----
            float mx0 = -1e30f, mx1 = -1e30f;
#pragma unroll
            for (int nj = 0; nj < 8; nj++) {
                mx0 = fmaxf(mx0, fmaxf(s[nj][0], s[nj][1]));
                mx1 = fmaxf(mx1, fmaxf(s[nj][2], s[nj][3]));
            }
            mx0 = fmaxf(mx0, __shfl_xor_sync(0xffffffffu, mx0, 1));
            mx0 = fmaxf(mx0, __shfl_xor_sync(0xffffffffu, mx0, 2));
            mx1 = fmaxf(mx1, __shfl_xor_sync(0xffffffffu, mx1, 1));
            mx1 = fmaxf(mx1, __shfl_xor_sync(0xffffffffu, mx1, 2));
            float mn0 = fmaxf(m0, mx0), mn1 = fmaxf(m1, mx1);
            float al0 = __expf(m0 - mn0), al1 = __expf(m1 - mn1);
            m0 = mn0; m1 = mn1;

            float rs0 = 0.f, rs1 = 0.f;
#pragma unroll
            for (int nj = 0; nj < 8; nj++) {
                s[nj][0] = __expf(s[nj][0] - mn0);
                s[nj][1] = __expf(s[nj][1] - mn0);
                s[nj][2] = __expf(s[nj][2] - mn1);
                s[nj][3] = __expf(s[nj][3] - mn1);
                rs0 += s[nj][0] + s[nj][1];
                rs1 += s[nj][2] + s[nj][3];
            }
            rs0 += __shfl_xor_sync(0xffffffffu, rs0, 1);
            rs0 += __shfl_xor_sync(0xffffffffu, rs0, 2);
            rs1 += __shfl_xor_sync(0xffffffffu, rs1, 1);
            rs1 += __shfl_xor_sync(0xffffffffu, rs1, 2);
            l0 = l0 * al0 + rs0;
            l1 = l1 * al1 + rs1;
#pragma unroll
            for (int nj = 0; nj < 8; nj++) {
                o[nj][0] *= al0; o[nj][1] *= al0;
                o[nj][2] *= al1; o[nj][3] *= al1;
            }

            // ---- P -> fp16 A-fragments (single), regs only ----
            uint32_t pf[4][4];
#pragma unroll
            for (int ksn = 0; ksn < 4; ksn++) {
                int ja = 2 * ksn, jb = ja + 1;
                pf[ksn][0] = packh(s[ja][0], s[ja][1]);
                pf[ksn][1] = packh(s[ja][2], s[ja][3]);
                pf[ksn][2] = packh(s[jb][0], s[jb][1]);
                pf[ksn][3] = packh(s[jb][2], s[jb][3]);
            }

            // ---- O += P V : 1 fp16 MMA per (nj, ksn) ----
#pragma unroll
            for (int nj = 0; nj < 8; nj++) {
                uint32_t ro = tb + AT_V + (uint32_t)(8 * nj) * AT_STRIDE + aoffB;
#pragma unroll
                for (int ksn = 0; ksn < 4; ksn++) {
                    uint32_t b0, b1;
                    LDSM_X2(b0, b1, ro + (uint32_t)ksn * 32);
                    MMA_F16(o[nj], pf[ksn], b0, b1);
                }
            }
        }
        __syncthreads();
        if (kt + 2 <= ktlast) stage_load(kt + 2);
    }

    // ---- epilogue: normalize, emit att as fp16 single in [b*s][h*hd] ----
    const float inv0 = 1.f / l0, inv1 = 1.f / l1;
    const int r0 = qbase + 16 * wid + g;
    const size_t base0 = ((size_t)bidx * S_LEN + r0) * DMODEL + hidx * 64 + 2 * t;
#pragma unroll
    for (int nj = 0; nj < 8; nj++) {
        float f0 = o[nj][0] * inv0, f1 = o[nj][1] * inv0;
        float f2 = o[nj][2] * inv1, f3 = o[nj][3] * inv1;
        size_t o0 = base0 + 8 * nj;
        size_t o1 = o0 + 8 * DMODEL;
        *(uint32_t*)(outh + o0) = packh(f0, f1);
        *(uint32_t*)(outh + o1) = packh(f2, f3);
    }
}

// ---------------- launch ----------------
extern "C" void kernel_launch(void* const* d_in, const int* in_sizes, int n_in,
                              void* d_out, int out_size)
{
    const float* x  = (const float*)d_in[0];
    const float* Wq = (const float*)d_in[1];
    const float* Wk = (const float*)d_in[2];
    const float* Wv = (const float*)d_in[3];
    const float* Wo = (const float*)d_in[4];
    float* out = (float*)d_out;

    float* v;
    __half *qh, *kh, *vth, *ah, *wth;
    cudaGetSymbolAddress((void**)&v,   g_v);
    cudaGetSymbolAddress((void**)&qh,  g_qh);
    cudaGetSymbolAddress((void**)&kh,  g_kh);
    cudaGetSymbolAddress((void**)&vth, g_vth);
    cudaGetSymbolAddress((void**)&ah,  g_ah);
    cudaGetSymbolAddress((void**)&wth, g_wth);

    cudaFuncSetAttribute(gemm_mma_kernel, cudaFuncAttributeMaxDynamicSharedMemorySize, GEMM_SMEM);
    cudaFuncSetAttribute(attn_tc_kernel, cudaFuncAttributeMaxDynamicSharedMemorySize, ATT_SMEM);

    const int n4 = NTOK * DMODEL / 4;
    const size_t WSZ = (size_t)DMODEL * DMODEL;

    // x -> fp16 single; all 4 weights -> fp16 W^T in one launch
    convert_h_kernel<<<n4 / 256, 256>>>(x, ah, n4);
    convert_wt4_kernel<<<dim3(DMODEL / 32, DMODEL / 32, 4), dim3(32, 8)>>>(Wq, Wk, Wv, Wo, wth);

    // fused QKV projection (one launch, N = 3072)
    gemm_mma_kernel<<<dim3(3 * DMODEL / 128, NTOK / 128), 128, GEMM_SMEM>>>(
        ah, wth, nullptr, qh, kh, v, 3);
    vt_kernel<<<dim3(S_LEN / 32, HDIM / 32, NBH), dim3(32, 8)>>>(v, vth);

    // fused causal attention -> att fp16 single
    attn_tc_kernel<<<dim3(S_LEN / 128, NBH), 256, ATT_SMEM>>>(qh, kh, vth, ah);

    // output projection
    gemm_mma_kernel<<<dim3(DMODEL / 128, NTOK / 128), 128, GEMM_SMEM>>>(
        ah, wth + 3 * WSZ, out, nullptr, nullptr, nullptr, 0);
}

// round 15
// speedup vs baseline: 9.3960x; 1.0176x over previous
#include <cuda_runtime.h>
#include <cuda_bf16.h>
#include <cuda_fp16.h>
#include <cstdint>

#define S_LEN  2048
#define NHEAD  16
#define HDIM   64
#define DMODEL 1024
#define BATCH  4
#define NTOK   (BATCH * S_LEN)   // 8192
#define NBH    (BATCH * NHEAD)   // 64

// ---------------- scratch (no allocations allowed) ----------------
__device__ __half g_qh [NBH * S_LEN * HDIM];      // Q fp16 single [bh][s][hd], pre-scaled 1/8
__device__ __half g_kh [NBH * S_LEN * HDIM];      // K fp16 single [bh][s][hd]
__device__ __half g_vh [NBH * S_LEN * HDIM];      // V fp16 single [bh][s][hd]
__device__ __half g_ah [NTOK * DMODEL];           // activation fp16 single (x, later att)
__device__ __half g_wth[4 * DMODEL * DMODEL];     // W^T fp16: [Wq;Wk;Wv;Wo]

// ================= helpers =================
__device__ __forceinline__ uint32_t smem_u32(const void* p) {
    uint32_t a;
    asm("{ .reg .u64 t; cvta.to.shared.u64 t, %1; cvt.u32.u64 %0, t; }" : "=r"(a) : "l"(p));
    return a;
}
#define CP16(dst, src) \
    asm volatile("cp.async.cg.shared.global [%0], [%1], 16;" :: "r"(dst), "l"(src))
#define CP_COMMIT() asm volatile("cp.async.commit_group;" ::: "memory")
#define CP_WAIT1()  asm volatile("cp.async.wait_group 1;" ::: "memory")
#define CP_WAIT0()  asm volatile("cp.async.wait_group 0;" ::: "memory")

#define LDSM_X4(r0, r1, r2, r3, addr) \
    asm volatile("ldmatrix.sync.aligned.m8n8.x4.shared.b16 {%0,%1,%2,%3}, [%4];" \
        : "=r"(r0), "=r"(r1), "=r"(r2), "=r"(r3) : "r"(addr))
#define LDSM_X2(r0, r1, addr) \
    asm volatile("ldmatrix.sync.aligned.m8n8.x2.shared.b16 {%0,%1}, [%2];" \
        : "=r"(r0), "=r"(r1) : "r"(addr))
#define LDSM_X2T(r0, r1, addr) \
    asm volatile("ldmatrix.sync.aligned.m8n8.x2.trans.shared.b16 {%0,%1}, [%2];" \
        : "=r"(r0), "=r"(r1) : "r"(addr))

// fp16 warp MMA, fp32 accum: D(16x8) += A(16x16) * B(16x8)
#define MMA_F16(d, a, b0, b1) \
    asm volatile("mma.sync.aligned.m16n8k16.row.col.f32.f16.f16.f32 " \
        "{%0,%1,%2,%3}, {%4,%5,%6,%7}, {%8,%9}, {%0,%1,%2,%3};" \
        : "+f"((d)[0]), "+f"((d)[1]), "+f"((d)[2]), "+f"((d)[3]) \
        : "r"((a)[0]), "r"((a)[1]), "r"((a)[2]), "r"((a)[3]), "r"(b0), "r"(b1))

__device__ __forceinline__ uint32_t packh(float lo, float hi) {
    uint32_t r;
    asm("cvt.rn.f16x2.f32 %0, %1, %2;" : "=r"(r) : "f"(hi), "f"(lo));
    return r;
}

// ================= conversion kernels =================
// fp32 -> fp16 single (pure cast)
__global__ void convert_h_kernel(const float* __restrict__ in,
                                 __half* __restrict__ out, int n4) {
    int i = blockIdx.x * blockDim.x + threadIdx.x;
    if (i >= n4) return;
    float4 v = ((const float4*)in)[i];
    ((uint32_t*)out)[2*i]   = packh(v.x, v.y);
    ((uint32_t*)out)[2*i+1] = packh(v.z, v.w);
}

// all 4 weights [K,N] row-major -> W^T fp16 [N,K], z selects the weight
__global__ void convert_wt4_kernel(const float* __restrict__ W0, const float* __restrict__ W1,
                                   const float* __restrict__ W2, const float* __restrict__ W3,
                                   __half* __restrict__ dst) {
    __shared__ float sm[32][33];
    const float* W = (blockIdx.z == 0) ? W0 : (blockIdx.z == 1) ? W1
                   : (blockIdx.z == 2) ? W2 : W3;
    __half* hT = dst + (size_t)blockIdx.z * DMODEL * DMODEL;
    int n0 = blockIdx.x * 32, k0 = blockIdx.y * 32;
    int tx = threadIdx.x, ty = threadIdx.y;   // 32 x 8
#pragma unroll
    for (int i = 0; i < 4; i++)
        sm[ty + 8*i][tx] = W[(size_t)(k0 + ty + 8*i) * DMODEL + n0 + tx];
    __syncthreads();
#pragma unroll
    for (int i = 0; i < 4; i++)
        hT[(size_t)(n0 + ty + 8*i) * DMODEL + k0 + tx] = __float2half(sm[tx][ty + 8*i]);
}

// ================= fp16 single GEMM, 64x64 warp tile, ldmatrix =================
// C = A*B; A fp16 single [M,K], B fp16 single transposed [N,K]. 1 MMA per tile op.
// CTA tile 128x128, 4 warps (2x2), K chunk 32, 3-stage cp.async ring.
// mode 0: fp32 C row-major. mode 3: fused QKV scatter (Q/K/V all fp16 [b,h,s,hd]).
#define SA       80
#define T_A      0
#define T_B      (128 * SA)
#define STAGE_SZ (2 * 128 * SA)        // 20480
#define GEMM_SMEM (3 * STAGE_SZ)       // 61440
#define NKCH     (DMODEL / 32)

__global__ __launch_bounds__(128, 2)
void gemm_mma_kernel(const __half* __restrict__ A, const __half* __restrict__ B,
                     float* __restrict__ C,
                     __half* __restrict__ Qh, __half* __restrict__ Kh,
                     __half* __restrict__ Vh, int mode)
{
    extern __shared__ char smem[];
    const uint32_t sb = smem_u32(smem);
    const int tid  = threadIdx.x;
    const int lane = tid & 31;
    const int wid  = tid >> 5;
    const int wm   = wid & 1;        // 2 warps along M, 64 rows each
    const int wn   = wid >> 1;       // 2 warps along N, 64 cols each
    const int m0   = blockIdx.y * 128;
    const int n0   = blockIdx.x * 128;
    const int g    = lane >> 2;
    const int t    = lane & 3;

    const int lrow = tid >> 2;       // 0..31 (+32p)
    const int lch  = tid & 3;        // 16B chunk in 64B row

    const uint32_t aoffA = (uint32_t)(lane & 15) * SA + ((uint32_t)(lane >> 4) << 4);
    const uint32_t aoffB = (uint32_t)(lane & 7) * SA + ((uint32_t)((lane >> 3) & 1) << 4);

    float d[4][8][4];
#pragma unroll
    for (int i = 0; i < 4; i++)
#pragma unroll
        for (int j = 0; j < 8; j++)
#pragma unroll
            for (int e = 0; e < 4; e++) d[i][j][e] = 0.f;

    auto ld_stage = [&](int c) {
        const int koe = c * 32;
        const uint32_t bufb = sb + (uint32_t)(c % 3) * STAGE_SZ;
#pragma unroll
        for (int p = 0; p < 4; p++) {
            int row = lrow + 32 * p;
            size_t ga = (size_t)(m0 + row) * DMODEL + koe + lch * 8;
            size_t gb = (size_t)(n0 + row) * DMODEL + koe + lch * 8;
            uint32_t so = bufb + (uint32_t)row * SA + lch * 16;
            CP16(so + T_A, A + ga);
            CP16(so + T_B, B + gb);
        }
        CP_COMMIT();
    };
    ld_stage(0);
    ld_stage(1);

    for (int c = 0; c < NKCH; c++) {
        if (c + 1 < NKCH) { CP_WAIT1(); } else { CP_WAIT0(); }
        __syncthreads();
        if (c + 2 < NKCH) ld_stage(c + 2);   // overlaps with compute below

        const uint32_t base = sb + (uint32_t)(c % 3) * STAGE_SZ;

        // preload ALL B fragments for this chunk
        uint32_t bf[2][8][2];
#pragma unroll
        for (int ks = 0; ks < 2; ks++)
#pragma unroll
            for (int nj = 0; nj < 8; nj++) {
                uint32_t rb = base + T_B + (uint32_t)(64 * wn + 8 * nj) * SA
                            + (uint32_t)ks * 32 + aoffB;
                LDSM_X2(bf[ks][nj][0], bf[ks][nj][1], rb);
            }

#pragma unroll
        for (int ks = 0; ks < 2; ks++) {
            uint32_t a[4][4];
#pragma unroll
            for (int mi = 0; mi < 4; mi++) {
                uint32_t ra = base + T_A + (uint32_t)(64 * wm + 16 * mi) * SA
                            + (uint32_t)ks * 32 + aoffA;
                LDSM_X4(a[mi][0], a[mi][1], a[mi][2], a[mi][3], ra);
            }
#pragma unroll
            for (int nj = 0; nj < 8; nj++)
#pragma unroll
                for (int mi = 0; mi < 4; mi++)
                    MMA_F16(d[mi][nj], a[mi], bf[ks][nj][0], bf[ks][nj][1]);
        }
    }

    // ---- epilogue ----
#pragma unroll
    for (int mi = 0; mi < 4; mi++) {
        int r0 = m0 + 64 * wm + 16 * mi + g;
#pragma unroll
        for (int nj = 0; nj < 8; nj++) {
            int n = n0 + 64 * wn + 8 * nj + 2 * t;
            float f0 = d[mi][nj][0], f1 = d[mi][nj][1];
            float f2 = d[mi][nj][2], f3 = d[mi][nj][3];
            if (mode == 0) {
                *(float2*)(C + (size_t)r0 * DMODEL + n)       = make_float2(f0, f1);
                *(float2*)(C + (size_t)(r0 + 8) * DMODEL + n) = make_float2(f2, f3);
            } else {
                int proj = n >> 10, nn = n & 1023;
                int h = nn >> 6, dd = nn & 63;
                int b0 = r0 >> 11, s0 = r0 & 2047;
                int b1 = (r0 + 8) >> 11, s1 = (r0 + 8) & 2047;
                size_t o0 = (((size_t)(b0 * NHEAD + h)) * S_LEN + s0) * HDIM + dd;
                size_t o1 = (((size_t)(b1 * NHEAD + h)) * S_LEN + s1) * HDIM + dd;
                if (proj == 0) {           // Q fp16 single, pre-scaled 1/8
                    *(uint32_t*)(Qh + o0) = packh(f0 * 0.125f, f1 * 0.125f);
                    *(uint32_t*)(Qh + o1) = packh(f2 * 0.125f, f3 * 0.125f);
                } else if (proj == 1) {    // K fp16 single
                    *(uint32_t*)(Kh + o0) = packh(f0, f1);
                    *(uint32_t*)(Kh + o1) = packh(f2, f3);
                } else {                   // V fp16 single (same layout as K)
                    *(uint32_t*)(Vh + o0) = packh(f0, f1);
                    *(uint32_t*)(Vh + o1) = packh(f2, f3);
                }
            }
        }
    }
}

// ================= tensor-core causal flash-attention =================
// QK^T: 1 fp16 MMA. P.V: 1 fp16 MMA, V staged row-major + ldmatrix.trans.
// 3-stage cp.async ring, ONE __syncthreads per k-tile.
#define AT_STRIDE 144
#define AT_K 0
#define AT_V (64 * AT_STRIDE)
#define AT_STAGE (2 * 64 * AT_STRIDE)   // 18432
#define ATT_SMEM (3 * AT_STAGE)         // 55296

__global__ __launch_bounds__(256, 2)
void attn_tc_kernel(const __half* __restrict__ qh_, const __half* __restrict__ kh_,
                    const __half* __restrict__ vh_, __half* __restrict__ outh)
{
    extern __shared__ char smem[];
    const uint32_t sb = smem_u32(smem);
    const int tid = threadIdx.x, lane = tid & 31, wid = tid >> 5;
    const int g = lane >> 2, t = lane & 3;
    const int qt = (int)gridDim.x - 1 - (int)blockIdx.x;   // heavy tiles first
    const int bh = blockIdx.y;
    const int bidx = bh >> 4, hidx = bh & 15;
    const int qbase = qt * 128;
    const int ktlast = 2 * qt + 1;

    const __half* qh = qh_ + (size_t)bh * (S_LEN * HDIM);
    const __half* kh = kh_ + (size_t)bh * (S_LEN * HDIM);
    const __half* vh = vh_ + (size_t)bh * (S_LEN * HDIM);

    const uint32_t aoffK = (uint32_t)(lane & 7) * AT_STRIDE
                         + ((uint32_t)((lane >> 3) & 1) << 4);
    const uint32_t aoffV = (uint32_t)(lane & 15) * AT_STRIDE;   // trans: 16 s-rows

    // ---- persistent Q fragments (16 rows x 64 hd, fp16 single) ----
    uint32_t qf[4][4];
    {
        const int r0 = 16 * wid + g;
        const uint32_t* ph = (const uint32_t*)(qh + (size_t)(qbase + r0) * HDIM);
#pragma unroll
        for (int ks = 0; ks < 4; ks++) {
            qf[ks][0] = ph[8*ks + t];        qf[ks][2] = ph[8*ks + t + 4];
            qf[ks][1] = ph[256 + 8*ks + t];  qf[ks][3] = ph[256 + 8*ks + t + 4];
        }
    }

    float o[8][4];
#pragma unroll
    for (int j = 0; j < 8; j++)
#pragma unroll
        for (int e = 0; e < 4; e++) o[j][e] = 0.f;
    float m0 = -1e30f, m1 = -1e30f, l0 = 0.f, l1 = 0.f;

    const int lrow = tid >> 3, lch = tid & 7;
    auto stage_load = [&](int kt) {
        const uint32_t dst = sb + (uint32_t)(kt % 3) * AT_STAGE;
#pragma unroll
        for (int p = 0; p < 2; p++) {
            int r = lrow + 32 * p;
            uint32_t so = dst + (uint32_t)r * AT_STRIDE + lch * 16;
            CP16(so + AT_K, kh + (size_t)(kt * 64 + r) * HDIM + lch * 8);
            CP16(so + AT_V, vh + (size_t)(kt * 64 + r) * HDIM + lch * 8);
        }
        CP_COMMIT();
    };
    stage_load(0);
    stage_load(1);

    for (int kt = 0; kt <= ktlast; kt++) {
        if (kt + 1 <= ktlast) { CP_WAIT1(); } else { CP_WAIT0(); }
        __syncthreads();                        // single barrier per k-tile
        if (kt + 2 <= ktlast) stage_load(kt + 2);  // slot (kt+2)%3: nobody reads it

        // last (diagonal-upper) tile: lower warp half fully masked -> skip
        const bool active = !(kt == ktlast && wid < 4);
        if (active) {
            const uint32_t tb = sb + (uint32_t)(kt % 3) * AT_STAGE;

            // ---- S = Q K^T : 1 fp16 MMA per (nj, ks) ----
            float s[8][4];
#pragma unroll
            for (int j = 0; j < 8; j++)
#pragma unroll
                for (int e = 0; e < 4; e++) s[j][e] = 0.f;
#pragma unroll
            for (int nj = 0; nj < 8; nj++) {
                uint32_t ro = tb + AT_K + (uint32_t)(8 * nj) * AT_STRIDE + aoffK;
#pragma unroll
                for (int ks = 0; ks < 4; ks++) {
                    uint32_t b0, b1;
                    LDSM_X2(b0, b1, ro + (uint32_t)ks * 32);
                    MMA_F16(s[nj], qf[ks], b0, b1);
                }
            }

            // ---- causal mask (only top 2 k-tiles intersect diagonal) ----
            if (kt >= 2 * qt) {
                const int kb = (kt - 2 * qt) * 64;
                const int r0 = 16 * wid + g, r1 = r0 + 8;
#pragma unroll
                for (int nj = 0; nj < 8; nj++) {
                    int k0 = kb + 8 * nj + 2 * t, k1 = k0 + 1;
                    if (k0 > r0) s[nj][0] = -1e30f;
                    if (k1 > r0) s[nj][1] = -1e30f;
                    if (k0 > r1) s[nj][2] = -1e30f;
                    if (k1 > r1) s[nj][3] = -1e30f;
                }
            }

            // ---- online softmax ----
            float mx0 = -1e30f, mx1 = -1e30f;
#pragma unroll
            for (int nj = 0; nj < 8; nj++) {
                mx0 = fmaxf(mx0, fmaxf(s[nj][0], s[nj][1]));
                mx1 = fmaxf(mx1, fmaxf(s[nj][2], s[nj][3]));
            }
            mx0 = fmaxf(mx0, __shfl_xor_sync(0xffffffffu, mx0, 1));
            mx0 = fmaxf(mx0, __shfl_xor_sync(0xffffffffu, mx0, 2));
            mx1 = fmaxf(mx1, __shfl_xor_sync(0xffffffffu, mx1, 1));
            mx1 = fmaxf(mx1, __shfl_xor_sync(0xffffffffu, mx1, 2));
            float mn0 = fmaxf(m0, mx0), mn1 = fmaxf(m1, mx1);
            float al0 = __expf(m0 - mn0), al1 = __expf(m1 - mn1);
            m0 = mn0; m1 = mn1;

            float rs0 = 0.f, rs1 = 0.f;
#pragma unroll
            for (int nj = 0; nj < 8; nj++) {
                s[nj][0] = __expf(s[nj][0] - mn0);
                s[nj][1] = __expf(s[nj][1] - mn0);
                s[nj][2] = __expf(s[nj][2] - mn1);
                s[nj][3] = __expf(s[nj][3] - mn1);
                rs0 += s[nj][0] + s[nj][1];
                rs1 += s[nj][2] + s[nj][3];
            }
            rs0 += __shfl_xor_sync(0xffffffffu, rs0, 1);
            rs0 += __shfl_xor_sync(0xffffffffu, rs0, 2);
            rs1 += __shfl_xor_sync(0xffffffffu, rs1, 1);
            rs1 += __shfl_xor_sync(0xffffffffu, rs1, 2);
            l0 = l0 * al0 + rs0;
            l1 = l1 * al1 + rs1;
#pragma unroll
            for (int nj = 0; nj < 8; nj++) {
                o[nj][0] *= al0; o[nj][1] *= al0;
                o[nj][2] *= al1; o[nj][3] *= al1;
            }

            // ---- P -> fp16 A-fragments (single), regs only ----
            uint32_t pf[4][4];
#pragma unroll
            for (int ksn = 0; ksn < 4; ksn++) {
                int ja = 2 * ksn, jb = ja + 1;
                pf[ksn][0] = packh(s[ja][0], s[ja][1]);
                pf[ksn][1] = packh(s[ja][2], s[ja][3]);
                pf[ksn][2] = packh(s[jb][0], s[jb][1]);
                pf[ksn][3] = packh(s[jb][2], s[jb][3]);
            }

            // ---- O += P V : V row-major + ldmatrix.trans, 1 MMA per (nj, ksn) ----
#pragma unroll
            for (int nj = 0; nj < 8; nj++) {
                uint32_t co = tb + AT_V + (uint32_t)(nj * 16) + aoffV;  // hd col 8*nj
#pragma unroll
                for (int ksn = 0; ksn < 4; ksn++) {
                    uint32_t b0, b1;
                    LDSM_X2T(b0, b1, co + (uint32_t)(16 * ksn) * AT_STRIDE);
                    MMA_F16(o[nj], pf[ksn], b0, b1);
                }
            }
        }
    }

    // ---- epilogue: normalize, emit att as fp16 single in [b*s][h*hd] ----
    const float inv0 = 1.f / l0, inv1 = 1.f / l1;
    const int r0 = qbase + 16 * wid + g;
    const size_t base0 = ((size_t)bidx * S_LEN + r0) * DMODEL + hidx * 64 + 2 * t;
#pragma unroll
    for (int nj = 0; nj < 8; nj++) {
        float f0 = o[nj][0] * inv0, f1 = o[nj][1] * inv0;
        float f2 = o[nj][2] * inv1, f3 = o[nj][3] * inv1;
        size_t o0 = base0 + 8 * nj;
        size_t o1 = o0 + 8 * DMODEL;
        *(uint32_t*)(outh + o0) = packh(f0, f1);
        *(uint32_t*)(outh + o1) = packh(f2, f3);
    }
}

// ---------------- launch ----------------
extern "C" void kernel_launch(void* const* d_in, const int* in_sizes, int n_in,
                              void* d_out, int out_size)
{
    const float* x  = (const float*)d_in[0];
    const float* Wq = (const float*)d_in[1];
    const float* Wk = (const float*)d_in[2];
    const float* Wv = (const float*)d_in[3];
    const float* Wo = (const float*)d_in[4];
    float* out = (float*)d_out;

    __half *qh, *kh, *vh, *ah, *wth;
    cudaGetSymbolAddress((void**)&qh,  g_qh);
    cudaGetSymbolAddress((void**)&kh,  g_kh);
    cudaGetSymbolAddress((void**)&vh,  g_vh);
    cudaGetSymbolAddress((void**)&ah,  g_ah);
    cudaGetSymbolAddress((void**)&wth, g_wth);

    cudaFuncSetAttribute(gemm_mma_kernel, cudaFuncAttributeMaxDynamicSharedMemorySize, GEMM_SMEM);
    cudaFuncSetAttribute(attn_tc_kernel, cudaFuncAttributeMaxDynamicSharedMemorySize, ATT_SMEM);

    const int n4 = NTOK * DMODEL / 4;
    const size_t WSZ = (size_t)DMODEL * DMODEL;

    // x -> fp16 single; all 4 weights -> fp16 W^T in one launch
    convert_h_kernel<<<n4 / 256, 256>>>(x, ah, n4);
    convert_wt4_kernel<<<dim3(DMODEL / 32, DMODEL / 32, 4), dim3(32, 8)>>>(Wq, Wk, Wv, Wo, wth);

    // fused QKV projection (one launch, N = 3072) -> Q, K, V all fp16 [b,h,s,hd]
    gemm_mma_kernel<<<dim3(3 * DMODEL / 128, NTOK / 128), 128, GEMM_SMEM>>>(
        ah, wth, nullptr, qh, kh, vh, 3);

    // fused causal attention -> att fp16 single
    attn_tc_kernel<<<dim3(S_LEN / 128, NBH), 256, ATT_SMEM>>>(qh, kh, vh, ah);

    // output projection
    gemm_mma_kernel<<<dim3(DMODEL / 128, NTOK / 128), 128, GEMM_SMEM>>>(
        ah, wth + 3 * WSZ, out, nullptr, nullptr, nullptr, 0);
}